// round 2
// baseline (speedup 1.0000x reference)
#include <cuda_runtime.h>
#include <math.h>

#define S_LEN 4096
#define HID   2048
#define NH    16
#define NKV   8
#define HD    128
#define QD    (NH*HD)    // 2048
#define KD    (NKV*HD)   // 1024
#define WINDOW 1024
#define SCALING 0.08838834764831845f  // 128^-0.5
#define SOFTCAP 50.0f

// Scratch (static device globals; no runtime allocation allowed)
__device__ float g_q[S_LEN*QD];     // 32 MB
__device__ float g_k[S_LEN*KD];     // 16 MB
__device__ float g_v[S_LEN*KD];     // 16 MB
__device__ float g_attn[S_LEN*QD];  // 32 MB

// ---------------------------------------------------------------------------
// Generic fp32 GEMM: C[M,N] = A[M,K] @ B[K,N], row-major.
// BM=BN=128, BK=16, 256 threads, 8x8 per thread. Requires M%128==0, N%128==0, K%16==0.
// ---------------------------------------------------------------------------
__global__ __launch_bounds__(256) void gemm128(const float* __restrict__ A,
                                               const float* __restrict__ B,
                                               float* __restrict__ C,
                                               int M, int N, int K) {
    __shared__ float As[16][128];
    __shared__ float Bs[16][128];
    const int tid = threadIdx.x;
    const int tx = tid & 15;
    const int ty = tid >> 4;
    const int m0 = blockIdx.y * 128;
    const int n0 = blockIdx.x * 128;

    float acc[8][8];
    #pragma unroll
    for (int i = 0; i < 8; i++)
        #pragma unroll
        for (int j = 0; j < 8; j++) acc[i][j] = 0.0f;

    for (int k0 = 0; k0 < K; k0 += 16) {
        #pragma unroll
        for (int it = 0; it < 2; it++) {
            int idx = tid + it * 256;           // 0..511
            int arow = idx >> 2, ak4 = idx & 3; // A: 128 rows x 4 float4
            float4 a = *(const float4*)(A + (size_t)(m0 + arow) * K + k0 + ak4 * 4);
            As[ak4*4+0][arow] = a.x;
            As[ak4*4+1][arow] = a.y;
            As[ak4*4+2][arow] = a.z;
            As[ak4*4+3][arow] = a.w;
            int brow = idx >> 5, bc4 = idx & 31; // B: 16 rows x 32 float4
            *(float4*)&Bs[brow][bc4*4] =
                *(const float4*)(B + (size_t)(k0 + brow) * N + n0 + bc4 * 4);
        }
        __syncthreads();
        #pragma unroll
        for (int k = 0; k < 16; k++) {
            float ra[8], rb[8];
            *(float4*)(ra)   = *(float4*)&As[k][ty*8];
            *(float4*)(ra+4) = *(float4*)&As[k][ty*8+4];
            *(float4*)(rb)   = *(float4*)&Bs[k][tx*8];
            *(float4*)(rb+4) = *(float4*)&Bs[k][tx*8+4];
            #pragma unroll
            for (int i = 0; i < 8; i++)
                #pragma unroll
                for (int j = 0; j < 8; j++)
                    acc[i][j] += ra[i] * rb[j];
        }
        __syncthreads();
    }
    #pragma unroll
    for (int i = 0; i < 8; i++) {
        float* cp = C + (size_t)(m0 + ty*8 + i) * N + n0 + tx*8;
        float4 v0 = make_float4(acc[i][0], acc[i][1], acc[i][2], acc[i][3]);
        float4 v1 = make_float4(acc[i][4], acc[i][5], acc[i][6], acc[i][7]);
        *(float4*)(cp)     = v0;
        *(float4*)(cp + 4) = v1;
    }
}

// ---------------------------------------------------------------------------
// RoPE in-place on q [S,NH,HD] and k [S,NKV,HD].
// Pair (d, d+64): out1 = x1*c - x2*s ; out2 = x2*c + x1*s  (cos/sin duplicated halves)
// ---------------------------------------------------------------------------
__global__ void rope_kernel(float* __restrict__ q, float* __restrict__ k,
                            const float* __restrict__ cosb,
                            const float* __restrict__ sinb) {
    const int NQP = S_LEN * NH * 64;
    const int NKP = S_LEN * NKV * 64;
    int idx = blockIdx.x * blockDim.x + threadIdx.x;
    if (idx < NQP) {
        int d = idx & 63;
        int h = (idx >> 6) % NH;
        int s = idx / (64 * NH);
        float c  = cosb[s * HD + d];
        float sn = sinb[s * HD + d];
        float* p = q + (size_t)s * QD + h * HD;
        float x1 = p[d], x2 = p[d + 64];
        p[d]      = x1 * c - x2 * sn;
        p[d + 64] = x2 * c + x1 * sn;
    } else if (idx < NQP + NKP) {
        int t = idx - NQP;
        int d = t & 63;
        int h = (t >> 6) % NKV;
        int s = t / (64 * NKV);
        float c  = cosb[s * HD + d];
        float sn = sinb[s * HD + d];
        float* p = k + (size_t)s * KD + h * HD;
        float x1 = p[d], x2 = p[d + 64];
        p[d]      = x1 * c - x2 * sn;
        p[d + 64] = x2 * c + x1 * sn;
    }
}

// ---------------------------------------------------------------------------
// Flash-style sliding-window attention with softcap.
// Grid: (S/64, NH). Block: 256 threads (16x16).
// Each CTA: 64 query rows of one head. Tiles of 64 keys.
// Mask computed analytically: allowed = (j <= i) && (i - j < WINDOW).
// Online softmax with finite NEG=-1e30: fully-masked tiles contribute garbage
// that is exactly zeroed when a real row-max appears (scale = exp(-1e30-x)=0).
// ---------------------------------------------------------------------------
#define ATTN_SMEM_FLOATS (64*129 + 64*129 + 64*128 + 64*65)

__global__ __launch_bounds__(256) void attn_kernel(const float* __restrict__ Q,
                                                   const float* __restrict__ K,
                                                   const float* __restrict__ V,
                                                   float* __restrict__ O) {
    extern __shared__ float sm[];
    float* Qs = sm;                    // [64][129]
    float* Ks = Qs + 64 * 129;         // [64][129]
    float* Vs = Ks + 64 * 129;         // [64][128]
    float* Ps = Vs + 64 * 128;         // [64][65]

    const int h   = blockIdx.y;
    const int qs  = blockIdx.x * 64;
    const int kvh = h >> 1;            // N_REP = 2
    const int tid = threadIdx.x;
    const int tx  = tid & 15;
    const int ty  = tid >> 4;

    // Load Q tile (64 x 128)
    #pragma unroll
    for (int it = 0; it < 8; it++) {
        int idx = tid + it * 256;
        int row = idx >> 5, c4 = idx & 31;
        float4 v = *(const float4*)(Q + (size_t)(qs + row) * QD + h * HD + c4 * 4);
        float* d = Qs + row * 129 + c4 * 4;
        d[0] = v.x; d[1] = v.y; d[2] = v.z; d[3] = v.w;
    }

    float m_i[4], l_i[4], acc[4][8];
    #pragma unroll
    for (int i = 0; i < 4; i++) {
        m_i[i] = -1e30f;
        l_i[i] = 0.0f;
        #pragma unroll
        for (int c = 0; c < 8; c++) acc[i][c] = 0.0f;
    }

    int jmin = qs - (WINDOW - 1);
    if (jmin < 0) jmin = 0;
    const int t0 = jmin >> 6;
    const int t1 = (qs + 63) >> 6;

    for (int t = t0; t <= t1; t++) {
        const int ks = t << 6;
        __syncthreads();  // previous iteration's smem reads complete
        #pragma unroll
        for (int it = 0; it < 8; it++) {
            int idx = tid + it * 256;
            int row = idx >> 5, c4 = idx & 31;
            size_t goff = (size_t)(ks + row) * KD + kvh * HD + c4 * 4;
            float4 kv = *(const float4*)(K + goff);
            float* kd = Ks + row * 129 + c4 * 4;
            kd[0] = kv.x; kd[1] = kv.y; kd[2] = kv.z; kd[3] = kv.w;
            *(float4*)(Vs + row * 128 + c4 * 4) = *(const float4*)(V + goff);
        }
        __syncthreads();

        // S = Q K^T  (4x4 per thread)
        float s[4][4];
        #pragma unroll
        for (int i = 0; i < 4; i++)
            #pragma unroll
            for (int j = 0; j < 4; j++) s[i][j] = 0.0f;

        #pragma unroll 4
        for (int d = 0; d < 128; d++) {
            float ra[4], rb[4];
            #pragma unroll
            for (int i = 0; i < 4; i++) ra[i] = Qs[(ty*4 + i) * 129 + d];
            #pragma unroll
            for (int j = 0; j < 4; j++) rb[j] = Ks[(tx*4 + j) * 129 + d];
            #pragma unroll
            for (int i = 0; i < 4; i++)
                #pragma unroll
                for (int j = 0; j < 4; j++)
                    s[i][j] += ra[i] * rb[j];
        }

        // softcap + mask + online softmax update
        #pragma unroll
        for (int i = 0; i < 4; i++) {
            const int gi = qs + ty*4 + i;
            float mx = -1e30f;
            #pragma unroll
            for (int j = 0; j < 4; j++) {
                float val = tanhf(s[i][j] * (SCALING / SOFTCAP)) * SOFTCAP;
                int gj = ks + tx*4 + j;
                bool ok = (gj <= gi) && (gi - gj < WINDOW);
                s[i][j] = ok ? val : -1e30f;
                mx = fmaxf(mx, s[i][j]);
            }
            #pragma unroll
            for (int o = 8; o >= 1; o >>= 1)
                mx = fmaxf(mx, __shfl_xor_sync(0xffffffffu, mx, o));

            float mnew = fmaxf(m_i[i], mx);
            float sc = __expf(m_i[i] - mnew);
            float rsum = 0.0f;
            #pragma unroll
            for (int j = 0; j < 4; j++) {
                float p = __expf(s[i][j] - mnew);
                s[i][j] = p;
                rsum += p;
            }
            #pragma unroll
            for (int o = 8; o >= 1; o >>= 1)
                rsum += __shfl_xor_sync(0xffffffffu, rsum, o);

            l_i[i] = l_i[i] * sc + rsum;
            m_i[i] = mnew;
            #pragma unroll
            for (int c = 0; c < 8; c++) acc[i][c] *= sc;
            #pragma unroll
            for (int j = 0; j < 4; j++)
                Ps[(ty*4 + i) * 65 + tx*4 + j] = s[i][j];
        }
        __syncthreads();

        // acc += P @ V  (4 rows x 8 cols per thread)
        #pragma unroll 4
        for (int kk = 0; kk < 64; kk++) {
            float pv[4];
            #pragma unroll
            for (int i = 0; i < 4; i++) pv[i] = Ps[(ty*4 + i) * 65 + kk];
            float rv[8];
            *(float4*)(rv)   = *(float4*)&Vs[kk * 128 + tx*8];
            *(float4*)(rv+4) = *(float4*)&Vs[kk * 128 + tx*8 + 4];
            #pragma unroll
            for (int i = 0; i < 4; i++)
                #pragma unroll
                for (int c = 0; c < 8; c++)
                    acc[i][c] += pv[i] * rv[c];
        }
    }

    // epilogue: normalize + store to [s, h*HD + d] layout (transpose fused)
    #pragma unroll
    for (int i = 0; i < 4; i++) {
        float inv = 1.0f / l_i[i];
        float* op = O + (size_t)(qs + ty*4 + i) * QD + h * HD + tx * 8;
        float4 v0 = make_float4(acc[i][0]*inv, acc[i][1]*inv, acc[i][2]*inv, acc[i][3]*inv);
        float4 v1 = make_float4(acc[i][4]*inv, acc[i][5]*inv, acc[i][6]*inv, acc[i][7]*inv);
        *(float4*)(op)     = v0;
        *(float4*)(op + 4) = v1;
    }
}

// ---------------------------------------------------------------------------
extern "C" void kernel_launch(void* const* d_in, const int* in_sizes, int n_in,
                              void* d_out, int out_size) {
    const float* hs   = (const float*)d_in[0];
    const float* cosb = (const float*)d_in[1];
    const float* sinb = (const float*)d_in[2];
    // d_in[3] = attention_mask (unused; mask computed analytically)
    const float* Wq = (const float*)d_in[4];
    const float* Wk = (const float*)d_in[5];
    const float* Wv = (const float*)d_in[6];
    const float* Wo = (const float*)d_in[7];
    float* out = (float*)d_out;

    float *q, *k, *v, *attn;
    cudaGetSymbolAddress((void**)&q,    g_q);
    cudaGetSymbolAddress((void**)&k,    g_k);
    cudaGetSymbolAddress((void**)&v,    g_v);
    cudaGetSymbolAddress((void**)&attn, g_attn);

    // Projections
    gemm128<<<dim3(QD/128, S_LEN/128), 256>>>(hs, Wq, q, S_LEN, QD, HID);
    gemm128<<<dim3(KD/128, S_LEN/128), 256>>>(hs, Wk, k, S_LEN, KD, HID);
    gemm128<<<dim3(KD/128, S_LEN/128), 256>>>(hs, Wv, v, S_LEN, KD, HID);

    // RoPE (q and k in place)
    int pairs = S_LEN*NH*64 + S_LEN*NKV*64;
    rope_kernel<<<(pairs + 255) / 256, 256>>>(q, k, cosb, sinb);

    // Attention
    size_t smbytes = ATTN_SMEM_FLOATS * sizeof(float);
    cudaFuncSetAttribute(attn_kernel, cudaFuncAttributeMaxDynamicSharedMemorySize,
                         (int)smbytes);
    attn_kernel<<<dim3(S_LEN/64, NH), 256, smbytes>>>(q, k, v, attn);

    // Output projection
    gemm128<<<dim3(QD/128, S_LEN/128), 256>>>(attn, Wo, out, S_LEN, QD, HID);
}

// round 4
// speedup vs baseline: 1.3512x; 1.3512x over previous
#include <cuda_runtime.h>
#include <cuda_bf16.h>
#include <cstdint>
#include <math.h>

#define S_LEN 4096
#define HID   2048
#define NH    16
#define NKV   8
#define HD    128
#define QD    (NH*HD)    // 2048
#define KD    (NKV*HD)   // 1024
#define WINDOW 1024
#define SCALING 0.08838834764831845f  // 128^-0.5
#define SOFTCAP 50.0f

#define K3    (3*HID)    // 6144 split-K
#define KC2   32         // bf16 K per mainloop iter
#define NITER (K3/KC2)   // 192

// ---------------- scratch (static device globals; no runtime alloc) ----------
__device__ float g_q[S_LEN*QD];                 // 32 MB
__device__ float g_k[S_LEN*KD];                 // 16 MB
__device__ float g_v[S_LEN*KD];                 // 16 MB
__device__ float g_attn[S_LEN*QD];              // 32 MB
__device__ __nv_bfloat16 g_a2[S_LEN*K3];        // 48 MB (split activations)
__device__ __nv_bfloat16 g_wq2[QD*K3];          // 24 MB
__device__ __nv_bfloat16 g_wk2[KD*K3];          // 12 MB
__device__ __nv_bfloat16 g_wv2[KD*K3];          // 12 MB
__device__ __nv_bfloat16 g_wo2[QD*K3];          // 24 MB

// ---------------- helpers ----------------------------------------------------
__device__ __forceinline__ uint32_t smem_u32(const void* p) {
    uint32_t a;
    asm("{ .reg .u64 t; cvta.to.shared.u64 t, %1; cvt.u32.u64 %0, t; }" : "=r"(a) : "l"(p));
    return a;
}
__device__ __forceinline__ void cpasync16(uint32_t saddr, const void* g) {
    asm volatile("cp.async.cg.shared.global [%0], [%1], 16;" :: "r"(saddr), "l"(g));
}
__device__ __forceinline__ void cp_commit() {
    asm volatile("cp.async.commit_group;" ::: "memory");
}
__device__ __forceinline__ void ldmatrix_x4(uint32_t* r, uint32_t addr) {
    asm volatile("ldmatrix.sync.aligned.m8n8.x4.shared.b16 {%0,%1,%2,%3}, [%4];"
                 : "=r"(r[0]), "=r"(r[1]), "=r"(r[2]), "=r"(r[3]) : "r"(addr));
}
__device__ __forceinline__ void ldmatrix_x2(uint32_t* r, uint32_t addr) {
    asm volatile("ldmatrix.sync.aligned.m8n8.x2.shared.b16 {%0,%1}, [%2];"
                 : "=r"(r[0]), "=r"(r[1]) : "r"(addr));
}
__device__ __forceinline__ void mma_bf16(float* d, const uint32_t* a, const uint32_t* b) {
    asm volatile(
        "mma.sync.aligned.m16n8k16.row.col.f32.bf16.bf16.f32 "
        "{%0,%1,%2,%3}, {%4,%5,%6,%7}, {%8,%9}, {%0,%1,%2,%3};"
        : "+f"(d[0]), "+f"(d[1]), "+f"(d[2]), "+f"(d[3])
        : "r"(a[0]), "r"(a[1]), "r"(a[2]), "r"(a[3]), "r"(b[0]), "r"(b[1]));
}

// ---------------------------------------------------------------------------
// split conversions: x = hi(bf16) + lo(bf16); A2=[hi|hi|lo], B2t=[hi|lo|hi]
// ---------------------------------------------------------------------------
__global__ void split_act(const float* __restrict__ X, __nv_bfloat16* __restrict__ A2,
                          int total) {
    int idx = blockIdx.x * blockDim.x + threadIdx.x;
    if (idx >= total) return;
    int m = idx / HID, k = idx - m * HID;
    float x = X[idx];
    __nv_bfloat16 hi = __float2bfloat16(x);
    __nv_bfloat16 lo = __float2bfloat16(x - __bfloat162float(hi));
    __nv_bfloat16* row = A2 + (size_t)m * K3;
    row[k] = hi; row[HID + k] = hi; row[2 * HID + k] = lo;
}

// W [HID, Ndim] fp32 -> B2t [Ndim, K3] bf16 (transposed + split)
__global__ void split_wt(const float* __restrict__ W, __nv_bfloat16* __restrict__ B2,
                         int Ndim) {
    __shared__ float tile[32][33];
    int k0 = blockIdx.y * 32, n0 = blockIdx.x * 32;
    int tx = threadIdx.x, ty = threadIdx.y;   // 32 x 8
    #pragma unroll
    for (int i = 0; i < 32; i += 8)
        tile[ty + i][tx] = W[(size_t)(k0 + ty + i) * Ndim + n0 + tx];
    __syncthreads();
    #pragma unroll
    for (int i = 0; i < 32; i += 8) {
        int n = n0 + ty + i, k = k0 + tx;
        float x = tile[tx][ty + i];
        __nv_bfloat16 hi = __float2bfloat16(x);
        __nv_bfloat16 lo = __float2bfloat16(x - __bfloat162float(hi));
        __nv_bfloat16* row = B2 + (size_t)n * K3;
        row[k] = hi; row[HID + k] = lo; row[2 * HID + k] = hi;
    }
}

// ---------------------------------------------------------------------------
// bf16 mma.sync GEMM: C[4096, N] = A2[4096, K3] · B2t[N, K3]^T  (fp32 accum)
// CTA 128x128, BK=32, 256 threads (8 warps, 2x4), warp tile 64x32.
// smem rows padded to 80B -> conflict-free ldmatrix phases.
// ---------------------------------------------------------------------------
#define TSTRIDE 80
#define TILE_B  (128*TSTRIDE)   // 10240

__global__ __launch_bounds__(256)
void gemm_bf16(const __nv_bfloat16* __restrict__ A2,
               const __nv_bfloat16* __restrict__ B2,
               float* __restrict__ C, int N) {
    __shared__ __align__(16) char smem[4 * TILE_B];
    // layout: A0 | B0 | A1 | B1
    const uint32_t sbase = smem_u32(smem);

    const int tid = threadIdx.x;
    const int wid = tid >> 5;
    const int lid = tid & 31;
    const int m0 = blockIdx.y * 128;
    const int n0 = blockIdx.x * 128;
    const int wm = (wid >> 2) * 64;   // warp row offset in tile
    const int wn = (wid & 3) * 32;    // warp col offset in tile

    // gmem->smem assignment: thread t -> row = t>>1 (0..127), chunk pair (t&1)*2
    const int lrow  = tid >> 1;
    const int cpair = (tid & 1) * 2;
    const __nv_bfloat16* Abase = A2 + (size_t)(m0 + lrow) * K3 + cpair * 8;
    const __nv_bfloat16* Bbase = B2 + (size_t)(n0 + lrow) * K3 + cpair * 8;
    const uint32_t sA_st = sbase + lrow * TSTRIDE + cpair * 16;
    const uint32_t sB_st = sA_st + TILE_B;

    // issue loads for iteration c into buffer b
    auto issue = [&](int c, int b) {
        const size_t ko = (size_t)c * KC2;
        const uint32_t off = b ? 2u * TILE_B : 0u;
        cpasync16(sA_st + off,      Abase + ko);
        cpasync16(sA_st + off + 16, Abase + ko + 8);
        cpasync16(sB_st + off,      Bbase + ko);
        cpasync16(sB_st + off + 16, Bbase + ko + 8);
    };

    float acc[4][4][4];
    #pragma unroll
    for (int i = 0; i < 4; i++)
        #pragma unroll
        for (int j = 0; j < 4; j++)
            #pragma unroll
            for (int r = 0; r < 4; r++) acc[i][j][r] = 0.0f;

    // ldmatrix addresses (per-thread, constant across iters except buffer offset)
    const uint32_t aAddrBase = sbase + (wm + (lid & 15)) * TSTRIDE + (lid >> 4) * 16;
    const uint32_t bAddrBase = sbase + TILE_B + (wn + (lid & 7)) * TSTRIDE + ((lid >> 3) & 1) * 16;

    issue(0, 0);
    cp_commit();

    for (int c = 0; c < NITER; c++) {
        const int b = c & 1;
        if (c + 1 < NITER) { issue(c + 1, b ^ 1); cp_commit(); }
        if (c + 1 < NITER) asm volatile("cp.async.wait_group 1;" ::: "memory");
        else               asm volatile("cp.async.wait_group 0;" ::: "memory");
        __syncthreads();

        const uint32_t boff = b ? 2u * TILE_B : 0u;
        #pragma unroll
        for (int ks = 0; ks < 2; ks++) {
            uint32_t afr[4][4], bfr[4][2];
            #pragma unroll
            for (int mt = 0; mt < 4; mt++)
                ldmatrix_x4(afr[mt], aAddrBase + boff + mt * (16 * TSTRIDE) + ks * 32);
            #pragma unroll
            for (int nt = 0; nt < 4; nt++)
                ldmatrix_x2(bfr[nt], bAddrBase + boff + nt * (8 * TSTRIDE) + ks * 32);
            #pragma unroll
            for (int mt = 0; mt < 4; mt++)
                #pragma unroll
                for (int nt = 0; nt < 4; nt++)
                    mma_bf16(acc[mt][nt], afr[mt], bfr[nt]);
        }
        __syncthreads();
    }

    // epilogue
    const int erow = (lid >> 2);
    const int ecol = (lid & 3) * 2;
    #pragma unroll
    for (int mt = 0; mt < 4; mt++) {
        #pragma unroll
        for (int nt = 0; nt < 4; nt++) {
            int r = m0 + wm + mt * 16 + erow;
            int col = n0 + wn + nt * 8 + ecol;
            *(float2*)&C[(size_t)r * N + col] = make_float2(acc[mt][nt][0], acc[mt][nt][1]);
            *(float2*)&C[(size_t)(r + 8) * N + col] = make_float2(acc[mt][nt][2], acc[mt][nt][3]);
        }
    }
}

// ---------------------------------------------------------------------------
// RoPE in-place on q [S,NH,HD] and k [S,NKV,HD].
// ---------------------------------------------------------------------------
__global__ void rope_kernel(float* __restrict__ q, float* __restrict__ k,
                            const float* __restrict__ cosb,
                            const float* __restrict__ sinb) {
    const int NQP = S_LEN * NH * 64;
    const int NKP = S_LEN * NKV * 64;
    int idx = blockIdx.x * blockDim.x + threadIdx.x;
    if (idx < NQP) {
        int d = idx & 63;
        int h = (idx >> 6) % NH;
        int s = idx / (64 * NH);
        float c  = cosb[s * HD + d];
        float sn = sinb[s * HD + d];
        float* p = q + (size_t)s * QD + h * HD;
        float x1 = p[d], x2 = p[d + 64];
        p[d]      = x1 * c - x2 * sn;
        p[d + 64] = x2 * c + x1 * sn;
    } else if (idx < NQP + NKP) {
        int t = idx - NQP;
        int d = t & 63;
        int h = (t >> 6) % NKV;
        int s = t / (64 * NKV);
        float c  = cosb[s * HD + d];
        float sn = sinb[s * HD + d];
        float* p = k + (size_t)s * KD + h * HD;
        float x1 = p[d], x2 = p[d + 64];
        p[d]      = x1 * c - x2 * sn;
        p[d + 64] = x2 * c + x1 * sn;
    }
}

// ---------------------------------------------------------------------------
// Flash-style sliding-window attention with softcap (fp32).
// ---------------------------------------------------------------------------
#define ATTN_SMEM_FLOATS (64*129 + 64*129 + 64*128 + 64*65)

__global__ __launch_bounds__(256) void attn_kernel(const float* __restrict__ Q,
                                                   const float* __restrict__ K,
                                                   const float* __restrict__ V,
                                                   float* __restrict__ O) {
    extern __shared__ float sm[];
    float* Qs = sm;                    // [64][129]
    float* Ks = Qs + 64 * 129;         // [64][129]
    float* Vs = Ks + 64 * 129;         // [64][128]
    float* Ps = Vs + 64 * 128;         // [64][65]

    const int h   = blockIdx.y;
    const int qs  = blockIdx.x * 64;
    const int kvh = h >> 1;            // N_REP = 2
    const int tid = threadIdx.x;
    const int tx  = tid & 15;
    const int ty  = tid >> 4;

    #pragma unroll
    for (int it = 0; it < 8; it++) {
        int idx = tid + it * 256;
        int row = idx >> 5, c4 = idx & 31;
        float4 v = *(const float4*)(Q + (size_t)(qs + row) * QD + h * HD + c4 * 4);
        float* d = Qs + row * 129 + c4 * 4;
        d[0] = v.x; d[1] = v.y; d[2] = v.z; d[3] = v.w;
    }

    float m_i[4], l_i[4], acc[4][8];
    #pragma unroll
    for (int i = 0; i < 4; i++) {
        m_i[i] = -1e30f;
        l_i[i] = 0.0f;
        #pragma unroll
        for (int c = 0; c < 8; c++) acc[i][c] = 0.0f;
    }

    int jmin = qs - (WINDOW - 1);
    if (jmin < 0) jmin = 0;
    const int t0 = jmin >> 6;
    const int t1 = (qs + 63) >> 6;

    for (int t = t0; t <= t1; t++) {
        const int ks = t << 6;
        __syncthreads();
        #pragma unroll
        for (int it = 0; it < 8; it++) {
            int idx = tid + it * 256;
            int row = idx >> 5, c4 = idx & 31;
            size_t goff = (size_t)(ks + row) * KD + kvh * HD + c4 * 4;
            float4 kv = *(const float4*)(K + goff);
            float* kd = Ks + row * 129 + c4 * 4;
            kd[0] = kv.x; kd[1] = kv.y; kd[2] = kv.z; kd[3] = kv.w;
            *(float4*)(Vs + row * 128 + c4 * 4) = *(const float4*)(V + goff);
        }
        __syncthreads();

        float s[4][4];
        #pragma unroll
        for (int i = 0; i < 4; i++)
            #pragma unroll
            for (int j = 0; j < 4; j++) s[i][j] = 0.0f;

        #pragma unroll 4
        for (int d = 0; d < 128; d++) {
            float ra[4], rb[4];
            #pragma unroll
            for (int i = 0; i < 4; i++) ra[i] = Qs[(ty*4 + i) * 129 + d];
            #pragma unroll
            for (int j = 0; j < 4; j++) rb[j] = Ks[(tx*4 + j) * 129 + d];
            #pragma unroll
            for (int i = 0; i < 4; i++)
                #pragma unroll
                for (int j = 0; j < 4; j++)
                    s[i][j] += ra[i] * rb[j];
        }

        #pragma unroll
        for (int i = 0; i < 4; i++) {
            const int gi = qs + ty*4 + i;
            float mx = -1e30f;
            #pragma unroll
            for (int j = 0; j < 4; j++) {
                float val = tanhf(s[i][j] * (SCALING / SOFTCAP)) * SOFTCAP;
                int gj = ks + tx*4 + j;
                bool ok = (gj <= gi) && (gi - gj < WINDOW);
                s[i][j] = ok ? val : -1e30f;
                mx = fmaxf(mx, s[i][j]);
            }
            #pragma unroll
            for (int o = 8; o >= 1; o >>= 1)
                mx = fmaxf(mx, __shfl_xor_sync(0xffffffffu, mx, o));

            float mnew = fmaxf(m_i[i], mx);
            float sc = __expf(m_i[i] - mnew);
            float rsum = 0.0f;
            #pragma unroll
            for (int j = 0; j < 4; j++) {
                float p = __expf(s[i][j] - mnew);
                s[i][j] = p;
                rsum += p;
            }
            #pragma unroll
            for (int o = 8; o >= 1; o >>= 1)
                rsum += __shfl_xor_sync(0xffffffffu, rsum, o);

            l_i[i] = l_i[i] * sc + rsum;
            m_i[i] = mnew;
            #pragma unroll
            for (int c = 0; c < 8; c++) acc[i][c] *= sc;
            #pragma unroll
            for (int j = 0; j < 4; j++)
                Ps[(ty*4 + i) * 65 + tx*4 + j] = s[i][j];
        }
        __syncthreads();

        #pragma unroll 4
        for (int kk = 0; kk < 64; kk++) {
            float pv[4];
            #pragma unroll
            for (int i = 0; i < 4; i++) pv[i] = Ps[(ty*4 + i) * 65 + kk];
            float rv[8];
            *(float4*)(rv)   = *(float4*)&Vs[kk * 128 + tx*8];
            *(float4*)(rv+4) = *(float4*)&Vs[kk * 128 + tx*8 + 4];
            #pragma unroll
            for (int i = 0; i < 4; i++)
                #pragma unroll
                for (int c = 0; c < 8; c++)
                    acc[i][c] += pv[i] * rv[c];
        }
    }

    #pragma unroll
    for (int i = 0; i < 4; i++) {
        float inv = 1.0f / l_i[i];
        float* op = O + (size_t)(qs + ty*4 + i) * QD + h * HD + tx * 8;
        float4 v0 = make_float4(acc[i][0]*inv, acc[i][1]*inv, acc[i][2]*inv, acc[i][3]*inv);
        float4 v1 = make_float4(acc[i][4]*inv, acc[i][5]*inv, acc[i][6]*inv, acc[i][7]*inv);
        *(float4*)(op)     = v0;
        *(float4*)(op + 4) = v1;
    }
}

// ---------------------------------------------------------------------------
extern "C" void kernel_launch(void* const* d_in, const int* in_sizes, int n_in,
                              void* d_out, int out_size) {
    const float* hs   = (const float*)d_in[0];
    const float* cosb = (const float*)d_in[1];
    const float* sinb = (const float*)d_in[2];
    // d_in[3] = attention_mask (unused; mask computed analytically)
    const float* Wq = (const float*)d_in[4];
    const float* Wk = (const float*)d_in[5];
    const float* Wv = (const float*)d_in[6];
    const float* Wo = (const float*)d_in[7];
    float* out = (float*)d_out;

    float *q, *k, *v, *attn;
    __nv_bfloat16 *a2, *wq2, *wk2, *wv2, *wo2;
    cudaGetSymbolAddress((void**)&q,    g_q);
    cudaGetSymbolAddress((void**)&k,    g_k);
    cudaGetSymbolAddress((void**)&v,    g_v);
    cudaGetSymbolAddress((void**)&attn, g_attn);
    cudaGetSymbolAddress((void**)&a2,   g_a2);
    cudaGetSymbolAddress((void**)&wq2,  g_wq2);
    cudaGetSymbolAddress((void**)&wk2,  g_wk2);
    cudaGetSymbolAddress((void**)&wv2,  g_wv2);
    cudaGetSymbolAddress((void**)&wo2,  g_wo2);

    // split conversions
    split_act<<<(S_LEN*HID + 255)/256, 256>>>(hs, a2, S_LEN*HID);
    split_wt<<<dim3(QD/32, HID/32), dim3(32, 8)>>>(Wq, wq2, QD);
    split_wt<<<dim3(KD/32, HID/32), dim3(32, 8)>>>(Wk, wk2, KD);
    split_wt<<<dim3(KD/32, HID/32), dim3(32, 8)>>>(Wv, wv2, KD);
    split_wt<<<dim3(QD/32, HID/32), dim3(32, 8)>>>(Wo, wo2, QD);

    // tensor-core projections (mma.sync bf16, split-K3)
    gemm_bf16<<<dim3(QD/128, S_LEN/128), 256>>>(a2, wq2, q, QD);
    gemm_bf16<<<dim3(KD/128, S_LEN/128), 256>>>(a2, wk2, k, KD);
    gemm_bf16<<<dim3(KD/128, S_LEN/128), 256>>>(a2, wv2, v, KD);

    // RoPE (q and k in place)
    int pairs = S_LEN*NH*64 + S_LEN*NKV*64;
    rope_kernel<<<(pairs + 255) / 256, 256>>>(q, k, cosb, sinb);

    // attention (fp32)
    size_t smbytes = ATTN_SMEM_FLOATS * sizeof(float);
    cudaFuncSetAttribute(attn_kernel, cudaFuncAttributeMaxDynamicSharedMemorySize,
                         (int)smbytes);
    attn_kernel<<<dim3(S_LEN/64, NH), 256, smbytes>>>(q, k, v, attn);

    // output projection
    split_act<<<(S_LEN*QD + 255)/256, 256>>>(attn, a2, S_LEN*QD);
    gemm_bf16<<<dim3(HID/128, S_LEN/128), 256>>>(a2, wo2, out, HID);
}

// round 5
// speedup vs baseline: 1.4474x; 1.0712x over previous
#include <cuda_runtime.h>
#include <cuda_bf16.h>
#include <cstdint>
#include <math.h>

#define S_LEN 4096
#define HID   2048
#define NH    16
#define NKV   8
#define HD    128
#define QD    (NH*HD)    // 2048
#define KD    (NKV*HD)   // 1024
#define WINDOW 1024
#define SCALING 0.08838834764831845f  // 128^-0.5
#define SOFTCAP 50.0f

#define K3    (3*HID)    // 6144 split-K
#define BK    32
#define NITER (K3/BK)    // 192

// ---------------- scratch (static device globals; no runtime alloc) ----------
__device__ float g_q[S_LEN*QD];                 // 32 MB
__device__ float g_k[S_LEN*KD];                 // 16 MB
__device__ float g_v[S_LEN*KD];                 // 16 MB
__device__ float g_attn[S_LEN*QD];              // 32 MB
__device__ __nv_bfloat16 g_a2[S_LEN*K3];        // 48 MB (split activations)
__device__ __nv_bfloat16 g_wq2[QD*K3];          // 24 MB
__device__ __nv_bfloat16 g_wk2[KD*K3];          // 12 MB
__device__ __nv_bfloat16 g_wv2[KD*K3];          // 12 MB
__device__ __nv_bfloat16 g_wo2[QD*K3];          // 24 MB

// ---------------- helpers ----------------------------------------------------
__device__ __forceinline__ uint32_t smem_u32(const void* p) {
    uint32_t a;
    asm("{ .reg .u64 t; cvta.to.shared.u64 t, %1; cvt.u32.u64 %0, t; }" : "=r"(a) : "l"(p));
    return a;
}
__device__ __forceinline__ void cpasync16(uint32_t saddr, const void* g) {
    asm volatile("cp.async.cg.shared.global [%0], [%1], 16;" :: "r"(saddr), "l"(g));
}
__device__ __forceinline__ void cp_commit() {
    asm volatile("cp.async.commit_group;" ::: "memory");
}
__device__ __forceinline__ void ldmatrix_x4(uint32_t* r, uint32_t addr) {
    asm volatile("ldmatrix.sync.aligned.m8n8.x4.shared.b16 {%0,%1,%2,%3}, [%4];"
                 : "=r"(r[0]), "=r"(r[1]), "=r"(r[2]), "=r"(r[3]) : "r"(addr));
}
__device__ __forceinline__ void ldmatrix_x2(uint32_t* r, uint32_t addr) {
    asm volatile("ldmatrix.sync.aligned.m8n8.x2.shared.b16 {%0,%1}, [%2];"
                 : "=r"(r[0]), "=r"(r[1]) : "r"(addr));
}
__device__ __forceinline__ void mma_bf16(float* d, const uint32_t* a, const uint32_t* b) {
    asm volatile(
        "mma.sync.aligned.m16n8k16.row.col.f32.bf16.bf16.f32 "
        "{%0,%1,%2,%3}, {%4,%5,%6,%7}, {%8,%9}, {%0,%1,%2,%3};"
        : "+f"(d[0]), "+f"(d[1]), "+f"(d[2]), "+f"(d[3])
        : "r"(a[0]), "r"(a[1]), "r"(a[2]), "r"(a[3]), "r"(b[0]), "r"(b[1]));
}

// ---------------------------------------------------------------------------
// split conversions: x = hi(bf16) + lo(bf16); A2=[hi|hi|lo], B2t=[hi|lo|hi]
// ---------------------------------------------------------------------------
__global__ void split_act(const float* __restrict__ X, __nv_bfloat16* __restrict__ A2,
                          int total) {
    int idx = blockIdx.x * blockDim.x + threadIdx.x;
    if (idx >= total) return;
    int m = idx / HID, k = idx - m * HID;
    float x = X[idx];
    __nv_bfloat16 hi = __float2bfloat16(x);
    __nv_bfloat16 lo = __float2bfloat16(x - __bfloat162float(hi));
    __nv_bfloat16* row = A2 + (size_t)m * K3;
    row[k] = hi; row[HID + k] = hi; row[2 * HID + k] = lo;
}

// W [HID, Ndim] fp32 -> B2t [Ndim, K3] bf16 (transposed + split)
__global__ void split_wt(const float* __restrict__ W, __nv_bfloat16* __restrict__ B2,
                         int Ndim) {
    __shared__ float tile[32][33];
    int k0 = blockIdx.y * 32, n0 = blockIdx.x * 32;
    int tx = threadIdx.x, ty = threadIdx.y;   // 32 x 8
    #pragma unroll
    for (int i = 0; i < 32; i += 8)
        tile[ty + i][tx] = W[(size_t)(k0 + ty + i) * Ndim + n0 + tx];
    __syncthreads();
    #pragma unroll
    for (int i = 0; i < 32; i += 8) {
        int n = n0 + ty + i, k = k0 + tx;
        float x = tile[tx][ty + i];
        __nv_bfloat16 hi = __float2bfloat16(x);
        __nv_bfloat16 lo = __float2bfloat16(x - __bfloat162float(hi));
        __nv_bfloat16* row = B2 + (size_t)n * K3;
        row[k] = hi; row[HID + k] = lo; row[2 * HID + k] = hi;
    }
}

// ---------------------------------------------------------------------------
// bf16 mma.sync GEMM v2: C[4096, N] = A2[4096, K3] · B2t[N, K3]^T (fp32 accum)
// BM=256, BN=128, BK=32, 3-stage cp.async, 512 threads (16 warps 4x4, 64x32 each)
// ---------------------------------------------------------------------------
#define TSTRIDE 80
#define A_STAGE (256*TSTRIDE)            // 20480
#define B_STAGE (128*TSTRIDE)            // 10240
#define STAGE_B (A_STAGE + B_STAGE)      // 30720
#define SM_GEMM (3*STAGE_B)              // 92160

__global__ __launch_bounds__(512)
void gemm_bf16(const __nv_bfloat16* __restrict__ A2,
               const __nv_bfloat16* __restrict__ B2,
               float* __restrict__ C, int N) {
    extern __shared__ __align__(16) char smem[];
    const uint32_t sbase = smem_u32(smem);

    const int tid = threadIdx.x;
    const int wid = tid >> 5;
    const int lid = tid & 31;
    const int m0 = blockIdx.y * 256;
    const int n0 = blockIdx.x * 128;
    const int wm = (wid & 3) * 64;     // warp row offset (4 warps in m)
    const int wn = (wid >> 2) * 32;    // warp col offset (4 warps in n)

    // gmem->smem mapping
    const int arow = tid >> 1;           // 0..255
    const int acp  = (tid & 1) * 2;      // chunk pair for A (2x16B)
    const int brow = tid >> 2;           // 0..127
    const int bc   = tid & 3;            // chunk for B (1x16B)
    const __nv_bfloat16* Abase = A2 + (size_t)(m0 + arow) * K3 + acp * 8;
    const __nv_bfloat16* Bbase = B2 + (size_t)(n0 + brow) * K3 + bc * 8;
    const uint32_t sA = sbase + arow * TSTRIDE + acp * 16;
    const uint32_t sB = sbase + A_STAGE + brow * TSTRIDE + bc * 16;

    auto issue = [&](int c, int st) {
        const size_t ko = (size_t)c * BK;
        const uint32_t so = (uint32_t)st * STAGE_B;
        cpasync16(sA + so,      Abase + ko);
        cpasync16(sA + so + 16, Abase + ko + 8);
        cpasync16(sB + so,      Bbase + ko);
    };

    float acc[4][4][4];
    #pragma unroll
    for (int i = 0; i < 4; i++)
        #pragma unroll
        for (int j = 0; j < 4; j++)
            #pragma unroll
            for (int r = 0; r < 4; r++) acc[i][j][r] = 0.0f;

    // per-thread ldmatrix bases (within stage 0)
    const uint32_t aAddr = sbase + (wm + (lid & 15)) * TSTRIDE + (lid >> 4) * 16;
    const uint32_t bAddr = sbase + A_STAGE + (wn + (lid & 7)) * TSTRIDE + ((lid >> 3) & 1) * 16;

    issue(0, 0); cp_commit();
    issue(1, 1); cp_commit();

    int st = 0;
    for (int c = 0; c < NITER; c++) {
        asm volatile("cp.async.wait_group 1;" ::: "memory");
        __syncthreads();
        if (c + 2 < NITER) {
            int st2 = st + 2; if (st2 >= 3) st2 -= 3;
            issue(c + 2, st2);
        }
        cp_commit();

        const uint32_t so = (uint32_t)st * STAGE_B;
        #pragma unroll
        for (int ks = 0; ks < 2; ks++) {
            uint32_t afr[4][4], bfr[4][2];
            #pragma unroll
            for (int mt = 0; mt < 4; mt++)
                ldmatrix_x4(afr[mt], aAddr + so + mt * (16 * TSTRIDE) + ks * 32);
            #pragma unroll
            for (int nt = 0; nt < 4; nt++)
                ldmatrix_x2(bfr[nt], bAddr + so + nt * (8 * TSTRIDE) + ks * 32);
            #pragma unroll
            for (int mt = 0; mt < 4; mt++)
                #pragma unroll
                for (int nt = 0; nt < 4; nt++)
                    mma_bf16(acc[mt][nt], afr[mt], bfr[nt]);
        }
        if (++st == 3) st = 0;
    }

    // epilogue
    const int erow = (lid >> 2);
    const int ecol = (lid & 3) * 2;
    #pragma unroll
    for (int mt = 0; mt < 4; mt++) {
        #pragma unroll
        for (int nt = 0; nt < 4; nt++) {
            int r = m0 + wm + mt * 16 + erow;
            int col = n0 + wn + nt * 8 + ecol;
            *(float2*)&C[(size_t)r * N + col] = make_float2(acc[mt][nt][0], acc[mt][nt][1]);
            *(float2*)&C[(size_t)(r + 8) * N + col] = make_float2(acc[mt][nt][2], acc[mt][nt][3]);
        }
    }
}

// ---------------------------------------------------------------------------
// RoPE in-place on q [S,NH,HD] and k [S,NKV,HD].
// ---------------------------------------------------------------------------
__global__ void rope_kernel(float* __restrict__ q, float* __restrict__ k,
                            const float* __restrict__ cosb,
                            const float* __restrict__ sinb) {
    const int NQP = S_LEN * NH * 64;
    const int NKP = S_LEN * NKV * 64;
    int idx = blockIdx.x * blockDim.x + threadIdx.x;
    if (idx < NQP) {
        int d = idx & 63;
        int h = (idx >> 6) % NH;
        int s = idx / (64 * NH);
        float c  = cosb[s * HD + d];
        float sn = sinb[s * HD + d];
        float* p = q + (size_t)s * QD + h * HD;
        float x1 = p[d], x2 = p[d + 64];
        p[d]      = x1 * c - x2 * sn;
        p[d + 64] = x2 * c + x1 * sn;
    } else if (idx < NQP + NKP) {
        int t = idx - NQP;
        int d = t & 63;
        int h = (t >> 6) % NKV;
        int s = t / (64 * NKV);
        float c  = cosb[s * HD + d];
        float sn = sinb[s * HD + d];
        float* p = k + (size_t)s * KD + h * HD;
        float x1 = p[d], x2 = p[d + 64];
        p[d]      = x1 * c - x2 * sn;
        p[d + 64] = x2 * c + x1 * sn;
    }
}

// ---------------------------------------------------------------------------
// Flash-style sliding-window attention with softcap (fp32).
// ---------------------------------------------------------------------------
#define ATTN_SMEM_FLOATS (64*129 + 64*129 + 64*128 + 64*65)

__global__ __launch_bounds__(256) void attn_kernel(const float* __restrict__ Q,
                                                   const float* __restrict__ K,
                                                   const float* __restrict__ V,
                                                   float* __restrict__ O) {
    extern __shared__ float sm[];
    float* Qs = sm;                    // [64][129]
    float* Ks = Qs + 64 * 129;         // [64][129]
    float* Vs = Ks + 64 * 129;         // [64][128]
    float* Ps = Vs + 64 * 128;         // [64][65]

    const int h   = blockIdx.y;
    const int qs  = blockIdx.x * 64;
    const int kvh = h >> 1;            // N_REP = 2
    const int tid = threadIdx.x;
    const int tx  = tid & 15;
    const int ty  = tid >> 4;

    #pragma unroll
    for (int it = 0; it < 8; it++) {
        int idx = tid + it * 256;
        int row = idx >> 5, c4 = idx & 31;
        float4 v = *(const float4*)(Q + (size_t)(qs + row) * QD + h * HD + c4 * 4);
        float* d = Qs + row * 129 + c4 * 4;
        d[0] = v.x; d[1] = v.y; d[2] = v.z; d[3] = v.w;
    }

    float m_i[4], l_i[4], acc[4][8];
    #pragma unroll
    for (int i = 0; i < 4; i++) {
        m_i[i] = -1e30f;
        l_i[i] = 0.0f;
        #pragma unroll
        for (int c = 0; c < 8; c++) acc[i][c] = 0.0f;
    }

    int jmin = qs - (WINDOW - 1);
    if (jmin < 0) jmin = 0;
    const int t0 = jmin >> 6;
    const int t1 = (qs + 63) >> 6;

    for (int t = t0; t <= t1; t++) {
        const int ks = t << 6;
        __syncthreads();
        #pragma unroll
        for (int it = 0; it < 8; it++) {
            int idx = tid + it * 256;
            int row = idx >> 5, c4 = idx & 31;
            size_t goff = (size_t)(ks + row) * KD + kvh * HD + c4 * 4;
            float4 kv = *(const float4*)(K + goff);
            float* kd = Ks + row * 129 + c4 * 4;
            kd[0] = kv.x; kd[1] = kv.y; kd[2] = kv.z; kd[3] = kv.w;
            *(float4*)(Vs + row * 128 + c4 * 4) = *(const float4*)(V + goff);
        }
        __syncthreads();

        float s[4][4];
        #pragma unroll
        for (int i = 0; i < 4; i++)
            #pragma unroll
            for (int j = 0; j < 4; j++) s[i][j] = 0.0f;

        #pragma unroll 4
        for (int d = 0; d < 128; d++) {
            float ra[4], rb[4];
            #pragma unroll
            for (int i = 0; i < 4; i++) ra[i] = Qs[(ty*4 + i) * 129 + d];
            #pragma unroll
            for (int j = 0; j < 4; j++) rb[j] = Ks[(tx*4 + j) * 129 + d];
            #pragma unroll
            for (int i = 0; i < 4; i++)
                #pragma unroll
                for (int j = 0; j < 4; j++)
                    s[i][j] += ra[i] * rb[j];
        }

        #pragma unroll
        for (int i = 0; i < 4; i++) {
            const int gi = qs + ty*4 + i;
            float mx = -1e30f;
            #pragma unroll
            for (int j = 0; j < 4; j++) {
                float val = tanhf(s[i][j] * (SCALING / SOFTCAP)) * SOFTCAP;
                int gj = ks + tx*4 + j;
                bool ok = (gj <= gi) && (gi - gj < WINDOW);
                s[i][j] = ok ? val : -1e30f;
                mx = fmaxf(mx, s[i][j]);
            }
            #pragma unroll
            for (int o = 8; o >= 1; o >>= 1)
                mx = fmaxf(mx, __shfl_xor_sync(0xffffffffu, mx, o));

            float mnew = fmaxf(m_i[i], mx);
            float sc = __expf(m_i[i] - mnew);
            float rsum = 0.0f;
            #pragma unroll
            for (int j = 0; j < 4; j++) {
                float p = __expf(s[i][j] - mnew);
                s[i][j] = p;
                rsum += p;
            }
            #pragma unroll
            for (int o = 8; o >= 1; o >>= 1)
                rsum += __shfl_xor_sync(0xffffffffu, rsum, o);

            l_i[i] = l_i[i] * sc + rsum;
            m_i[i] = mnew;
            #pragma unroll
            for (int c = 0; c < 8; c++) acc[i][c] *= sc;
            #pragma unroll
            for (int j = 0; j < 4; j++)
                Ps[(ty*4 + i) * 65 + tx*4 + j] = s[i][j];
        }
        __syncthreads();

        #pragma unroll 4
        for (int kk = 0; kk < 64; kk++) {
            float pv[4];
            #pragma unroll
            for (int i = 0; i < 4; i++) pv[i] = Ps[(ty*4 + i) * 65 + kk];
            float rv[8];
            *(float4*)(rv)   = *(float4*)&Vs[kk * 128 + tx*8];
            *(float4*)(rv+4) = *(float4*)&Vs[kk * 128 + tx*8 + 4];
            #pragma unroll
            for (int i = 0; i < 4; i++)
                #pragma unroll
                for (int c = 0; c < 8; c++)
                    acc[i][c] += pv[i] * rv[c];
        }
    }

    #pragma unroll
    for (int i = 0; i < 4; i++) {
        float inv = 1.0f / l_i[i];
        float* op = O + (size_t)(qs + ty*4 + i) * QD + h * HD + tx * 8;
        float4 v0 = make_float4(acc[i][0]*inv, acc[i][1]*inv, acc[i][2]*inv, acc[i][3]*inv);
        float4 v1 = make_float4(acc[i][4]*inv, acc[i][5]*inv, acc[i][6]*inv, acc[i][7]*inv);
        *(float4*)(op)     = v0;
        *(float4*)(op + 4) = v1;
    }
}

// ---------------------------------------------------------------------------
extern "C" void kernel_launch(void* const* d_in, const int* in_sizes, int n_in,
                              void* d_out, int out_size) {
    const float* hs   = (const float*)d_in[0];
    const float* cosb = (const float*)d_in[1];
    const float* sinb = (const float*)d_in[2];
    // d_in[3] = attention_mask (unused; mask computed analytically)
    const float* Wq = (const float*)d_in[4];
    const float* Wk = (const float*)d_in[5];
    const float* Wv = (const float*)d_in[6];
    const float* Wo = (const float*)d_in[7];
    float* out = (float*)d_out;

    float *q, *k, *v, *attn;
    __nv_bfloat16 *a2, *wq2, *wk2, *wv2, *wo2;
    cudaGetSymbolAddress((void**)&q,    g_q);
    cudaGetSymbolAddress((void**)&k,    g_k);
    cudaGetSymbolAddress((void**)&v,    g_v);
    cudaGetSymbolAddress((void**)&attn, g_attn);
    cudaGetSymbolAddress((void**)&a2,   g_a2);
    cudaGetSymbolAddress((void**)&wq2,  g_wq2);
    cudaGetSymbolAddress((void**)&wk2,  g_wk2);
    cudaGetSymbolAddress((void**)&wv2,  g_wv2);
    cudaGetSymbolAddress((void**)&wo2,  g_wo2);

    cudaFuncSetAttribute(gemm_bf16, cudaFuncAttributeMaxDynamicSharedMemorySize, SM_GEMM);

    // split conversions
    split_act<<<(S_LEN*HID + 255)/256, 256>>>(hs, a2, S_LEN*HID);
    split_wt<<<dim3(QD/32, HID/32), dim3(32, 8)>>>(Wq, wq2, QD);
    split_wt<<<dim3(KD/32, HID/32), dim3(32, 8)>>>(Wk, wk2, KD);
    split_wt<<<dim3(KD/32, HID/32), dim3(32, 8)>>>(Wv, wv2, KD);
    split_wt<<<dim3(QD/32, HID/32), dim3(32, 8)>>>(Wo, wo2, QD);

    // tensor-core projections (mma.sync bf16, split-K3)
    gemm_bf16<<<dim3(QD/128, S_LEN/256), 512, SM_GEMM>>>(a2, wq2, q, QD);
    gemm_bf16<<<dim3(KD/128, S_LEN/256), 512, SM_GEMM>>>(a2, wk2, k, KD);
    gemm_bf16<<<dim3(KD/128, S_LEN/256), 512, SM_GEMM>>>(a2, wv2, v, KD);

    // RoPE (q and k in place)
    int pairs = S_LEN*NH*64 + S_LEN*NKV*64;
    rope_kernel<<<(pairs + 255) / 256, 256>>>(q, k, cosb, sinb);

    // attention (fp32)
    size_t smbytes = ATTN_SMEM_FLOATS * sizeof(float);
    cudaFuncSetAttribute(attn_kernel, cudaFuncAttributeMaxDynamicSharedMemorySize,
                         (int)smbytes);
    attn_kernel<<<dim3(S_LEN/64, NH), 256, smbytes>>>(q, k, v, attn);

    // output projection
    split_act<<<(S_LEN*QD + 255)/256, 256>>>(attn, a2, S_LEN*QD);
    gemm_bf16<<<dim3(HID/128, S_LEN/256), 512, SM_GEMM>>>(a2, wo2, out, HID);
}

// round 6
// speedup vs baseline: 2.1644x; 1.4954x over previous
#include <cuda_runtime.h>
#include <cuda_bf16.h>
#include <cstdint>
#include <math.h>

#define S_LEN 4096
#define HID   2048
#define NH    16
#define NKV   8
#define HD    128
#define QD    (NH*HD)    // 2048
#define KD    (NKV*HD)   // 1024
#define WINDOW 1024
#define SCALING 0.08838834764831845f  // 128^-0.5
#define SOFTCAP 50.0f
#define TANHF2 (2.0f*SCALING/SOFTCAP)

#define K3    (3*HID)    // 6144 split-K
#define BK    32
#define NITER (K3/BK)    // 192

// ---------------- scratch (static device globals; no runtime alloc) ----------
__device__ float g_q[S_LEN*QD];                 // 32 MB (pre-rope fp32)
__device__ float g_k[S_LEN*KD];                 // 16 MB
__device__ float g_v[S_LEN*KD];                 // 16 MB
__device__ __nv_bfloat16 g_a2[S_LEN*K3];        // 48 MB (split activations)
__device__ __nv_bfloat16 g_wq2[QD*K3];          // 24 MB
__device__ __nv_bfloat16 g_wk2[KD*K3];          // 12 MB
__device__ __nv_bfloat16 g_wv2[KD*K3];          // 12 MB
__device__ __nv_bfloat16 g_wo2[QD*K3];          // 24 MB
__device__ __nv_bfloat16 g_qh[S_LEN*QD];        // 16 MB (post-rope split)
__device__ __nv_bfloat16 g_ql[S_LEN*QD];        // 16 MB
__device__ __nv_bfloat16 g_kh[S_LEN*KD];        // 8 MB
__device__ __nv_bfloat16 g_kl[S_LEN*KD];        // 8 MB
__device__ __nv_bfloat16 g_vh[S_LEN*KD];        // 8 MB
__device__ __nv_bfloat16 g_vl[S_LEN*KD];        // 8 MB

// ---------------- helpers ----------------------------------------------------
__device__ __forceinline__ uint32_t smem_u32(const void* p) {
    uint32_t a;
    asm("{ .reg .u64 t; cvta.to.shared.u64 t, %1; cvt.u32.u64 %0, t; }" : "=r"(a) : "l"(p));
    return a;
}
__device__ __forceinline__ void cpasync16(uint32_t saddr, const void* g) {
    asm volatile("cp.async.cg.shared.global [%0], [%1], 16;" :: "r"(saddr), "l"(g));
}
__device__ __forceinline__ void cp_commit() {
    asm volatile("cp.async.commit_group;" ::: "memory");
}
__device__ __forceinline__ void ldmatrix_x4(uint32_t* r, uint32_t addr) {
    asm volatile("ldmatrix.sync.aligned.m8n8.x4.shared.b16 {%0,%1,%2,%3}, [%4];"
                 : "=r"(r[0]), "=r"(r[1]), "=r"(r[2]), "=r"(r[3]) : "r"(addr));
}
__device__ __forceinline__ void ldmatrix_x4_t(uint32_t* r, uint32_t addr) {
    asm volatile("ldmatrix.sync.aligned.m8n8.x4.trans.shared.b16 {%0,%1,%2,%3}, [%4];"
                 : "=r"(r[0]), "=r"(r[1]), "=r"(r[2]), "=r"(r[3]) : "r"(addr));
}
__device__ __forceinline__ void ldmatrix_x2(uint32_t* r, uint32_t addr) {
    asm volatile("ldmatrix.sync.aligned.m8n8.x2.shared.b16 {%0,%1}, [%2];"
                 : "=r"(r[0]), "=r"(r[1]) : "r"(addr));
}
__device__ __forceinline__ void mma_bf16(float* d, const uint32_t* a, const uint32_t* b) {
    asm volatile(
        "mma.sync.aligned.m16n8k16.row.col.f32.bf16.bf16.f32 "
        "{%0,%1,%2,%3}, {%4,%5,%6,%7}, {%8,%9}, {%0,%1,%2,%3};"
        : "+f"(d[0]), "+f"(d[1]), "+f"(d[2]), "+f"(d[3])
        : "r"(a[0]), "r"(a[1]), "r"(a[2]), "r"(a[3]), "r"(b[0]), "r"(b[1]));
}

// ---------------------------------------------------------------------------
// split conversions: x = hi(bf16) + lo(bf16); A2=[hi|hi|lo], B2t=[hi|lo|hi]
// ---------------------------------------------------------------------------
__global__ void split_act(const float* __restrict__ X, __nv_bfloat16* __restrict__ A2,
                          int total) {
    int idx = blockIdx.x * blockDim.x + threadIdx.x;
    if (idx >= total) return;
    int m = idx / HID, k = idx - m * HID;
    float x = X[idx];
    __nv_bfloat16 hi = __float2bfloat16(x);
    __nv_bfloat16 lo = __float2bfloat16(x - __bfloat162float(hi));
    __nv_bfloat16* row = A2 + (size_t)m * K3;
    row[k] = hi; row[HID + k] = hi; row[2 * HID + k] = lo;
}

__global__ void split_wt(const float* __restrict__ W, __nv_bfloat16* __restrict__ B2,
                         int Ndim) {
    __shared__ float tile[32][33];
    int k0 = blockIdx.y * 32, n0 = blockIdx.x * 32;
    int tx = threadIdx.x, ty = threadIdx.y;   // 32 x 8
    #pragma unroll
    for (int i = 0; i < 32; i += 8)
        tile[ty + i][tx] = W[(size_t)(k0 + ty + i) * Ndim + n0 + tx];
    __syncthreads();
    #pragma unroll
    for (int i = 0; i < 32; i += 8) {
        int n = n0 + ty + i, k = k0 + tx;
        float x = tile[tx][ty + i];
        __nv_bfloat16 hi = __float2bfloat16(x);
        __nv_bfloat16 lo = __float2bfloat16(x - __bfloat162float(hi));
        __nv_bfloat16* row = B2 + (size_t)n * K3;
        row[k] = hi; row[HID + k] = lo; row[2 * HID + k] = hi;
    }
}

// ---------------------------------------------------------------------------
// bf16 mma.sync GEMM: BM=256, BN=128, BK=32, 3-stage cp.async, 512 threads
// ---------------------------------------------------------------------------
#define TSTRIDE 80
#define A_STAGE (256*TSTRIDE)
#define B_STAGE (128*TSTRIDE)
#define STAGE_B (A_STAGE + B_STAGE)
#define SM_GEMM (3*STAGE_B)

__global__ __launch_bounds__(512)
void gemm_bf16(const __nv_bfloat16* __restrict__ A2,
               const __nv_bfloat16* __restrict__ B2,
               float* __restrict__ C, int N) {
    extern __shared__ __align__(16) char smem[];
    const uint32_t sbase = smem_u32(smem);

    const int tid = threadIdx.x;
    const int wid = tid >> 5;
    const int lid = tid & 31;
    const int m0 = blockIdx.y * 256;
    const int n0 = blockIdx.x * 128;
    const int wm = (wid & 3) * 64;
    const int wn = (wid >> 2) * 32;

    const int arow = tid >> 1;
    const int acp  = (tid & 1) * 2;
    const int brow = tid >> 2;
    const int bc   = tid & 3;
    const __nv_bfloat16* Abase = A2 + (size_t)(m0 + arow) * K3 + acp * 8;
    const __nv_bfloat16* Bbase = B2 + (size_t)(n0 + brow) * K3 + bc * 8;
    const uint32_t sA = sbase + arow * TSTRIDE + acp * 16;
    const uint32_t sB = sbase + A_STAGE + brow * TSTRIDE + bc * 16;

    auto issue = [&](int c, int st) {
        const size_t ko = (size_t)c * BK;
        const uint32_t so = (uint32_t)st * STAGE_B;
        cpasync16(sA + so,      Abase + ko);
        cpasync16(sA + so + 16, Abase + ko + 8);
        cpasync16(sB + so,      Bbase + ko);
    };

    float acc[4][4][4];
    #pragma unroll
    for (int i = 0; i < 4; i++)
        #pragma unroll
        for (int j = 0; j < 4; j++)
            #pragma unroll
            for (int r = 0; r < 4; r++) acc[i][j][r] = 0.0f;

    const uint32_t aAddr = sbase + (wm + (lid & 15)) * TSTRIDE + (lid >> 4) * 16;
    const uint32_t bAddr = sbase + A_STAGE + (wn + (lid & 7)) * TSTRIDE + ((lid >> 3) & 1) * 16;

    issue(0, 0); cp_commit();
    issue(1, 1); cp_commit();

    int st = 0;
    for (int c = 0; c < NITER; c++) {
        asm volatile("cp.async.wait_group 1;" ::: "memory");
        __syncthreads();
        if (c + 2 < NITER) {
            int st2 = st + 2; if (st2 >= 3) st2 -= 3;
            issue(c + 2, st2);
        }
        cp_commit();

        const uint32_t so = (uint32_t)st * STAGE_B;
        #pragma unroll
        for (int ks = 0; ks < 2; ks++) {
            uint32_t afr[4][4], bfr[4][2];
            #pragma unroll
            for (int mt = 0; mt < 4; mt++)
                ldmatrix_x4(afr[mt], aAddr + so + mt * (16 * TSTRIDE) + ks * 32);
            #pragma unroll
            for (int nt = 0; nt < 4; nt++)
                ldmatrix_x2(bfr[nt], bAddr + so + nt * (8 * TSTRIDE) + ks * 32);
            #pragma unroll
            for (int mt = 0; mt < 4; mt++)
                #pragma unroll
                for (int nt = 0; nt < 4; nt++)
                    mma_bf16(acc[mt][nt], afr[mt], bfr[nt]);
        }
        if (++st == 3) st = 0;
    }

    const int erow = (lid >> 2);
    const int ecol = (lid & 3) * 2;
    #pragma unroll
    for (int mt = 0; mt < 4; mt++) {
        #pragma unroll
        for (int nt = 0; nt < 4; nt++) {
            int r = m0 + wm + mt * 16 + erow;
            int col = n0 + wn + nt * 8 + ecol;
            *(float2*)&C[(size_t)r * N + col] = make_float2(acc[mt][nt][0], acc[mt][nt][1]);
            *(float2*)&C[(size_t)(r + 8) * N + col] = make_float2(acc[mt][nt][2], acc[mt][nt][3]);
        }
    }
}

// ---------------------------------------------------------------------------
// RoPE + split conversion (fused): q,k fp32 -> rotated bf16 hi/lo; v -> hi/lo
// ---------------------------------------------------------------------------
__global__ void rope_split(const float* __restrict__ q, const float* __restrict__ k,
                           const float* __restrict__ v,
                           const float* __restrict__ cosb, const float* __restrict__ sinb,
                           __nv_bfloat16* __restrict__ qh, __nv_bfloat16* __restrict__ ql,
                           __nv_bfloat16* __restrict__ kh, __nv_bfloat16* __restrict__ kl,
                           __nv_bfloat16* __restrict__ vh, __nv_bfloat16* __restrict__ vl) {
    const int NQP = S_LEN * NH * 64;
    const int NKP = S_LEN * NKV * 64;
    const int NV  = S_LEN * KD;
    int idx = blockIdx.x * blockDim.x + threadIdx.x;
    if (idx < NQP) {
        int d = idx & 63, hh = (idx >> 6) % NH, s = idx / (64 * NH);
        float c = cosb[s * HD + d], sn = sinb[s * HD + d];
        const float* p = q + (size_t)s * QD + hh * HD;
        float x1 = p[d], x2 = p[d + 64];
        float y1 = x1 * c - x2 * sn, y2 = x2 * c + x1 * sn;
        size_t o = (size_t)s * QD + hh * HD + d;
        __nv_bfloat16 h1 = __float2bfloat16(y1);
        qh[o] = h1; ql[o] = __float2bfloat16(y1 - __bfloat162float(h1));
        __nv_bfloat16 h2 = __float2bfloat16(y2);
        qh[o + 64] = h2; ql[o + 64] = __float2bfloat16(y2 - __bfloat162float(h2));
    } else if (idx < NQP + NKP) {
        int t = idx - NQP;
        int d = t & 63, hh = (t >> 6) % NKV, s = t / (64 * NKV);
        float c = cosb[s * HD + d], sn = sinb[s * HD + d];
        const float* p = k + (size_t)s * KD + hh * HD;
        float x1 = p[d], x2 = p[d + 64];
        float y1 = x1 * c - x2 * sn, y2 = x2 * c + x1 * sn;
        size_t o = (size_t)s * KD + hh * HD + d;
        __nv_bfloat16 h1 = __float2bfloat16(y1);
        kh[o] = h1; kl[o] = __float2bfloat16(y1 - __bfloat162float(h1));
        __nv_bfloat16 h2 = __float2bfloat16(y2);
        kh[o + 64] = h2; kl[o + 64] = __float2bfloat16(y2 - __bfloat162float(h2));
    } else if (idx < NQP + NKP + NV) {
        int t = idx - NQP - NKP;
        float x = v[t];
        __nv_bfloat16 hx = __float2bfloat16(x);
        vh[t] = hx; vl[t] = __float2bfloat16(x - __bfloat162float(hx));
    }
}

// ---------------------------------------------------------------------------
// Tensor-core flash attention, split-bf16, sliding window + softcap.
// CTA = 128 q rows x 1 head, 8 warps x 16 rows, 64-key tiles, double-buffered.
// Epilogue writes split [hi|hi|lo] rows directly into a2 for the O-projection.
// ---------------------------------------------------------------------------
#define RSTR   272                    // smem row stride bytes (128 halves + pad)
#define QL_OFF 34816                  // 128*272
#define STG_OFF 69632                 // Q region size (Qh+Ql)
#define KSTG   17408                  // 64*272
#define STG_SZ 69632                  // Kh+Kl+Vh+Vl
#define ATTN_SMEM (STG_OFF + 2*STG_SZ)  // 208896

__global__ __launch_bounds__(256, 1)
void attn_tc(const __nv_bfloat16* __restrict__ Qh, const __nv_bfloat16* __restrict__ Ql,
             const __nv_bfloat16* __restrict__ Kh, const __nv_bfloat16* __restrict__ Kl,
             const __nv_bfloat16* __restrict__ Vh, const __nv_bfloat16* __restrict__ Vl,
             __nv_bfloat16* __restrict__ Out) {
    extern __shared__ __align__(16) char smem[];
    const uint32_t sb = smem_u32(smem);
    const int tid = threadIdx.x, wid = tid >> 5, lid = tid & 31;
    const int h = blockIdx.y, q0 = blockIdx.x * 128, kvh = h >> 1;

    // Q loads (grouped with first KV tile)
    #pragma unroll
    for (int i = 0; i < 16; i++) {
        int id = tid + i * 256;
        int mat = id >> 11, id2 = id & 2047;
        int row = id2 >> 4, c = id2 & 15;
        const __nv_bfloat16* src = (mat ? Ql : Qh) + (size_t)(q0 + row) * QD + h * HD + c * 8;
        cpasync16(sb + (mat ? QL_OFF : 0) + row * RSTR + c * 16, src);
    }

    int jmin = q0 - (WINDOW - 1); if (jmin < 0) jmin = 0;
    const int t0 = jmin >> 6, t1 = (q0 + 127) >> 6;

    auto issueKV = [&](int t, int st) {
        const int kt = t << 6;
        const uint32_t sbase = sb + STG_OFF + (uint32_t)st * STG_SZ;
        #pragma unroll
        for (int i = 0; i < 16; i++) {
            int id = tid + i * 256;
            int mat = id >> 10, id2 = id & 1023;
            int row = id2 >> 4, c = id2 & 15;
            const __nv_bfloat16* base = (mat == 0) ? Kh : (mat == 1) ? Kl : (mat == 2) ? Vh : Vl;
            cpasync16(sbase + mat * KSTG + row * RSTR + c * 16,
                      base + (size_t)(kt + row) * KD + kvh * HD + c * 8);
        }
    };
    issueKV(t0, 0); cp_commit();

    float o[16][4];
    #pragma unroll
    for (int i = 0; i < 16; i++)
        #pragma unroll
        for (int j = 0; j < 4; j++) o[i][j] = 0.0f;
    float m0 = -1e30f, m1 = -1e30f, l0 = 0.0f, l1 = 0.0f;

    const int wm = wid * 16;
    const int i0 = q0 + wm + (lid >> 2), i1 = i0 + 8;
    const uint32_t qa_h = sb + (wm + (lid & 15)) * RSTR + (lid >> 4) * 16;
    const uint32_t ka_row = (lid & 7) + ((lid >> 4) & 1) * 8;
    const uint32_t ka_coff = ((lid >> 3) & 1) * 16;
    const uint32_t v_row = (lid & 7) + ((lid >> 3) & 1) * 8;
    const uint32_t v_coff = ((lid >> 4) & 1) * 16;

    int st = 0;
    for (int t = t0; t <= t1; t++) {
        if (t < t1) { issueKV(t + 1, st ^ 1); cp_commit(); }
        if (t < t1) asm volatile("cp.async.wait_group 1;" ::: "memory");
        else        asm volatile("cp.async.wait_group 0;" ::: "memory");
        __syncthreads();

        const uint32_t stg = sb + STG_OFF + (uint32_t)st * STG_SZ;

        float sf[8][4];
        #pragma unroll
        for (int nt = 0; nt < 8; nt++)
            #pragma unroll
            for (int j = 0; j < 4; j++) sf[nt][j] = 0.0f;

        // S = Qh·Kh^T + Qh·Kl^T + Ql·Kh^T
        #pragma unroll
        for (int pass = 0; pass < 3; pass++) {
            const uint32_t qa = (pass == 2) ? qa_h + QL_OFF : qa_h;
            const uint32_t kb = stg + ((pass == 1) ? KSTG : 0);
            #pragma unroll
            for (int kk = 0; kk < 8; kk++) {
                uint32_t a[4];
                ldmatrix_x4(a, qa + kk * 32);
                #pragma unroll
                for (int ntp = 0; ntp < 4; ntp++) {
                    uint32_t b[4];
                    ldmatrix_x4(b, kb + (ntp * 16 + ka_row) * RSTR + ka_coff + kk * 32);
                    mma_bf16(sf[2 * ntp],     a, b);
                    mma_bf16(sf[2 * ntp + 1], a, b + 2);
                }
            }
        }

        // softcap + mask
        const int jt = t << 6;
        float mx0 = -1e30f, mx1 = -1e30f;
        #pragma unroll
        for (int nt = 0; nt < 8; nt++) {
            int jb = jt + nt * 8 + ((lid & 3) << 1);
            #pragma unroll
            for (int vv = 0; vv < 4; vv++) {
                int jj = jb + (vv & 1);
                int ii = (vv < 2) ? i0 : i1;
                float e = __expf(sf[nt][vv] * TANHF2);
                float val = SOFTCAP * __fdividef(e - 1.0f, e + 1.0f);
                bool ok = (jj <= ii) && (ii - jj < WINDOW);
                sf[nt][vv] = ok ? val : -1e30f;
            }
            mx0 = fmaxf(mx0, fmaxf(sf[nt][0], sf[nt][1]));
            mx1 = fmaxf(mx1, fmaxf(sf[nt][2], sf[nt][3]));
        }
        mx0 = fmaxf(mx0, __shfl_xor_sync(0xffffffffu, mx0, 1));
        mx0 = fmaxf(mx0, __shfl_xor_sync(0xffffffffu, mx0, 2));
        mx1 = fmaxf(mx1, __shfl_xor_sync(0xffffffffu, mx1, 1));
        mx1 = fmaxf(mx1, __shfl_xor_sync(0xffffffffu, mx1, 2));

        float mn0 = fmaxf(m0, mx0), mn1 = fmaxf(m1, mx1);
        float sc0 = __expf(m0 - mn0), sc1 = __expf(m1 - mn1);
        m0 = mn0; m1 = mn1;

        float s0 = 0.0f, s1 = 0.0f;
        uint32_t phA[8], phB[8], plA[8], plB[8];
        #pragma unroll
        for (int nt = 0; nt < 8; nt++) {
            float p0 = __expf(sf[nt][0] - mn0), p1 = __expf(sf[nt][1] - mn0);
            float p2 = __expf(sf[nt][2] - mn1), p3 = __expf(sf[nt][3] - mn1);
            s0 += p0 + p1; s1 += p2 + p3;
            __nv_bfloat162 hA = __floats2bfloat162_rn(p0, p1);
            __nv_bfloat162 hB = __floats2bfloat162_rn(p2, p3);
            phA[nt] = *reinterpret_cast<uint32_t*>(&hA);
            phB[nt] = *reinterpret_cast<uint32_t*>(&hB);
            __nv_bfloat162 lA = __floats2bfloat162_rn(p0 - __bfloat162float(hA.x),
                                                      p1 - __bfloat162float(hA.y));
            __nv_bfloat162 lB = __floats2bfloat162_rn(p2 - __bfloat162float(hB.x),
                                                      p3 - __bfloat162float(hB.y));
            plA[nt] = *reinterpret_cast<uint32_t*>(&lA);
            plB[nt] = *reinterpret_cast<uint32_t*>(&lB);
        }
        s0 += __shfl_xor_sync(0xffffffffu, s0, 1);
        s0 += __shfl_xor_sync(0xffffffffu, s0, 2);
        s1 += __shfl_xor_sync(0xffffffffu, s1, 1);
        s1 += __shfl_xor_sync(0xffffffffu, s1, 2);
        l0 = l0 * sc0 + s0;
        l1 = l1 * sc1 + s1;

        #pragma unroll
        for (int nt = 0; nt < 16; nt++) {
            o[nt][0] *= sc0; o[nt][1] *= sc0;
            o[nt][2] *= sc1; o[nt][3] *= sc1;
        }

        // O += Ph·Vh + Ph·Vl + Pl·Vh
        #pragma unroll
        for (int pass = 0; pass < 3; pass++) {
            const uint32_t vb = stg + 2 * KSTG + ((pass == 1) ? KSTG : 0);
            const uint32_t* pA = (pass == 2) ? plA : phA;
            const uint32_t* pB = (pass == 2) ? plB : phB;
            #pragma unroll
            for (int kk = 0; kk < 4; kk++) {
                uint32_t a[4] = { pA[2 * kk], pB[2 * kk], pA[2 * kk + 1], pB[2 * kk + 1] };
                #pragma unroll
                for (int np = 0; np < 8; np++) {
                    uint32_t b[4];
                    ldmatrix_x4_t(b, vb + (kk * 16 + v_row) * RSTR + np * 32 + v_coff);
                    mma_bf16(o[2 * np],     a, b);
                    mma_bf16(o[2 * np + 1], a, b + 2);
                }
            }
        }
        __syncthreads();
        st ^= 1;
    }

    // epilogue: normalize + write split [hi|hi|lo] rows into a2
    const float inv0 = 1.0f / l0, inv1 = 1.0f / l1;
    #pragma unroll
    for (int nt = 0; nt < 16; nt++) {
        int col = h * HD + nt * 8 + ((lid & 3) << 1);
        {
            float x0 = o[nt][0] * inv0, x1 = o[nt][1] * inv0;
            __nv_bfloat162 hh = __floats2bfloat162_rn(x0, x1);
            __nv_bfloat162 ll = __floats2bfloat162_rn(x0 - __bfloat162float(hh.x),
                                                      x1 - __bfloat162float(hh.y));
            uint32_t* row = reinterpret_cast<uint32_t*>(Out + (size_t)i0 * K3);
            uint32_t uh = *reinterpret_cast<uint32_t*>(&hh);
            row[col >> 1] = uh;
            row[(HID + col) >> 1] = uh;
            row[(2 * HID + col) >> 1] = *reinterpret_cast<uint32_t*>(&ll);
        }
        {
            float x0 = o[nt][2] * inv1, x1 = o[nt][3] * inv1;
            __nv_bfloat162 hh = __floats2bfloat162_rn(x0, x1);
            __nv_bfloat162 ll = __floats2bfloat162_rn(x0 - __bfloat162float(hh.x),
                                                      x1 - __bfloat162float(hh.y));
            uint32_t* row = reinterpret_cast<uint32_t*>(Out + (size_t)i1 * K3);
            uint32_t uh = *reinterpret_cast<uint32_t*>(&hh);
            row[col >> 1] = uh;
            row[(HID + col) >> 1] = uh;
            row[(2 * HID + col) >> 1] = *reinterpret_cast<uint32_t*>(&ll);
        }
    }
}

// ---------------------------------------------------------------------------
extern "C" void kernel_launch(void* const* d_in, const int* in_sizes, int n_in,
                              void* d_out, int out_size) {
    const float* hs   = (const float*)d_in[0];
    const float* cosb = (const float*)d_in[1];
    const float* sinb = (const float*)d_in[2];
    // d_in[3] = attention_mask (unused; mask computed analytically)
    const float* Wq = (const float*)d_in[4];
    const float* Wk = (const float*)d_in[5];
    const float* Wv = (const float*)d_in[6];
    const float* Wo = (const float*)d_in[7];
    float* out = (float*)d_out;

    float *q, *k, *v;
    __nv_bfloat16 *a2, *wq2, *wk2, *wv2, *wo2, *qh, *ql, *kh, *kl, *vh, *vl;
    cudaGetSymbolAddress((void**)&q,   g_q);
    cudaGetSymbolAddress((void**)&k,   g_k);
    cudaGetSymbolAddress((void**)&v,   g_v);
    cudaGetSymbolAddress((void**)&a2,  g_a2);
    cudaGetSymbolAddress((void**)&wq2, g_wq2);
    cudaGetSymbolAddress((void**)&wk2, g_wk2);
    cudaGetSymbolAddress((void**)&wv2, g_wv2);
    cudaGetSymbolAddress((void**)&wo2, g_wo2);
    cudaGetSymbolAddress((void**)&qh,  g_qh);
    cudaGetSymbolAddress((void**)&ql,  g_ql);
    cudaGetSymbolAddress((void**)&kh,  g_kh);
    cudaGetSymbolAddress((void**)&kl,  g_kl);
    cudaGetSymbolAddress((void**)&vh,  g_vh);
    cudaGetSymbolAddress((void**)&vl,  g_vl);

    cudaFuncSetAttribute(gemm_bf16, cudaFuncAttributeMaxDynamicSharedMemorySize, SM_GEMM);
    cudaFuncSetAttribute(attn_tc,  cudaFuncAttributeMaxDynamicSharedMemorySize, ATTN_SMEM);

    // split conversions
    split_act<<<(S_LEN*HID + 255)/256, 256>>>(hs, a2, S_LEN*HID);
    split_wt<<<dim3(QD/32, HID/32), dim3(32, 8)>>>(Wq, wq2, QD);
    split_wt<<<dim3(KD/32, HID/32), dim3(32, 8)>>>(Wk, wk2, KD);
    split_wt<<<dim3(KD/32, HID/32), dim3(32, 8)>>>(Wv, wv2, KD);
    split_wt<<<dim3(QD/32, HID/32), dim3(32, 8)>>>(Wo, wo2, QD);

    // projections
    gemm_bf16<<<dim3(QD/128, S_LEN/256), 512, SM_GEMM>>>(a2, wq2, q, QD);
    gemm_bf16<<<dim3(KD/128, S_LEN/256), 512, SM_GEMM>>>(a2, wk2, k, KD);
    gemm_bf16<<<dim3(KD/128, S_LEN/256), 512, SM_GEMM>>>(a2, wv2, v, KD);

    // fused rope + split
    int total = S_LEN*NH*64 + S_LEN*NKV*64 + S_LEN*KD;
    rope_split<<<(total + 255)/256, 256>>>(q, k, v, cosb, sinb, qh, ql, kh, kl, vh, vl);

    // tensor-core attention -> writes split activations into a2
    attn_tc<<<dim3(S_LEN/128, NH), 256, ATTN_SMEM>>>(qh, ql, kh, kl, vh, vl, a2);

    // output projection
    gemm_bf16<<<dim3(HID/128, S_LEN/256), 512, SM_GEMM>>>(a2, wo2, out, HID);
}

// round 8
// speedup vs baseline: 2.5199x; 1.1642x over previous
#include <cuda_runtime.h>
#include <cuda_bf16.h>
#include <cstdint>
#include <math.h>

#define S_LEN 4096
#define HID   2048
#define NH    16
#define NKV   8
#define HD    128
#define QD    (NH*HD)    // 2048
#define KD    (NKV*HD)   // 1024
#define QKV_N 4096       // fused projection width: q(2048)|k(1024)|v(1024)
#define WINDOW 1024
#define SCALING 0.08838834764831845f  // 128^-0.5
#define SOFTCAP 50.0f
#define TANHF2 (2.0f*SCALING/SOFTCAP)

#define K3    (3*HID)    // 6144 split-K
#define BK    32
#define NITER (K3/BK)    // 192

// ---------------- scratch (static device globals; no runtime alloc) ----------
__device__ float g_qkv[S_LEN*QKV_N];            // 64 MB fused q|k|v fp32
__device__ __nv_bfloat16 g_a2[S_LEN*K3];        // 48 MB (split activations)
__device__ __nv_bfloat16 g_wqkv2[QKV_N*K3];     // 48 MB fused split weights
__device__ __nv_bfloat16 g_wo2[QD*K3];          // 24 MB
__device__ __nv_bfloat16 g_qh[S_LEN*QD];        // 16 MB (post-rope split)
__device__ __nv_bfloat16 g_ql[S_LEN*QD];        // 16 MB
__device__ __nv_bfloat16 g_kh[S_LEN*KD];        // 8 MB
__device__ __nv_bfloat16 g_kl[S_LEN*KD];        // 8 MB
__device__ __nv_bfloat16 g_vh[S_LEN*KD];        // 8 MB
__device__ __nv_bfloat16 g_vl[S_LEN*KD];        // 8 MB

// ---------------- helpers ----------------------------------------------------
__device__ __forceinline__ uint32_t smem_u32(const void* p) {
    uint32_t a;
    asm("{ .reg .u64 t; cvta.to.shared.u64 t, %1; cvt.u32.u64 %0, t; }" : "=r"(a) : "l"(p));
    return a;
}
__device__ __forceinline__ void cpasync16(uint32_t saddr, const void* g) {
    asm volatile("cp.async.cg.shared.global [%0], [%1], 16;" :: "r"(saddr), "l"(g));
}
__device__ __forceinline__ void cp_commit() {
    asm volatile("cp.async.commit_group;" ::: "memory");
}
__device__ __forceinline__ void ldmatrix_x4(uint32_t* r, uint32_t addr) {
    asm volatile("ldmatrix.sync.aligned.m8n8.x4.shared.b16 {%0,%1,%2,%3}, [%4];"
                 : "=r"(r[0]), "=r"(r[1]), "=r"(r[2]), "=r"(r[3]) : "r"(addr));
}
__device__ __forceinline__ void ldmatrix_x4_t(uint32_t* r, uint32_t addr) {
    asm volatile("ldmatrix.sync.aligned.m8n8.x4.trans.shared.b16 {%0,%1,%2,%3}, [%4];"
                 : "=r"(r[0]), "=r"(r[1]), "=r"(r[2]), "=r"(r[3]) : "r"(addr));
}
__device__ __forceinline__ void mma_bf16(float* d, const uint32_t* a, const uint32_t* b) {
    asm volatile(
        "mma.sync.aligned.m16n8k16.row.col.f32.bf16.bf16.f32 "
        "{%0,%1,%2,%3}, {%4,%5,%6,%7}, {%8,%9}, {%0,%1,%2,%3};"
        : "+f"(d[0]), "+f"(d[1]), "+f"(d[2]), "+f"(d[3])
        : "r"(a[0]), "r"(a[1]), "r"(a[2]), "r"(a[3]), "r"(b[0]), "r"(b[1]));
}

// ---------------------------------------------------------------------------
// split conversions: x = hi(bf16) + lo(bf16); A2=[hi|hi|lo], B2t=[hi|lo|hi]
// ---------------------------------------------------------------------------
__global__ void split_act(const float* __restrict__ X, __nv_bfloat16* __restrict__ A2,
                          int total) {
    int idx = blockIdx.x * blockDim.x + threadIdx.x;
    if (idx >= total) return;
    int m = idx / HID, k = idx - m * HID;
    float x = X[idx];
    __nv_bfloat16 hi = __float2bfloat16(x);
    __nv_bfloat16 lo = __float2bfloat16(x - __bfloat162float(hi));
    __nv_bfloat16* row = A2 + (size_t)m * K3;
    row[k] = hi; row[HID + k] = hi; row[2 * HID + k] = lo;
}

// W [HID, Ndim] fp32 -> B2t rows [Ndim, K3] bf16 (transposed + split); B2 may be
// pre-offset so multiple weights pack into one fused buffer.
__global__ void split_wt(const float* __restrict__ W, __nv_bfloat16* __restrict__ B2,
                         int Ndim) {
    __shared__ float tile[32][33];
    int k0 = blockIdx.y * 32, n0 = blockIdx.x * 32;
    int tx = threadIdx.x, ty = threadIdx.y;   // 32 x 8
    #pragma unroll
    for (int i = 0; i < 32; i += 8)
        tile[ty + i][tx] = W[(size_t)(k0 + ty + i) * Ndim + n0 + tx];
    __syncthreads();
    #pragma unroll
    for (int i = 0; i < 32; i += 8) {
        int n = n0 + ty + i, k = k0 + tx;
        float x = tile[tx][ty + i];
        __nv_bfloat16 hi = __float2bfloat16(x);
        __nv_bfloat16 lo = __float2bfloat16(x - __bfloat162float(hi));
        __nv_bfloat16* row = B2 + (size_t)n * K3;
        row[k] = hi; row[HID + k] = lo; row[2 * HID + k] = hi;
    }
}

// ---------------------------------------------------------------------------
// bf16 mma.sync GEMM v3: C[4096, N] = A2[4096, K3] · B2t[N, K3]^T (fp32 accum)
// BM=256, BN=128, BK=32, 4-stage cp.async, 1024 threads (32 warps 8x4, 32x32 each)
// ---------------------------------------------------------------------------
#define TSTRIDE 80
#define A_STAGE (256*TSTRIDE)            // 20480
#define B_STAGE (128*TSTRIDE)            // 10240
#define STAGE_B (A_STAGE + B_STAGE)      // 30720
#define SM_GEMM (4*STAGE_B)              // 122880

__global__ __launch_bounds__(1024, 1)
void gemm_bf16(const __nv_bfloat16* __restrict__ A2,
               const __nv_bfloat16* __restrict__ B2,
               float* __restrict__ C, int N) {
    extern __shared__ __align__(16) char smem[];
    const uint32_t sbase = smem_u32(smem);

    const int tid = threadIdx.x;
    const int wid = tid >> 5;
    const int lid = tid & 31;
    const int m0 = blockIdx.y * 256;
    const int n0 = blockIdx.x * 128;
    const int wm = (wid & 7) * 32;     // 8 warp rows
    const int wn = (wid >> 3) * 32;    // 4 warp cols

    // gmem->smem mapping: A 256 rows x 4 chunks (1024 threads), B 128 x 4 (512)
    const int arow = tid >> 2;
    const int ac   = tid & 3;
    const __nv_bfloat16* Abase = A2 + (size_t)(m0 + arow) * K3 + ac * 8;
    const int brow = (tid >> 2) & 127;
    const __nv_bfloat16* Bbase = B2 + (size_t)(n0 + brow) * K3 + ac * 8;
    const uint32_t sA = sbase + arow * TSTRIDE + ac * 16;
    const uint32_t sB = sbase + A_STAGE + brow * TSTRIDE + ac * 16;

    auto issue = [&](int c, int st) {
        const size_t ko = (size_t)c * BK;
        const uint32_t so = (uint32_t)st * STAGE_B;
        cpasync16(sA + so, Abase + ko);
        if (tid < 512) cpasync16(sB + so, Bbase + ko);
    };

    float acc[2][4][4];
    #pragma unroll
    for (int i = 0; i < 2; i++)
        #pragma unroll
        for (int j = 0; j < 4; j++)
            #pragma unroll
            for (int r = 0; r < 4; r++) acc[i][j][r] = 0.0f;

    // per-thread ldmatrix bases (stage 0)
    const uint32_t aAddr = sbase + (wm + (lid & 15)) * TSTRIDE + (lid >> 4) * 16;
    const uint32_t bAddr = sbase + A_STAGE
        + (wn + (lid & 7) + ((lid >> 4) & 1) * 8) * TSTRIDE + ((lid >> 3) & 1) * 16;

    issue(0, 0); cp_commit();
    issue(1, 1); cp_commit();
    issue(2, 2); cp_commit();

    for (int c = 0; c < NITER; c++) {
        asm volatile("cp.async.wait_group 2;" ::: "memory");
        __syncthreads();
        if (c + 3 < NITER) issue(c + 3, (c + 3) & 3);
        cp_commit();

        const uint32_t so = (uint32_t)(c & 3) * STAGE_B;
        #pragma unroll
        for (int ks = 0; ks < 2; ks++) {
            uint32_t afr[2][4], bfr[2][4];
            #pragma unroll
            for (int mt = 0; mt < 2; mt++)
                ldmatrix_x4(afr[mt], aAddr + so + mt * (16 * TSTRIDE) + ks * 32);
            #pragma unroll
            for (int ntp = 0; ntp < 2; ntp++)
                ldmatrix_x4(bfr[ntp], bAddr + so + ntp * (16 * TSTRIDE) + ks * 32);
            #pragma unroll
            for (int mt = 0; mt < 2; mt++)
                #pragma unroll
                for (int ntp = 0; ntp < 2; ntp++) {
                    mma_bf16(acc[mt][2 * ntp],     afr[mt], bfr[ntp]);
                    mma_bf16(acc[mt][2 * ntp + 1], afr[mt], bfr[ntp] + 2);
                }
        }
    }

    // epilogue
    const int erow = (lid >> 2);
    const int ecol = (lid & 3) * 2;
    #pragma unroll
    for (int mt = 0; mt < 2; mt++) {
        #pragma unroll
        for (int nt = 0; nt < 4; nt++) {
            int r = m0 + wm + mt * 16 + erow;
            int col = n0 + wn + nt * 8 + ecol;
            *(float2*)&C[(size_t)r * N + col] = make_float2(acc[mt][nt][0], acc[mt][nt][1]);
            *(float2*)&C[(size_t)(r + 8) * N + col] = make_float2(acc[mt][nt][2], acc[mt][nt][3]);
        }
    }
}

// ---------------------------------------------------------------------------
// RoPE + split conversion (fused): reads fused qkv [S, q2048|k1024|v1024]
// ---------------------------------------------------------------------------
__global__ void rope_split(const float* __restrict__ qkv,
                           const float* __restrict__ cosb, const float* __restrict__ sinb,
                           __nv_bfloat16* __restrict__ qh, __nv_bfloat16* __restrict__ ql,
                           __nv_bfloat16* __restrict__ kh, __nv_bfloat16* __restrict__ kl,
                           __nv_bfloat16* __restrict__ vh, __nv_bfloat16* __restrict__ vl) {
    const int NQP = S_LEN * NH * 64;
    const int NKP = S_LEN * NKV * 64;
    const int NV  = S_LEN * KD;
    int idx = blockIdx.x * blockDim.x + threadIdx.x;
    if (idx < NQP) {
        int d = idx & 63, hh = (idx >> 6) % NH, s = idx / (64 * NH);
        float c = cosb[s * HD + d], sn = sinb[s * HD + d];
        const float* p = qkv + (size_t)s * QKV_N + hh * HD;
        float x1 = p[d], x2 = p[d + 64];
        float y1 = x1 * c - x2 * sn, y2 = x2 * c + x1 * sn;
        size_t o = (size_t)s * QD + hh * HD + d;
        __nv_bfloat16 h1 = __float2bfloat16(y1);
        qh[o] = h1; ql[o] = __float2bfloat16(y1 - __bfloat162float(h1));
        __nv_bfloat16 h2 = __float2bfloat16(y2);
        qh[o + 64] = h2; ql[o + 64] = __float2bfloat16(y2 - __bfloat162float(h2));
    } else if (idx < NQP + NKP) {
        int t = idx - NQP;
        int d = t & 63, hh = (t >> 6) % NKV, s = t / (64 * NKV);
        float c = cosb[s * HD + d], sn = sinb[s * HD + d];
        const float* p = qkv + (size_t)s * QKV_N + QD + hh * HD;
        float x1 = p[d], x2 = p[d + 64];
        float y1 = x1 * c - x2 * sn, y2 = x2 * c + x1 * sn;
        size_t o = (size_t)s * KD + hh * HD + d;
        __nv_bfloat16 h1 = __float2bfloat16(y1);
        kh[o] = h1; kl[o] = __float2bfloat16(y1 - __bfloat162float(h1));
        __nv_bfloat16 h2 = __float2bfloat16(y2);
        kh[o + 64] = h2; kl[o + 64] = __float2bfloat16(y2 - __bfloat162float(h2));
    } else if (idx < NQP + NKP + NV) {
        int t = idx - NQP - NKP;
        int s = t / KD, j = t - s * KD;
        float x = qkv[(size_t)s * QKV_N + QD + KD + j];
        __nv_bfloat16 hx = __float2bfloat16(x);
        vh[t] = hx; vl[t] = __float2bfloat16(x - __bfloat162float(hx));
    }
}

// ---------------------------------------------------------------------------
// Tensor-core flash attention, split-bf16, sliding window + softcap.
// ---------------------------------------------------------------------------
#define RSTR   272
#define QL_OFF 34816
#define STG_OFF 69632
#define KSTG   17408
#define STG_SZ 69632
#define ATTN_SMEM (STG_OFF + 2*STG_SZ)  // 208896

__global__ __launch_bounds__(256, 1)
void attn_tc(const __nv_bfloat16* __restrict__ Qh, const __nv_bfloat16* __restrict__ Ql,
             const __nv_bfloat16* __restrict__ Kh, const __nv_bfloat16* __restrict__ Kl,
             const __nv_bfloat16* __restrict__ Vh, const __nv_bfloat16* __restrict__ Vl,
             __nv_bfloat16* __restrict__ Out) {
    extern __shared__ __align__(16) char smem[];
    const uint32_t sb = smem_u32(smem);
    const int tid = threadIdx.x, wid = tid >> 5, lid = tid & 31;
    const int h = blockIdx.y, q0 = blockIdx.x * 128, kvh = h >> 1;

    #pragma unroll
    for (int i = 0; i < 16; i++) {
        int id = tid + i * 256;
        int mat = id >> 11, id2 = id & 2047;
        int row = id2 >> 4, c = id2 & 15;
        const __nv_bfloat16* src = (mat ? Ql : Qh) + (size_t)(q0 + row) * QD + h * HD + c * 8;
        cpasync16(sb + (mat ? QL_OFF : 0) + row * RSTR + c * 16, src);
    }

    int jmin = q0 - (WINDOW - 1); if (jmin < 0) jmin = 0;
    const int t0 = jmin >> 6, t1 = (q0 + 127) >> 6;

    auto issueKV = [&](int t, int st) {
        const int kt = t << 6;
        const uint32_t sbase = sb + STG_OFF + (uint32_t)st * STG_SZ;
        #pragma unroll
        for (int i = 0; i < 16; i++) {
            int id = tid + i * 256;
            int mat = id >> 10, id2 = id & 1023;
            int row = id2 >> 4, c = id2 & 15;
            const __nv_bfloat16* base = (mat == 0) ? Kh : (mat == 1) ? Kl : (mat == 2) ? Vh : Vl;
            cpasync16(sbase + mat * KSTG + row * RSTR + c * 16,
                      base + (size_t)(kt + row) * KD + kvh * HD + c * 8);
        }
    };
    issueKV(t0, 0); cp_commit();

    float o[16][4];
    #pragma unroll
    for (int i = 0; i < 16; i++)
        #pragma unroll
        for (int j = 0; j < 4; j++) o[i][j] = 0.0f;
    float m0 = -1e30f, m1 = -1e30f, l0 = 0.0f, l1 = 0.0f;

    const int wm = wid * 16;
    const int i0 = q0 + wm + (lid >> 2), i1 = i0 + 8;
    const uint32_t qa_h = sb + (wm + (lid & 15)) * RSTR + (lid >> 4) * 16;
    const uint32_t ka_row = (lid & 7) + ((lid >> 4) & 1) * 8;
    const uint32_t ka_coff = ((lid >> 3) & 1) * 16;
    const uint32_t v_row = (lid & 7) + ((lid >> 3) & 1) * 8;
    const uint32_t v_coff = ((lid >> 4) & 1) * 16;

    int st = 0;
    for (int t = t0; t <= t1; t++) {
        if (t < t1) { issueKV(t + 1, st ^ 1); cp_commit(); }
        if (t < t1) asm volatile("cp.async.wait_group 1;" ::: "memory");
        else        asm volatile("cp.async.wait_group 0;" ::: "memory");
        __syncthreads();

        const uint32_t stg = sb + STG_OFF + (uint32_t)st * STG_SZ;

        float sf[8][4];
        #pragma unroll
        for (int nt = 0; nt < 8; nt++)
            #pragma unroll
            for (int j = 0; j < 4; j++) sf[nt][j] = 0.0f;

        #pragma unroll
        for (int pass = 0; pass < 3; pass++) {
            const uint32_t qa = (pass == 2) ? qa_h + QL_OFF : qa_h;
            const uint32_t kb = stg + ((pass == 1) ? KSTG : 0);
            #pragma unroll
            for (int kk = 0; kk < 8; kk++) {
                uint32_t a[4];
                ldmatrix_x4(a, qa + kk * 32);
                #pragma unroll
                for (int ntp = 0; ntp < 4; ntp++) {
                    uint32_t b[4];
                    ldmatrix_x4(b, kb + (ntp * 16 + ka_row) * RSTR + ka_coff + kk * 32);
                    mma_bf16(sf[2 * ntp],     a, b);
                    mma_bf16(sf[2 * ntp + 1], a, b + 2);
                }
            }
        }

        const int jt = t << 6;
        float mx0 = -1e30f, mx1 = -1e30f;
        #pragma unroll
        for (int nt = 0; nt < 8; nt++) {
            int jb = jt + nt * 8 + ((lid & 3) << 1);
            #pragma unroll
            for (int vv = 0; vv < 4; vv++) {
                int jj = jb + (vv & 1);
                int ii = (vv < 2) ? i0 : i1;
                float e = __expf(sf[nt][vv] * TANHF2);
                float val = SOFTCAP * __fdividef(e - 1.0f, e + 1.0f);
                bool ok = (jj <= ii) && (ii - jj < WINDOW);
                sf[nt][vv] = ok ? val : -1e30f;
            }
            mx0 = fmaxf(mx0, fmaxf(sf[nt][0], sf[nt][1]));
            mx1 = fmaxf(mx1, fmaxf(sf[nt][2], sf[nt][3]));
        }
        mx0 = fmaxf(mx0, __shfl_xor_sync(0xffffffffu, mx0, 1));
        mx0 = fmaxf(mx0, __shfl_xor_sync(0xffffffffu, mx0, 2));
        mx1 = fmaxf(mx1, __shfl_xor_sync(0xffffffffu, mx1, 1));
        mx1 = fmaxf(mx1, __shfl_xor_sync(0xffffffffu, mx1, 2));

        float mn0 = fmaxf(m0, mx0), mn1 = fmaxf(m1, mx1);
        float sc0 = __expf(m0 - mn0), sc1 = __expf(m1 - mn1);
        m0 = mn0; m1 = mn1;

        float s0 = 0.0f, s1 = 0.0f;
        uint32_t phA[8], phB[8], plA[8], plB[8];
        #pragma unroll
        for (int nt = 0; nt < 8; nt++) {
            float p0 = __expf(sf[nt][0] - mn0), p1 = __expf(sf[nt][1] - mn0);
            float p2 = __expf(sf[nt][2] - mn1), p3 = __expf(sf[nt][3] - mn1);
            s0 += p0 + p1; s1 += p2 + p3;
            __nv_bfloat162 hA = __floats2bfloat162_rn(p0, p1);
            __nv_bfloat162 hB = __floats2bfloat162_rn(p2, p3);
            phA[nt] = *reinterpret_cast<uint32_t*>(&hA);
            phB[nt] = *reinterpret_cast<uint32_t*>(&hB);
            __nv_bfloat162 lA = __floats2bfloat162_rn(p0 - __bfloat162float(hA.x),
                                                      p1 - __bfloat162float(hA.y));
            __nv_bfloat162 lB = __floats2bfloat162_rn(p2 - __bfloat162float(hB.x),
                                                      p3 - __bfloat162float(hB.y));
            plA[nt] = *reinterpret_cast<uint32_t*>(&lA);
            plB[nt] = *reinterpret_cast<uint32_t*>(&lB);
        }
        s0 += __shfl_xor_sync(0xffffffffu, s0, 1);
        s0 += __shfl_xor_sync(0xffffffffu, s0, 2);
        s1 += __shfl_xor_sync(0xffffffffu, s1, 1);
        s1 += __shfl_xor_sync(0xffffffffu, s1, 2);
        l0 = l0 * sc0 + s0;
        l1 = l1 * sc1 + s1;

        #pragma unroll
        for (int nt = 0; nt < 16; nt++) {
            o[nt][0] *= sc0; o[nt][1] *= sc0;
            o[nt][2] *= sc1; o[nt][3] *= sc1;
        }

        #pragma unroll
        for (int pass = 0; pass < 3; pass++) {
            const uint32_t vb = stg + 2 * KSTG + ((pass == 1) ? KSTG : 0);
            const uint32_t* pA = (pass == 2) ? plA : phA;
            const uint32_t* pB = (pass == 2) ? plB : phB;
            #pragma unroll
            for (int kk = 0; kk < 4; kk++) {
                uint32_t a[4] = { pA[2 * kk], pB[2 * kk], pA[2 * kk + 1], pB[2 * kk + 1] };
                #pragma unroll
                for (int np = 0; np < 8; np++) {
                    uint32_t b[4];
                    ldmatrix_x4_t(b, vb + (kk * 16 + v_row) * RSTR + np * 32 + v_coff);
                    mma_bf16(o[2 * np],     a, b);
                    mma_bf16(o[2 * np + 1], a, b + 2);
                }
            }
        }
        __syncthreads();
        st ^= 1;
    }

    const float inv0 = 1.0f / l0, inv1 = 1.0f / l1;
    #pragma unroll
    for (int nt = 0; nt < 16; nt++) {
        int col = h * HD + nt * 8 + ((lid & 3) << 1);
        {
            float x0 = o[nt][0] * inv0, x1 = o[nt][1] * inv0;
            __nv_bfloat162 hh = __floats2bfloat162_rn(x0, x1);
            __nv_bfloat162 ll = __floats2bfloat162_rn(x0 - __bfloat162float(hh.x),
                                                      x1 - __bfloat162float(hh.y));
            uint32_t* row = reinterpret_cast<uint32_t*>(Out + (size_t)i0 * K3);
            uint32_t uh = *reinterpret_cast<uint32_t*>(&hh);
            row[col >> 1] = uh;
            row[(HID + col) >> 1] = uh;
            row[(2 * HID + col) >> 1] = *reinterpret_cast<uint32_t*>(&ll);
        }
        {
            float x0 = o[nt][2] * inv1, x1 = o[nt][3] * inv1;
            __nv_bfloat162 hh = __floats2bfloat162_rn(x0, x1);
            __nv_bfloat162 ll = __floats2bfloat162_rn(x0 - __bfloat162float(hh.x),
                                                      x1 - __bfloat162float(hh.y));
            uint32_t* row = reinterpret_cast<uint32_t*>(Out + (size_t)i1 * K3);
            uint32_t uh = *reinterpret_cast<uint32_t*>(&hh);
            row[col >> 1] = uh;
            row[(HID + col) >> 1] = uh;
            row[(2 * HID + col) >> 1] = *reinterpret_cast<uint32_t*>(&ll);
        }
    }
}

// ---------------------------------------------------------------------------
extern "C" void kernel_launch(void* const* d_in, const int* in_sizes, int n_in,
                              void* d_out, int out_size) {
    const float* hs   = (const float*)d_in[0];
    const float* cosb = (const float*)d_in[1];
    const float* sinb = (const float*)d_in[2];
    // d_in[3] = attention_mask (unused; mask computed analytically)
    const float* Wq = (const float*)d_in[4];
    const float* Wk = (const float*)d_in[5];
    const float* Wv = (const float*)d_in[6];
    const float* Wo = (const float*)d_in[7];
    float* out = (float*)d_out;

    float *qkv;
    __nv_bfloat16 *a2, *wqkv2, *wo2, *qh, *ql, *kh, *kl, *vh, *vl;
    cudaGetSymbolAddress((void**)&qkv,   g_qkv);
    cudaGetSymbolAddress((void**)&a2,    g_a2);
    cudaGetSymbolAddress((void**)&wqkv2, g_wqkv2);
    cudaGetSymbolAddress((void**)&wo2,   g_wo2);
    cudaGetSymbolAddress((void**)&qh,    g_qh);
    cudaGetSymbolAddress((void**)&ql,    g_ql);
    cudaGetSymbolAddress((void**)&kh,    g_kh);
    cudaGetSymbolAddress((void**)&kl,    g_kl);
    cudaGetSymbolAddress((void**)&vh,    g_vh);
    cudaGetSymbolAddress((void**)&vl,    g_vl);

    cudaFuncSetAttribute(gemm_bf16, cudaFuncAttributeMaxDynamicSharedMemorySize, SM_GEMM);
    cudaFuncSetAttribute(attn_tc,  cudaFuncAttributeMaxDynamicSharedMemorySize, ATTN_SMEM);

    // split conversions (weights packed into one fused buffer: rows q|k|v)
    split_act<<<(S_LEN*HID + 255)/256, 256>>>(hs, a2, S_LEN*HID);
    split_wt<<<dim3(QD/32, HID/32), dim3(32, 8)>>>(Wq, wqkv2, QD);
    split_wt<<<dim3(KD/32, HID/32), dim3(32, 8)>>>(Wk, wqkv2 + (size_t)QD * K3, KD);
    split_wt<<<dim3(KD/32, HID/32), dim3(32, 8)>>>(Wv, wqkv2 + (size_t)(QD + KD) * K3, KD);
    split_wt<<<dim3(QD/32, HID/32), dim3(32, 8)>>>(Wo, wo2, QD);

    // fused QKV projection (one launch, N=4096)
    gemm_bf16<<<dim3(QKV_N/128, S_LEN/256), 1024, SM_GEMM>>>(a2, wqkv2, qkv, QKV_N);

    // fused rope + split
    int total = S_LEN*NH*64 + S_LEN*NKV*64 + S_LEN*KD;
    rope_split<<<(total + 255)/256, 256>>>(qkv, cosb, sinb, qh, ql, kh, kl, vh, vl);

    // tensor-core attention -> writes split activations into a2
    attn_tc<<<dim3(S_LEN/128, NH), 256, ATTN_SMEM>>>(qh, ql, kh, kl, vh, vl, a2);

    // output projection
    gemm_bf16<<<dim3(HID/128, S_LEN/256), 1024, SM_GEMM>>>(a2, wo2, out, HID);
}

// round 9
// speedup vs baseline: 2.6901x; 1.0675x over previous
#include <cuda_runtime.h>
#include <cuda_bf16.h>
#include <cuda_fp16.h>
#include <cstdint>
#include <math.h>

#define S_LEN 4096
#define HID   2048
#define NH    16
#define NKV   8
#define HD    128
#define QD    (NH*HD)    // 2048
#define KD    (NKV*HD)   // 1024
#define QKV_N 4096       // fused projection width: q(2048)|k(1024)|v(1024)
#define WINDOW 1024
#define SCALING 0.08838834764831845f  // 128^-0.5
#define SOFTCAP 50.0f
#define TANHF2 (2.0f*SCALING/SOFTCAP)

#define K2    (2*HID)    // 4096: [hi|lo] storage
#define BK    32
#define NITER 192        // 3 products (hi.hi, hi.lo, lo.hi) x 64 chunks

// ---------------- scratch (static device globals; no runtime alloc) ----------
__device__ float g_qkv[S_LEN*QKV_N];            // 64 MB fused q|k|v fp32
__device__ __nv_bfloat16 g_a2[S_LEN*K2];        // 32 MB (split activations [hi|lo])
__device__ __nv_bfloat16 g_wqkv2[QKV_N*K2];     // 32 MB fused split weights
__device__ __nv_bfloat16 g_wo2[QD*K2];          // 16 MB
__device__ __half g_qh[S_LEN*QD];               // 16 MB (post-rope fp16 split)
__device__ __half g_ql[S_LEN*QD];               // 16 MB
__device__ __half g_kh[S_LEN*KD];               // 8 MB (hi only)
__device__ __half g_vh[S_LEN*KD];               // 8 MB (hi only)

// ---------------- helpers ----------------------------------------------------
__device__ __forceinline__ uint32_t smem_u32(const void* p) {
    uint32_t a;
    asm("{ .reg .u64 t; cvta.to.shared.u64 t, %1; cvt.u32.u64 %0, t; }" : "=r"(a) : "l"(p));
    return a;
}
__device__ __forceinline__ void cpasync16(uint32_t saddr, const void* g) {
    asm volatile("cp.async.cg.shared.global [%0], [%1], 16;" :: "r"(saddr), "l"(g));
}
__device__ __forceinline__ void cp_commit() {
    asm volatile("cp.async.commit_group;" ::: "memory");
}
__device__ __forceinline__ void ldmatrix_x4(uint32_t* r, uint32_t addr) {
    asm volatile("ldmatrix.sync.aligned.m8n8.x4.shared.b16 {%0,%1,%2,%3}, [%4];"
                 : "=r"(r[0]), "=r"(r[1]), "=r"(r[2]), "=r"(r[3]) : "r"(addr));
}
__device__ __forceinline__ void ldmatrix_x4_t(uint32_t* r, uint32_t addr) {
    asm volatile("ldmatrix.sync.aligned.m8n8.x4.trans.shared.b16 {%0,%1,%2,%3}, [%4];"
                 : "=r"(r[0]), "=r"(r[1]), "=r"(r[2]), "=r"(r[3]) : "r"(addr));
}
__device__ __forceinline__ void mma_bf16(float* d, const uint32_t* a, const uint32_t* b) {
    asm volatile(
        "mma.sync.aligned.m16n8k16.row.col.f32.bf16.bf16.f32 "
        "{%0,%1,%2,%3}, {%4,%5,%6,%7}, {%8,%9}, {%0,%1,%2,%3};"
        : "+f"(d[0]), "+f"(d[1]), "+f"(d[2]), "+f"(d[3])
        : "r"(a[0]), "r"(a[1]), "r"(a[2]), "r"(a[3]), "r"(b[0]), "r"(b[1]));
}
__device__ __forceinline__ void mma_f16(float* d, const uint32_t* a, const uint32_t* b) {
    asm volatile(
        "mma.sync.aligned.m16n8k16.row.col.f32.f16.f16.f32 "
        "{%0,%1,%2,%3}, {%4,%5,%6,%7}, {%8,%9}, {%0,%1,%2,%3};"
        : "+f"(d[0]), "+f"(d[1]), "+f"(d[2]), "+f"(d[3])
        : "r"(a[0]), "r"(a[1]), "r"(a[2]), "r"(a[3]), "r"(b[0]), "r"(b[1]));
}

// ---------------------------------------------------------------------------
// split conversions: x = hi(bf16) + lo(bf16); storage [hi(2048) | lo(2048)]
// ---------------------------------------------------------------------------
__global__ void split_act(const float* __restrict__ X, __nv_bfloat16* __restrict__ A2,
                          int total) {
    int idx = blockIdx.x * blockDim.x + threadIdx.x;
    if (idx >= total) return;
    int m = idx / HID, k = idx - m * HID;
    float x = X[idx];
    __nv_bfloat16 hi = __float2bfloat16(x);
    __nv_bfloat16 lo = __float2bfloat16(x - __bfloat162float(hi));
    __nv_bfloat16* row = A2 + (size_t)m * K2;
    row[k] = hi; row[HID + k] = lo;
}

// W [HID, Ndim] fp32 -> B2t rows [Ndim, K2] bf16 (transposed + split [hi|lo])
__global__ void split_wt(const float* __restrict__ W, __nv_bfloat16* __restrict__ B2,
                         int Ndim) {
    __shared__ float tile[32][33];
    int k0 = blockIdx.y * 32, n0 = blockIdx.x * 32;
    int tx = threadIdx.x, ty = threadIdx.y;   // 32 x 8
    #pragma unroll
    for (int i = 0; i < 32; i += 8)
        tile[ty + i][tx] = W[(size_t)(k0 + ty + i) * Ndim + n0 + tx];
    __syncthreads();
    #pragma unroll
    for (int i = 0; i < 32; i += 8) {
        int n = n0 + ty + i, k = k0 + tx;
        float x = tile[tx][ty + i];
        __nv_bfloat16 hi = __float2bfloat16(x);
        __nv_bfloat16 lo = __float2bfloat16(x - __bfloat162float(hi));
        __nv_bfloat16* row = B2 + (size_t)n * K2;
        row[k] = hi; row[HID + k] = lo;
    }
}

// ---------------------------------------------------------------------------
// bf16 mma.sync GEMM: C = A2·B2^T, 3 products via segment-mapped k offsets:
//   c in [0,64): hi.hi   [64,128): hi.lo   [128,192): lo.hi
// BM=256, BN=128, BK=32, 4-stage cp.async, 1024 threads (32 warps 8x4, 32x32)
// ---------------------------------------------------------------------------
#define TSTRIDE 80
#define A_STAGE (256*TSTRIDE)            // 20480
#define B_STAGE (128*TSTRIDE)            // 10240
#define STAGE_B (A_STAGE + B_STAGE)      // 30720
#define SM_GEMM (4*STAGE_B)              // 122880

__global__ __launch_bounds__(1024, 1)
void gemm_bf16(const __nv_bfloat16* __restrict__ A2,
               const __nv_bfloat16* __restrict__ B2,
               float* __restrict__ C, int N) {
    extern __shared__ __align__(16) char smem[];
    const uint32_t sbase = smem_u32(smem);

    const int tid = threadIdx.x;
    const int wid = tid >> 5;
    const int lid = tid & 31;
    const int m0 = blockIdx.y * 256;
    const int n0 = blockIdx.x * 128;
    const int wm = (wid & 7) * 32;     // 8 warp rows
    const int wn = (wid >> 3) * 32;    // 4 warp cols

    const int arow = tid >> 2;
    const int ac   = tid & 3;
    const __nv_bfloat16* Abase = A2 + (size_t)(m0 + arow) * K2 + ac * 8;
    const int brow = (tid >> 2) & 127;
    const __nv_bfloat16* Bbase = B2 + (size_t)(n0 + brow) * K2 + ac * 8;
    const uint32_t sA = sbase + arow * TSTRIDE + ac * 16;
    const uint32_t sB = sbase + A_STAGE + brow * TSTRIDE + ac * 16;

    auto issue = [&](int c, int st) {
        const int cc = c & 63;
        const size_t koA = (size_t)cc * BK + ((c >= 128) ? HID : 0);
        const size_t koB = (size_t)cc * BK + ((c >= 64 && c < 128) ? HID : 0);
        const uint32_t so = (uint32_t)st * STAGE_B;
        cpasync16(sA + so, Abase + koA);
        if (tid < 512) cpasync16(sB + so, Bbase + koB);
    };

    float acc[2][4][4];
    #pragma unroll
    for (int i = 0; i < 2; i++)
        #pragma unroll
        for (int j = 0; j < 4; j++)
            #pragma unroll
            for (int r = 0; r < 4; r++) acc[i][j][r] = 0.0f;

    const uint32_t aAddr = sbase + (wm + (lid & 15)) * TSTRIDE + (lid >> 4) * 16;
    const uint32_t bAddr = sbase + A_STAGE
        + (wn + (lid & 7) + ((lid >> 4) & 1) * 8) * TSTRIDE + ((lid >> 3) & 1) * 16;

    issue(0, 0); cp_commit();
    issue(1, 1); cp_commit();
    issue(2, 2); cp_commit();

    for (int c = 0; c < NITER; c++) {
        asm volatile("cp.async.wait_group 2;" ::: "memory");
        __syncthreads();
        if (c + 3 < NITER) issue(c + 3, (c + 3) & 3);
        cp_commit();

        const uint32_t so = (uint32_t)(c & 3) * STAGE_B;
        #pragma unroll
        for (int ks = 0; ks < 2; ks++) {
            uint32_t afr[2][4], bfr[2][4];
            #pragma unroll
            for (int mt = 0; mt < 2; mt++)
                ldmatrix_x4(afr[mt], aAddr + so + mt * (16 * TSTRIDE) + ks * 32);
            #pragma unroll
            for (int ntp = 0; ntp < 2; ntp++)
                ldmatrix_x4(bfr[ntp], bAddr + so + ntp * (16 * TSTRIDE) + ks * 32);
            #pragma unroll
            for (int mt = 0; mt < 2; mt++)
                #pragma unroll
                for (int ntp = 0; ntp < 2; ntp++) {
                    mma_bf16(acc[mt][2 * ntp],     afr[mt], bfr[ntp]);
                    mma_bf16(acc[mt][2 * ntp + 1], afr[mt], bfr[ntp] + 2);
                }
        }
    }

    const int erow = (lid >> 2);
    const int ecol = (lid & 3) * 2;
    #pragma unroll
    for (int mt = 0; mt < 2; mt++) {
        #pragma unroll
        for (int nt = 0; nt < 4; nt++) {
            int r = m0 + wm + mt * 16 + erow;
            int col = n0 + wn + nt * 8 + ecol;
            *(float2*)&C[(size_t)r * N + col] = make_float2(acc[mt][nt][0], acc[mt][nt][1]);
            *(float2*)&C[(size_t)(r + 8) * N + col] = make_float2(acc[mt][nt][2], acc[mt][nt][3]);
        }
    }
}

// ---------------------------------------------------------------------------
// RoPE + fp16 split: q -> qh+ql (both), k -> kh only, v -> vh only
// ---------------------------------------------------------------------------
__global__ void rope_split(const float* __restrict__ qkv,
                           const float* __restrict__ cosb, const float* __restrict__ sinb,
                           __half* __restrict__ qh, __half* __restrict__ ql,
                           __half* __restrict__ kh, __half* __restrict__ vh) {
    const int NQP = S_LEN * NH * 64;
    const int NKP = S_LEN * NKV * 64;
    const int NV  = S_LEN * KD;
    int idx = blockIdx.x * blockDim.x + threadIdx.x;
    if (idx < NQP) {
        int d = idx & 63, hh = (idx >> 6) % NH, s = idx / (64 * NH);
        float c = cosb[s * HD + d], sn = sinb[s * HD + d];
        const float* p = qkv + (size_t)s * QKV_N + hh * HD;
        float x1 = p[d], x2 = p[d + 64];
        float y1 = x1 * c - x2 * sn, y2 = x2 * c + x1 * sn;
        size_t o = (size_t)s * QD + hh * HD + d;
        __half h1 = __float2half(y1);
        qh[o] = h1; ql[o] = __float2half(y1 - __half2float(h1));
        __half h2 = __float2half(y2);
        qh[o + 64] = h2; ql[o + 64] = __float2half(y2 - __half2float(h2));
    } else if (idx < NQP + NKP) {
        int t = idx - NQP;
        int d = t & 63, hh = (t >> 6) % NKV, s = t / (64 * NKV);
        float c = cosb[s * HD + d], sn = sinb[s * HD + d];
        const float* p = qkv + (size_t)s * QKV_N + QD + hh * HD;
        float x1 = p[d], x2 = p[d + 64];
        size_t o = (size_t)s * KD + hh * HD + d;
        kh[o]      = __float2half(x1 * c - x2 * sn);
        kh[o + 64] = __float2half(x2 * c + x1 * sn);
    } else if (idx < NQP + NKP + NV) {
        int t = idx - NQP - NKP;
        int s = t / KD, j = t - s * KD;
        vh[t] = __float2half(qkv[(size_t)s * QKV_N + QD + KD + j]);
    }
}

// ---------------------------------------------------------------------------
// Tensor-core flash attention, split-fp16 2-pass, sliding window + softcap.
// QK^T = Qh·Kh + Ql·Kh ; O = Ph·Vh + Pl·Vh. Epilogue -> a2 [hi|lo] bf16.
// ---------------------------------------------------------------------------
#define RSTR   272
#define QL_OFF 34816                  // 128*272
#define STG_OFF 69632                 // Qh+Ql
#define KSTG   17408                  // 64*272
#define STG_SZ 34816                  // Kh+Vh per stage
#define ATTN_SMEM (STG_OFF + 2*STG_SZ)  // 139264

__global__ __launch_bounds__(256, 1)
void attn_tc(const __half* __restrict__ Qh, const __half* __restrict__ Ql,
             const __half* __restrict__ Kh, const __half* __restrict__ Vh,
             __nv_bfloat16* __restrict__ Out) {
    extern __shared__ __align__(16) char smem[];
    const uint32_t sb = smem_u32(smem);
    const int tid = threadIdx.x, wid = tid >> 5, lid = tid & 31;
    const int h = blockIdx.y, q0 = blockIdx.x * 128, kvh = h >> 1;

    // Q loads: Qh + Ql, 128 rows x 16 chunks each
    #pragma unroll
    for (int i = 0; i < 16; i++) {
        int id = tid + i * 256;
        int mat = id >> 11, id2 = id & 2047;
        int row = id2 >> 4, c = id2 & 15;
        const __half* src = (mat ? Ql : Qh) + (size_t)(q0 + row) * QD + h * HD + c * 8;
        cpasync16(sb + (mat ? QL_OFF : 0) + row * RSTR + c * 16, src);
    }

    int jmin = q0 - (WINDOW - 1); if (jmin < 0) jmin = 0;
    const int t0 = jmin >> 6, t1 = (q0 + 127) >> 6;

    auto issueKV = [&](int t, int st) {
        const int kt = t << 6;
        const uint32_t sbase = sb + STG_OFF + (uint32_t)st * STG_SZ;
        #pragma unroll
        for (int i = 0; i < 8; i++) {
            int id = tid + i * 256;
            int mat = id >> 10, id2 = id & 1023;    // 0=Kh, 1=Vh
            int row = id2 >> 4, c = id2 & 15;
            const __half* base = mat ? Vh : Kh;
            cpasync16(sbase + mat * KSTG + row * RSTR + c * 16,
                      base + (size_t)(kt + row) * KD + kvh * HD + c * 8);
        }
    };
    issueKV(t0, 0); cp_commit();

    float o[16][4];
    #pragma unroll
    for (int i = 0; i < 16; i++)
        #pragma unroll
        for (int j = 0; j < 4; j++) o[i][j] = 0.0f;
    float m0 = -1e30f, m1 = -1e30f, l0 = 0.0f, l1 = 0.0f;

    const int wm = wid * 16;
    const int i0 = q0 + wm + (lid >> 2), i1 = i0 + 8;
    const uint32_t qa_h = sb + (wm + (lid & 15)) * RSTR + (lid >> 4) * 16;
    const uint32_t ka_row = (lid & 7) + ((lid >> 4) & 1) * 8;
    const uint32_t ka_coff = ((lid >> 3) & 1) * 16;
    const uint32_t v_row = (lid & 7) + ((lid >> 3) & 1) * 8;
    const uint32_t v_coff = ((lid >> 4) & 1) * 16;

    int st = 0;
    for (int t = t0; t <= t1; t++) {
        if (t < t1) { issueKV(t + 1, st ^ 1); cp_commit(); }
        if (t < t1) asm volatile("cp.async.wait_group 1;" ::: "memory");
        else        asm volatile("cp.async.wait_group 0;" ::: "memory");
        __syncthreads();

        const uint32_t stg = sb + STG_OFF + (uint32_t)st * STG_SZ;

        float sf[8][4];
        #pragma unroll
        for (int nt = 0; nt < 8; nt++)
            #pragma unroll
            for (int j = 0; j < 4; j++) sf[nt][j] = 0.0f;

        // S = Qh·Kh^T + Ql·Kh^T  (fp16 2-pass)
        #pragma unroll
        for (int pass = 0; pass < 2; pass++) {
            const uint32_t qa = pass ? qa_h + QL_OFF : qa_h;
            #pragma unroll
            for (int kk = 0; kk < 8; kk++) {
                uint32_t a[4];
                ldmatrix_x4(a, qa + kk * 32);
                #pragma unroll
                for (int ntp = 0; ntp < 4; ntp++) {
                    uint32_t b[4];
                    ldmatrix_x4(b, stg + (ntp * 16 + ka_row) * RSTR + ka_coff + kk * 32);
                    mma_f16(sf[2 * ntp],     a, b);
                    mma_f16(sf[2 * ntp + 1], a, b + 2);
                }
            }
        }

        const int jt = t << 6;
        float mx0 = -1e30f, mx1 = -1e30f;
        #pragma unroll
        for (int nt = 0; nt < 8; nt++) {
            int jb = jt + nt * 8 + ((lid & 3) << 1);
            #pragma unroll
            for (int vv = 0; vv < 4; vv++) {
                int jj = jb + (vv & 1);
                int ii = (vv < 2) ? i0 : i1;
                float e = __expf(sf[nt][vv] * TANHF2);
                float val = SOFTCAP * __fdividef(e - 1.0f, e + 1.0f);
                bool ok = (jj <= ii) && (ii - jj < WINDOW);
                sf[nt][vv] = ok ? val : -1e30f;
            }
            mx0 = fmaxf(mx0, fmaxf(sf[nt][0], sf[nt][1]));
            mx1 = fmaxf(mx1, fmaxf(sf[nt][2], sf[nt][3]));
        }
        mx0 = fmaxf(mx0, __shfl_xor_sync(0xffffffffu, mx0, 1));
        mx0 = fmaxf(mx0, __shfl_xor_sync(0xffffffffu, mx0, 2));
        mx1 = fmaxf(mx1, __shfl_xor_sync(0xffffffffu, mx1, 1));
        mx1 = fmaxf(mx1, __shfl_xor_sync(0xffffffffu, mx1, 2));

        float mn0 = fmaxf(m0, mx0), mn1 = fmaxf(m1, mx1);
        float sc0 = __expf(m0 - mn0), sc1 = __expf(m1 - mn1);
        m0 = mn0; m1 = mn1;

        float s0 = 0.0f, s1 = 0.0f;
        uint32_t phA[8], phB[8], plA[8], plB[8];
        #pragma unroll
        for (int nt = 0; nt < 8; nt++) {
            float p0 = __expf(sf[nt][0] - mn0), p1 = __expf(sf[nt][1] - mn0);
            float p2 = __expf(sf[nt][2] - mn1), p3 = __expf(sf[nt][3] - mn1);
            s0 += p0 + p1; s1 += p2 + p3;
            __half2 hA = __floats2half2_rn(p0, p1);
            __half2 hB = __floats2half2_rn(p2, p3);
            phA[nt] = *reinterpret_cast<uint32_t*>(&hA);
            phB[nt] = *reinterpret_cast<uint32_t*>(&hB);
            __half2 lA = __floats2half2_rn(p0 - __half2float(__low2half(hA)),
                                           p1 - __half2float(__high2half(hA)));
            __half2 lB = __floats2half2_rn(p2 - __half2float(__low2half(hB)),
                                           p3 - __half2float(__high2half(hB)));
            plA[nt] = *reinterpret_cast<uint32_t*>(&lA);
            plB[nt] = *reinterpret_cast<uint32_t*>(&lB);
        }
        s0 += __shfl_xor_sync(0xffffffffu, s0, 1);
        s0 += __shfl_xor_sync(0xffffffffu, s0, 2);
        s1 += __shfl_xor_sync(0xffffffffu, s1, 1);
        s1 += __shfl_xor_sync(0xffffffffu, s1, 2);
        l0 = l0 * sc0 + s0;
        l1 = l1 * sc1 + s1;

        #pragma unroll
        for (int nt = 0; nt < 16; nt++) {
            o[nt][0] *= sc0; o[nt][1] *= sc0;
            o[nt][2] *= sc1; o[nt][3] *= sc1;
        }

        // O += Ph·Vh + Pl·Vh  (fp16 2-pass)
        const uint32_t vb = stg + KSTG;
        #pragma unroll
        for (int pass = 0; pass < 2; pass++) {
            const uint32_t* pA = pass ? plA : phA;
            const uint32_t* pB = pass ? plB : phB;
            #pragma unroll
            for (int kk = 0; kk < 4; kk++) {
                uint32_t a[4] = { pA[2 * kk], pB[2 * kk], pA[2 * kk + 1], pB[2 * kk + 1] };
                #pragma unroll
                for (int np = 0; np < 8; np++) {
                    uint32_t b[4];
                    ldmatrix_x4_t(b, vb + (kk * 16 + v_row) * RSTR + np * 32 + v_coff);
                    mma_f16(o[2 * np],     a, b);
                    mma_f16(o[2 * np + 1], a, b + 2);
                }
            }
        }
        __syncthreads();
        st ^= 1;
    }

    // epilogue: normalize + write split [hi|lo] rows into a2
    const float inv0 = 1.0f / l0, inv1 = 1.0f / l1;
    #pragma unroll
    for (int nt = 0; nt < 16; nt++) {
        int col = h * HD + nt * 8 + ((lid & 3) << 1);
        {
            float x0 = o[nt][0] * inv0, x1 = o[nt][1] * inv0;
            __nv_bfloat162 hh = __floats2bfloat162_rn(x0, x1);
            __nv_bfloat162 ll = __floats2bfloat162_rn(x0 - __bfloat162float(hh.x),
                                                      x1 - __bfloat162float(hh.y));
            uint32_t* row = reinterpret_cast<uint32_t*>(Out + (size_t)i0 * K2);
            row[col >> 1] = *reinterpret_cast<uint32_t*>(&hh);
            row[(HID + col) >> 1] = *reinterpret_cast<uint32_t*>(&ll);
        }
        {
            float x0 = o[nt][2] * inv1, x1 = o[nt][3] * inv1;
            __nv_bfloat162 hh = __floats2bfloat162_rn(x0, x1);
            __nv_bfloat162 ll = __floats2bfloat162_rn(x0 - __bfloat162float(hh.x),
                                                      x1 - __bfloat162float(hh.y));
            uint32_t* row = reinterpret_cast<uint32_t*>(Out + (size_t)i1 * K2);
            row[col >> 1] = *reinterpret_cast<uint32_t*>(&hh);
            row[(HID + col) >> 1] = *reinterpret_cast<uint32_t*>(&ll);
        }
    }
}

// ---------------------------------------------------------------------------
extern "C" void kernel_launch(void* const* d_in, const int* in_sizes, int n_in,
                              void* d_out, int out_size) {
    const float* hs   = (const float*)d_in[0];
    const float* cosb = (const float*)d_in[1];
    const float* sinb = (const float*)d_in[2];
    // d_in[3] = attention_mask (unused; mask computed analytically)
    const float* Wq = (const float*)d_in[4];
    const float* Wk = (const float*)d_in[5];
    const float* Wv = (const float*)d_in[6];
    const float* Wo = (const float*)d_in[7];
    float* out = (float*)d_out;

    float *qkv;
    __nv_bfloat16 *a2, *wqkv2, *wo2;
    __half *qh, *ql, *kh, *vh;
    cudaGetSymbolAddress((void**)&qkv,   g_qkv);
    cudaGetSymbolAddress((void**)&a2,    g_a2);
    cudaGetSymbolAddress((void**)&wqkv2, g_wqkv2);
    cudaGetSymbolAddress((void**)&wo2,   g_wo2);
    cudaGetSymbolAddress((void**)&qh,    g_qh);
    cudaGetSymbolAddress((void**)&ql,    g_ql);
    cudaGetSymbolAddress((void**)&kh,    g_kh);
    cudaGetSymbolAddress((void**)&vh,    g_vh);

    cudaFuncSetAttribute(gemm_bf16, cudaFuncAttributeMaxDynamicSharedMemorySize, SM_GEMM);
    cudaFuncSetAttribute(attn_tc,  cudaFuncAttributeMaxDynamicSharedMemorySize, ATTN_SMEM);

    // split conversions (weights packed into one fused buffer: rows q|k|v)
    split_act<<<(S_LEN*HID + 255)/256, 256>>>(hs, a2, S_LEN*HID);
    split_wt<<<dim3(QD/32, HID/32), dim3(32, 8)>>>(Wq, wqkv2, QD);
    split_wt<<<dim3(KD/32, HID/32), dim3(32, 8)>>>(Wk, wqkv2 + (size_t)QD * K2, KD);
    split_wt<<<dim3(KD/32, HID/32), dim3(32, 8)>>>(Wv, wqkv2 + (size_t)(QD + KD) * K2, KD);
    split_wt<<<dim3(QD/32, HID/32), dim3(32, 8)>>>(Wo, wo2, QD);

    // fused QKV projection
    gemm_bf16<<<dim3(QKV_N/128, S_LEN/256), 1024, SM_GEMM>>>(a2, wqkv2, qkv, QKV_N);

    // fused rope + fp16 split
    int total = S_LEN*NH*64 + S_LEN*NKV*64 + S_LEN*KD;
    rope_split<<<(total + 255)/256, 256>>>(qkv, cosb, sinb, qh, ql, kh, vh);

    // tensor-core attention -> writes split activations into a2
    attn_tc<<<dim3(S_LEN/128, NH), 256, ATTN_SMEM>>>(qh, ql, kh, vh, a2);

    // output projection
    gemm_bf16<<<dim3(HID/128, S_LEN/256), 1024, SM_GEMM>>>(a2, wo2, out, HID);
}

// round 12
// speedup vs baseline: 3.5820x; 1.3315x over previous
#include <cuda_runtime.h>
#include <cuda_bf16.h>
#include <cuda_fp16.h>
#include <cstdint>
#include <math.h>

#define S_LEN 4096
#define HID   2048
#define NH    16
#define NKV   8
#define HD    128
#define QD    (NH*HD)    // 2048
#define KD    (NKV*HD)   // 1024
#define QKV_N 4096       // fused projection width: q(2048)|k(1024)|v(1024)
#define WINDOW 1024
#define SCALING 0.08838834764831845f  // 128^-0.5
#define SOFTCAP 50.0f
#define TANHF2 (2.0f*SCALING/SOFTCAP)

#define K2    (2*HID)    // 4096: activation [hi|lo] storage
#define BK    32
#define NITER 128        // 2 passes (Ah·Wh, Al·Wh) x 64 chunks

// ---------------- scratch (static device globals; no runtime alloc) ----------
__device__ float g_qkv[S_LEN*QKV_N];            // 64 MB fused q|k|v fp32
__device__ __half g_a2[S_LEN*K2];               // 32 MB split activations [hi|lo]
__device__ __half g_wqkv[QKV_N*HID];            // 16 MB fp16 weights (rows q|k|v)
__device__ __half g_wo[HID*QD];                 // 8 MB  fp16 Wo^T
__device__ __half g_qh[S_LEN*QD];               // 16 MB (post-rope fp16 split)
__device__ __half g_ql[S_LEN*QD];               // 16 MB
__device__ __half g_kh[S_LEN*KD];               // 8 MB (hi only)
__device__ __half g_vh[S_LEN*KD];               // 8 MB (hi only)

// ---------------- helpers ----------------------------------------------------
__device__ __forceinline__ uint32_t smem_u32(const void* p) {
    uint32_t a;
    asm("{ .reg .u64 t; cvta.to.shared.u64 t, %1; cvt.u32.u64 %0, t; }" : "=r"(a) : "l"(p));
    return a;
}
__device__ __forceinline__ void cpasync16(uint32_t saddr, const void* g) {
    asm volatile("cp.async.cg.shared.global [%0], [%1], 16;" :: "r"(saddr), "l"(g));
}
__device__ __forceinline__ void cp_commit() {
    asm volatile("cp.async.commit_group;" ::: "memory");
}
__device__ __forceinline__ void ldmatrix_x4(uint32_t* r, uint32_t addr) {
    asm volatile("ldmatrix.sync.aligned.m8n8.x4.shared.b16 {%0,%1,%2,%3}, [%4];"
                 : "=r"(r[0]), "=r"(r[1]), "=r"(r[2]), "=r"(r[3]) : "r"(addr));
}
__device__ __forceinline__ void ldmatrix_x4_t(uint32_t* r, uint32_t addr) {
    asm volatile("ldmatrix.sync.aligned.m8n8.x4.trans.shared.b16 {%0,%1,%2,%3}, [%4];"
                 : "=r"(r[0]), "=r"(r[1]), "=r"(r[2]), "=r"(r[3]) : "r"(addr));
}
__device__ __forceinline__ void mma_f16(float* d, const uint32_t* a, const uint32_t* b) {
    asm volatile(
        "mma.sync.aligned.m16n8k16.row.col.f32.f16.f16.f32 "
        "{%0,%1,%2,%3}, {%4,%5,%6,%7}, {%8,%9}, {%0,%1,%2,%3};"
        : "+f"(d[0]), "+f"(d[1]), "+f"(d[2]), "+f"(d[3])
        : "r"(a[0]), "r"(a[1]), "r"(a[2]), "r"(a[3]), "r"(b[0]), "r"(b[1]));
}

// ---------------------------------------------------------------------------
// split_act: x = hi(fp16) + lo(fp16); storage [hi(2048) | lo(2048)]
// ---------------------------------------------------------------------------
__global__ void split_act(const float* __restrict__ X, __half* __restrict__ A2,
                          int total) {
    int idx = blockIdx.x * blockDim.x + threadIdx.x;
    if (idx >= total) return;
    int m = idx / HID, k = idx - m * HID;
    float x = X[idx];
    __half hi = __float2half(x);
    __half lo = __float2half(x - __half2float(hi));
    __half* row = A2 + (size_t)m * K2;
    row[k] = hi; row[HID + k] = lo;
}

// W [HID, Ndim] fp32 -> B rows [Ndim, HID] fp16 (transposed + rounded)
__global__ void wt_f16(const float* __restrict__ W, __half* __restrict__ B2,
                       int Ndim) {
    __shared__ float tile[32][33];
    int k0 = blockIdx.y * 32, n0 = blockIdx.x * 32;
    int tx = threadIdx.x, ty = threadIdx.y;   // 32 x 8
    #pragma unroll
    for (int i = 0; i < 32; i += 8)
        tile[ty + i][tx] = W[(size_t)(k0 + ty + i) * Ndim + n0 + tx];
    __syncthreads();
    #pragma unroll
    for (int i = 0; i < 32; i += 8) {
        int n = n0 + ty + i, k = k0 + tx;
        B2[(size_t)n * HID + k] = __float2half(tile[tx][ty + i]);
    }
}

// ---------------------------------------------------------------------------
// fp16 mma.sync GEMM: C = (Ah+Al)·W^T, 2 passes via segment-mapped A offsets:
//   c in [0,64): Ah·Wh    [64,128): Al·Wh
// BM=256, BN=128, BK=32, 4-stage cp.async, 1024 threads (32 warps 8x4, 32x32)
// A row stride = K2 (split storage); B row stride = HID (fp16 rounded).
// ---------------------------------------------------------------------------
#define TSTRIDE 80
#define A_STAGE (256*TSTRIDE)            // 20480
#define B_STAGE (128*TSTRIDE)            // 10240
#define STAGE_B (A_STAGE + B_STAGE)      // 30720
#define SM_GEMM (4*STAGE_B)              // 122880

__global__ __launch_bounds__(1024, 1)
void gemm_f16(const __half* __restrict__ A2,
              const __half* __restrict__ B2,
              float* __restrict__ C, int N) {
    extern __shared__ __align__(16) char smem[];
    const uint32_t sbase = smem_u32(smem);

    const int tid = threadIdx.x;
    const int wid = tid >> 5;
    const int lid = tid & 31;
    const int m0 = blockIdx.y * 256;
    const int n0 = blockIdx.x * 128;
    const int wm = (wid & 7) * 32;     // 8 warp rows
    const int wn = (wid >> 3) * 32;    // 4 warp cols

    const int arow = tid >> 2;
    const int ac   = tid & 3;
    const __half* Abase = A2 + (size_t)(m0 + arow) * K2 + ac * 8;
    const int brow = (tid >> 2) & 127;
    const __half* Bbase = B2 + (size_t)(n0 + brow) * HID + ac * 8;
    const uint32_t sA = sbase + arow * TSTRIDE + ac * 16;
    const uint32_t sB = sbase + A_STAGE + brow * TSTRIDE + ac * 16;

    auto issue = [&](int c, int st) {
        const int cc = c & 63;
        const size_t koA = (size_t)cc * BK + ((c >= 64) ? HID : 0);
        const size_t koB = (size_t)cc * BK;
        const uint32_t so = (uint32_t)st * STAGE_B;
        cpasync16(sA + so, Abase + koA);
        if (tid < 512) cpasync16(sB + so, Bbase + koB);
    };

    float acc[2][4][4];
    #pragma unroll
    for (int i = 0; i < 2; i++)
        #pragma unroll
        for (int j = 0; j < 4; j++)
            #pragma unroll
            for (int r = 0; r < 4; r++) acc[i][j][r] = 0.0f;

    const uint32_t aAddr = sbase + (wm + (lid & 15)) * TSTRIDE + (lid >> 4) * 16;
    const uint32_t bAddr = sbase + A_STAGE
        + (wn + (lid & 7) + ((lid >> 4) & 1) * 8) * TSTRIDE + ((lid >> 3) & 1) * 16;

    issue(0, 0); cp_commit();
    issue(1, 1); cp_commit();
    issue(2, 2); cp_commit();

    for (int c = 0; c < NITER; c++) {
        asm volatile("cp.async.wait_group 2;" ::: "memory");
        __syncthreads();
        if (c + 3 < NITER) issue(c + 3, (c + 3) & 3);
        cp_commit();

        const uint32_t so = (uint32_t)(c & 3) * STAGE_B;
        #pragma unroll
        for (int ks = 0; ks < 2; ks++) {
            uint32_t afr[2][4], bfr[2][4];
            #pragma unroll
            for (int mt = 0; mt < 2; mt++)
                ldmatrix_x4(afr[mt], aAddr + so + mt * (16 * TSTRIDE) + ks * 32);
            #pragma unroll
            for (int ntp = 0; ntp < 2; ntp++)
                ldmatrix_x4(bfr[ntp], bAddr + so + ntp * (16 * TSTRIDE) + ks * 32);
            #pragma unroll
            for (int mt = 0; mt < 2; mt++)
                #pragma unroll
                for (int ntp = 0; ntp < 2; ntp++) {
                    mma_f16(acc[mt][2 * ntp],     afr[mt], bfr[ntp]);
                    mma_f16(acc[mt][2 * ntp + 1], afr[mt], bfr[ntp] + 2);
                }
        }
    }

    const int erow = (lid >> 2);
    const int ecol = (lid & 3) * 2;
    #pragma unroll
    for (int mt = 0; mt < 2; mt++) {
        #pragma unroll
        for (int nt = 0; nt < 4; nt++) {
            int r = m0 + wm + mt * 16 + erow;
            int col = n0 + wn + nt * 8 + ecol;
            *(float2*)&C[(size_t)r * N + col] = make_float2(acc[mt][nt][0], acc[mt][nt][1]);
            *(float2*)&C[(size_t)(r + 8) * N + col] = make_float2(acc[mt][nt][2], acc[mt][nt][3]);
        }
    }
}

// ---------------------------------------------------------------------------
// RoPE + fp16 split: q -> qh+ql (both), k -> kh only, v -> vh only
// ---------------------------------------------------------------------------
__global__ void rope_split(const float* __restrict__ qkv,
                           const float* __restrict__ cosb, const float* __restrict__ sinb,
                           __half* __restrict__ qh, __half* __restrict__ ql,
                           __half* __restrict__ kh, __half* __restrict__ vh) {
    const int NQP = S_LEN * NH * 64;
    const int NKP = S_LEN * NKV * 64;
    const int NV  = S_LEN * KD;
    int idx = blockIdx.x * blockDim.x + threadIdx.x;
    if (idx < NQP) {
        int d = idx & 63, hh = (idx >> 6) % NH, s = idx / (64 * NH);
        float c = cosb[s * HD + d], sn = sinb[s * HD + d];
        const float* p = qkv + (size_t)s * QKV_N + hh * HD;
        float x1 = p[d], x2 = p[d + 64];
        float y1 = x1 * c - x2 * sn, y2 = x2 * c + x1 * sn;
        size_t o = (size_t)s * QD + hh * HD + d;
        __half h1 = __float2half(y1);
        qh[o] = h1; ql[o] = __float2half(y1 - __half2float(h1));
        __half h2 = __float2half(y2);
        qh[o + 64] = h2; ql[o + 64] = __float2half(y2 - __half2float(h2));
    } else if (idx < NQP + NKP) {
        int t = idx - NQP;
        int d = t & 63, hh = (t >> 6) % NKV, s = t / (64 * NKV);
        float c = cosb[s * HD + d], sn = sinb[s * HD + d];
        const float* p = qkv + (size_t)s * QKV_N + QD + hh * HD;
        float x1 = p[d], x2 = p[d + 64];
        size_t o = (size_t)s * KD + hh * HD + d;
        kh[o]      = __float2half(x1 * c - x2 * sn);
        kh[o + 64] = __float2half(x2 * c + x1 * sn);
    } else if (idx < NQP + NKP + NV) {
        int t = idx - NQP - NKP;
        int s = t / KD, j = t - s * KD;
        vh[t] = __float2half(qkv[(size_t)s * QKV_N + QD + KD + j]);
    }
}

// ---------------------------------------------------------------------------
// Tensor-core flash attention, split-fp16 2-pass, sliding window + softcap.
// QK^T = Qh·Kh + Ql·Kh ; O = Ph·Vh + Pl·Vh. Epilogue -> a2 [hi|lo] fp16.
// ---------------------------------------------------------------------------
#define RSTR   272
#define QL_OFF 34816                  // 128*272
#define STG_OFF 69632                 // Qh+Ql
#define KSTG   17408                  // 64*272
#define STG_SZ 34816                  // Kh+Vh per stage
#define ATTN_SMEM (STG_OFF + 2*STG_SZ)  // 139264

__global__ __launch_bounds__(256, 1)
void attn_tc(const __half* __restrict__ Qh, const __half* __restrict__ Ql,
             const __half* __restrict__ Kh, const __half* __restrict__ Vh,
             __half* __restrict__ Out) {
    extern __shared__ __align__(16) char smem[];
    const uint32_t sb = smem_u32(smem);
    const int tid = threadIdx.x, wid = tid >> 5, lid = tid & 31;
    const int h = blockIdx.y, q0 = blockIdx.x * 128, kvh = h >> 1;

    // Q loads: Qh + Ql, 128 rows x 16 chunks each
    #pragma unroll
    for (int i = 0; i < 16; i++) {
        int id = tid + i * 256;
        int mat = id >> 11, id2 = id & 2047;
        int row = id2 >> 4, c = id2 & 15;
        const __half* src = (mat ? Ql : Qh) + (size_t)(q0 + row) * QD + h * HD + c * 8;
        cpasync16(sb + (mat ? QL_OFF : 0) + row * RSTR + c * 16, src);
    }

    int jmin = q0 - (WINDOW - 1); if (jmin < 0) jmin = 0;
    const int t0 = jmin >> 6, t1 = (q0 + 127) >> 6;

    auto issueKV = [&](int t, int st) {
        const int kt = t << 6;
        const uint32_t sbase = sb + STG_OFF + (uint32_t)st * STG_SZ;
        #pragma unroll
        for (int i = 0; i < 8; i++) {
            int id = tid + i * 256;
            int mat = id >> 10, id2 = id & 1023;    // 0=Kh, 1=Vh
            int row = id2 >> 4, c = id2 & 15;
            const __half* base = mat ? Vh : Kh;
            cpasync16(sbase + mat * KSTG + row * RSTR + c * 16,
                      base + (size_t)(kt + row) * KD + kvh * HD + c * 8);
        }
    };
    issueKV(t0, 0); cp_commit();

    float o[16][4];
    #pragma unroll
    for (int i = 0; i < 16; i++)
        #pragma unroll
        for (int j = 0; j < 4; j++) o[i][j] = 0.0f;
    float m0 = -1e30f, m1 = -1e30f, l0 = 0.0f, l1 = 0.0f;

    const int wm = wid * 16;
    const int i0 = q0 + wm + (lid >> 2), i1 = i0 + 8;
    const uint32_t qa_h = sb + (wm + (lid & 15)) * RSTR + (lid >> 4) * 16;
    const uint32_t ka_row = (lid & 7) + ((lid >> 4) & 1) * 8;
    const uint32_t ka_coff = ((lid >> 3) & 1) * 16;
    const uint32_t v_row = (lid & 7) + ((lid >> 3) & 1) * 8;
    const uint32_t v_coff = ((lid >> 4) & 1) * 16;

    int st = 0;
    for (int t = t0; t <= t1; t++) {
        if (t < t1) { issueKV(t + 1, st ^ 1); cp_commit(); }
        if (t < t1) asm volatile("cp.async.wait_group 1;" ::: "memory");
        else        asm volatile("cp.async.wait_group 0;" ::: "memory");
        __syncthreads();

        const uint32_t stg = sb + STG_OFF + (uint32_t)st * STG_SZ;

        float sf[8][4];
        #pragma unroll
        for (int nt = 0; nt < 8; nt++)
            #pragma unroll
            for (int j = 0; j < 4; j++) sf[nt][j] = 0.0f;

        // S = Qh·Kh^T + Ql·Kh^T
        #pragma unroll
        for (int pass = 0; pass < 2; pass++) {
            const uint32_t qa = pass ? qa_h + QL_OFF : qa_h;
            #pragma unroll
            for (int kk = 0; kk < 8; kk++) {
                uint32_t a[4];
                ldmatrix_x4(a, qa + kk * 32);
                #pragma unroll
                for (int ntp = 0; ntp < 4; ntp++) {
                    uint32_t b[4];
                    ldmatrix_x4(b, stg + (ntp * 16 + ka_row) * RSTR + ka_coff + kk * 32);
                    mma_f16(sf[2 * ntp],     a, b);
                    mma_f16(sf[2 * ntp + 1], a, b + 2);
                }
            }
        }

        const int jt = t << 6;
        float mx0 = -1e30f, mx1 = -1e30f;
        #pragma unroll
        for (int nt = 0; nt < 8; nt++) {
            int jb = jt + nt * 8 + ((lid & 3) << 1);
            #pragma unroll
            for (int vv = 0; vv < 4; vv++) {
                int jj = jb + (vv & 1);
                int ii = (vv < 2) ? i0 : i1;
                float e = __expf(sf[nt][vv] * TANHF2);
                float val = SOFTCAP * __fdividef(e - 1.0f, e + 1.0f);
                bool ok = (jj <= ii) && (ii - jj < WINDOW);
                sf[nt][vv] = ok ? val : -1e30f;
            }
            mx0 = fmaxf(mx0, fmaxf(sf[nt][0], sf[nt][1]));
            mx1 = fmaxf(mx1, fmaxf(sf[nt][2], sf[nt][3]));
        }
        mx0 = fmaxf(mx0, __shfl_xor_sync(0xffffffffu, mx0, 1));
        mx0 = fmaxf(mx0, __shfl_xor_sync(0xffffffffu, mx0, 2));
        mx1 = fmaxf(mx1, __shfl_xor_sync(0xffffffffu, mx1, 1));
        mx1 = fmaxf(mx1, __shfl_xor_sync(0xffffffffu, mx1, 2));

        float mn0 = fmaxf(m0, mx0), mn1 = fmaxf(m1, mx1);
        float sc0 = __expf(m0 - mn0), sc1 = __expf(m1 - mn1);
        m0 = mn0; m1 = mn1;

        float s0 = 0.0f, s1 = 0.0f;
        uint32_t phA[8], phB[8], plA[8], plB[8];
        #pragma unroll
        for (int nt = 0; nt < 8; nt++) {
            float p0 = __expf(sf[nt][0] - mn0), p1 = __expf(sf[nt][1] - mn0);
            float p2 = __expf(sf[nt][2] - mn1), p3 = __expf(sf[nt][3] - mn1);
            s0 += p0 + p1; s1 += p2 + p3;
            __half2 hA = __floats2half2_rn(p0, p1);
            __half2 hB = __floats2half2_rn(p2, p3);
            phA[nt] = *reinterpret_cast<uint32_t*>(&hA);
            phB[nt] = *reinterpret_cast<uint32_t*>(&hB);
            __half2 lA = __floats2half2_rn(p0 - __half2float(__low2half(hA)),
                                           p1 - __half2float(__high2half(hA)));
            __half2 lB = __floats2half2_rn(p2 - __half2float(__low2half(hB)),
                                           p3 - __half2float(__high2half(hB)));
            plA[nt] = *reinterpret_cast<uint32_t*>(&lA);
            plB[nt] = *reinterpret_cast<uint32_t*>(&lB);
        }
        s0 += __shfl_xor_sync(0xffffffffu, s0, 1);
        s0 += __shfl_xor_sync(0xffffffffu, s0, 2);
        s1 += __shfl_xor_sync(0xffffffffu, s1, 1);
        s1 += __shfl_xor_sync(0xffffffffu, s1, 2);
        l0 = l0 * sc0 + s0;
        l1 = l1 * sc1 + s1;

        #pragma unroll
        for (int nt = 0; nt < 16; nt++) {
            o[nt][0] *= sc0; o[nt][1] *= sc0;
            o[nt][2] *= sc1; o[nt][3] *= sc1;
        }

        // O += Ph·Vh + Pl·Vh
        const uint32_t vb = stg + KSTG;
        #pragma unroll
        for (int pass = 0; pass < 2; pass++) {
            const uint32_t* pA = pass ? plA : phA;
            const uint32_t* pB = pass ? plB : phB;
            #pragma unroll
            for (int kk = 0; kk < 4; kk++) {
                uint32_t a[4] = { pA[2 * kk], pB[2 * kk], pA[2 * kk + 1], pB[2 * kk + 1] };
                #pragma unroll
                for (int np = 0; np < 8; np++) {
                    uint32_t b[4];
                    ldmatrix_x4_t(b, vb + (kk * 16 + v_row) * RSTR + np * 32 + v_coff);
                    mma_f16(o[2 * np],     a, b);
                    mma_f16(o[2 * np + 1], a, b + 2);
                }
            }
        }
        __syncthreads();
        st ^= 1;
    }

    // epilogue: normalize + write split [hi|lo] fp16 rows into a2
    const float inv0 = 1.0f / l0, inv1 = 1.0f / l1;
    #pragma unroll
    for (int nt = 0; nt < 16; nt++) {
        int col = h * HD + nt * 8 + ((lid & 3) << 1);
        {
            float x0 = o[nt][0] * inv0, x1 = o[nt][1] * inv0;
            __half2 hh = __floats2half2_rn(x0, x1);
            __half2 ll = __floats2half2_rn(x0 - __half2float(__low2half(hh)),
                                           x1 - __half2float(__high2half(hh)));
            uint32_t* row = reinterpret_cast<uint32_t*>(Out + (size_t)i0 * K2);
            row[col >> 1] = *reinterpret_cast<uint32_t*>(&hh);
            row[(HID + col) >> 1] = *reinterpret_cast<uint32_t*>(&ll);
        }
        {
            float x0 = o[nt][2] * inv1, x1 = o[nt][3] * inv1;
            __half2 hh = __floats2half2_rn(x0, x1);
            __half2 ll = __floats2half2_rn(x0 - __half2float(__low2half(hh)),
                                           x1 - __half2float(__high2half(hh)));
            uint32_t* row = reinterpret_cast<uint32_t*>(Out + (size_t)i1 * K2);
            row[col >> 1] = *reinterpret_cast<uint32_t*>(&hh);
            row[(HID + col) >> 1] = *reinterpret_cast<uint32_t*>(&ll);
        }
    }
}

// ---------------------------------------------------------------------------
extern "C" void kernel_launch(void* const* d_in, const int* in_sizes, int n_in,
                              void* d_out, int out_size) {
    const float* hs   = (const float*)d_in[0];
    const float* cosb = (const float*)d_in[1];
    const float* sinb = (const float*)d_in[2];
    // d_in[3] = attention_mask (unused; mask computed analytically)
    const float* Wq = (const float*)d_in[4];
    const float* Wk = (const float*)d_in[5];
    const float* Wv = (const float*)d_in[6];
    const float* Wo = (const float*)d_in[7];
    float* out = (float*)d_out;

    float *qkv;
    __half *a2, *wqkv, *wo, *qh, *ql, *kh, *vh;
    cudaGetSymbolAddress((void**)&qkv,  g_qkv);
    cudaGetSymbolAddress((void**)&a2,   g_a2);
    cudaGetSymbolAddress((void**)&wqkv, g_wqkv);
    cudaGetSymbolAddress((void**)&wo,   g_wo);
    cudaGetSymbolAddress((void**)&qh,   g_qh);
    cudaGetSymbolAddress((void**)&ql,   g_ql);
    cudaGetSymbolAddress((void**)&kh,   g_kh);
    cudaGetSymbolAddress((void**)&vh,   g_vh);

    cudaFuncSetAttribute(gemm_f16, cudaFuncAttributeMaxDynamicSharedMemorySize, SM_GEMM);
    cudaFuncSetAttribute(attn_tc, cudaFuncAttributeMaxDynamicSharedMemorySize, ATTN_SMEM);

    // conversions (weights packed into one fused fp16 buffer: rows q|k|v)
    split_act<<<(S_LEN*HID + 255)/256, 256>>>(hs, a2, S_LEN*HID);
    wt_f16<<<dim3(QD/32, HID/32), dim3(32, 8)>>>(Wq, wqkv, QD);
    wt_f16<<<dim3(KD/32, HID/32), dim3(32, 8)>>>(Wk, wqkv + (size_t)QD * HID, KD);
    wt_f16<<<dim3(KD/32, HID/32), dim3(32, 8)>>>(Wv, wqkv + (size_t)(QD + KD) * HID, KD);
    wt_f16<<<dim3(QD/32, HID/32), dim3(32, 8)>>>(Wo, wo, QD);

    // fused QKV projection (fp16 2-pass)
    gemm_f16<<<dim3(QKV_N/128, S_LEN/256), 1024, SM_GEMM>>>(a2, wqkv, qkv, QKV_N);

    // fused rope + fp16 split
    int total = S_LEN*NH*64 + S_LEN*NKV*64 + S_LEN*KD;
    rope_split<<<(total + 255)/256, 256>>>(qkv, cosb, sinb, qh, ql, kh, vh);

    // tensor-core attention -> writes split activations into a2
    attn_tc<<<dim3(S_LEN/128, NH), 256, ATTN_SMEM>>>(qh, ql, kh, vh, a2);

    // output projection (fp16 2-pass)
    gemm_f16<<<dim3(HID/128, S_LEN/256), 1024, SM_GEMM>>>(a2, wo, out, HID);
}

// round 14
// speedup vs baseline: 3.8321x; 1.0698x over previous
#include <cuda_runtime.h>
#include <cuda_bf16.h>
#include <cuda_fp16.h>
#include <cstdint>
#include <math.h>

#define S_LEN 4096
#define HID   2048
#define NH    16
#define NKV   8
#define HD    128
#define QD    (NH*HD)    // 2048
#define KD    (NKV*HD)   // 1024
#define QKV_N 4096       // fused projection width: q(2048)|k(1024)|v(1024)
#define WINDOW 1024
#define SCALING 0.08838834764831845f  // 128^-0.5
#define SOFTCAP 50.0f
#define TANHF2 (2.0f*SCALING/SOFTCAP)

#define K2    (2*HID)    // 4096: activation [hi|lo] storage
#define BK    32
#define NITER 128        // 2 passes (Ah·Wh, Al·Wh) x 64 chunks

// ---------------- scratch (static device globals; no runtime alloc) ----------
__device__ float g_qkv[S_LEN*QKV_N];            // 64 MB fused q|k|v fp32
__device__ __half g_a2[S_LEN*K2];               // 32 MB split activations [hi|lo]
__device__ __half g_wqkv[QKV_N*HID];            // 16 MB fp16 weights (rows q|k|v)
__device__ __half g_wo[HID*QD];                 // 8 MB  fp16 Wo^T
__device__ __half g_qh[S_LEN*QD];               // 16 MB (post-rope fp16)
__device__ __half g_kh[S_LEN*KD];               // 8 MB
__device__ __half g_vh[S_LEN*KD];               // 8 MB

// ---------------- helpers ----------------------------------------------------
__device__ __forceinline__ uint32_t smem_u32(const void* p) {
    uint32_t a;
    asm("{ .reg .u64 t; cvta.to.shared.u64 t, %1; cvt.u32.u64 %0, t; }" : "=r"(a) : "l"(p));
    return a;
}
__device__ __forceinline__ void cpasync16(uint32_t saddr, const void* g) {
    asm volatile("cp.async.cg.shared.global [%0], [%1], 16;" :: "r"(saddr), "l"(g));
}
__device__ __forceinline__ void cp_commit() {
    asm volatile("cp.async.commit_group;" ::: "memory");
}
__device__ __forceinline__ void ldmatrix_x4(uint32_t* r, uint32_t addr) {
    asm volatile("ldmatrix.sync.aligned.m8n8.x4.shared.b16 {%0,%1,%2,%3}, [%4];"
                 : "=r"(r[0]), "=r"(r[1]), "=r"(r[2]), "=r"(r[3]) : "r"(addr));
}
__device__ __forceinline__ void ldmatrix_x4_t(uint32_t* r, uint32_t addr) {
    asm volatile("ldmatrix.sync.aligned.m8n8.x4.trans.shared.b16 {%0,%1,%2,%3}, [%4];"
                 : "=r"(r[0]), "=r"(r[1]), "=r"(r[2]), "=r"(r[3]) : "r"(addr));
}
__device__ __forceinline__ void mma_f16(float* d, const uint32_t* a, const uint32_t* b) {
    asm volatile(
        "mma.sync.aligned.m16n8k16.row.col.f32.f16.f16.f32 "
        "{%0,%1,%2,%3}, {%4,%5,%6,%7}, {%8,%9}, {%0,%1,%2,%3};"
        : "+f"(d[0]), "+f"(d[1]), "+f"(d[2]), "+f"(d[3])
        : "r"(a[0]), "r"(a[1]), "r"(a[2]), "r"(a[3]), "r"(b[0]), "r"(b[1]));
}

// ---------------------------------------------------------------------------
// split_act: x = hi(fp16) + lo(fp16); storage [hi(2048) | lo(2048)]
// ---------------------------------------------------------------------------
__global__ void split_act(const float* __restrict__ X, __half* __restrict__ A2,
                          int total) {
    int idx = blockIdx.x * blockDim.x + threadIdx.x;
    if (idx >= total) return;
    int m = idx / HID, k = idx - m * HID;
    float x = X[idx];
    __half hi = __float2half(x);
    __half lo = __float2half(x - __half2float(hi));
    __half* row = A2 + (size_t)m * K2;
    row[k] = hi; row[HID + k] = lo;
}

// W [HID, Ndim] fp32 -> B rows [Ndim, HID] fp16 (transposed + rounded)
__global__ void wt_f16(const float* __restrict__ W, __half* __restrict__ B2,
                       int Ndim) {
    __shared__ float tile[32][33];
    int k0 = blockIdx.y * 32, n0 = blockIdx.x * 32;
    int tx = threadIdx.x, ty = threadIdx.y;   // 32 x 8
    #pragma unroll
    for (int i = 0; i < 32; i += 8)
        tile[ty + i][tx] = W[(size_t)(k0 + ty + i) * Ndim + n0 + tx];
    __syncthreads();
    #pragma unroll
    for (int i = 0; i < 32; i += 8) {
        int n = n0 + ty + i, k = k0 + tx;
        B2[(size_t)n * HID + k] = __float2half(tile[tx][ty + i]);
    }
}

// ---------------------------------------------------------------------------
// fp16 mma.sync GEMM: C = (Ah+Al)·W^T, 2 passes via segment-mapped A offsets:
//   c in [0,64): Ah·Wh    [64,128): Al·Wh
// BM=256, BN=128, BK=32, 4-stage cp.async, 1024 threads (32 warps 8x4, 32x32)
// ---------------------------------------------------------------------------
#define TSTRIDE 80
#define A_STAGE (256*TSTRIDE)            // 20480
#define B_STAGE (128*TSTRIDE)            // 10240
#define STAGE_B (A_STAGE + B_STAGE)      // 30720
#define SM_GEMM (4*STAGE_B)              // 122880

__global__ __launch_bounds__(1024, 1)
void gemm_f16(const __half* __restrict__ A2,
              const __half* __restrict__ B2,
              float* __restrict__ C, int N) {
    extern __shared__ __align__(16) char smem[];
    const uint32_t sbase = smem_u32(smem);

    const int tid = threadIdx.x;
    const int wid = tid >> 5;
    const int lid = tid & 31;
    const int m0 = blockIdx.y * 256;
    const int n0 = blockIdx.x * 128;
    const int wm = (wid & 7) * 32;     // 8 warp rows
    const int wn = (wid >> 3) * 32;    // 4 warp cols

    const int arow = tid >> 2;
    const int ac   = tid & 3;
    const __half* Abase = A2 + (size_t)(m0 + arow) * K2 + ac * 8;
    const int brow = (tid >> 2) & 127;
    const __half* Bbase = B2 + (size_t)(n0 + brow) * HID + ac * 8;
    const uint32_t sA = sbase + arow * TSTRIDE + ac * 16;
    const uint32_t sB = sbase + A_STAGE + brow * TSTRIDE + ac * 16;

    auto issue = [&](int c, int st) {
        const int cc = c & 63;
        const size_t koA = (size_t)cc * BK + ((c >= 64) ? HID : 0);
        const size_t koB = (size_t)cc * BK;
        const uint32_t so = (uint32_t)st * STAGE_B;
        cpasync16(sA + so, Abase + koA);
        if (tid < 512) cpasync16(sB + so, Bbase + koB);
    };

    float acc[2][4][4];
    #pragma unroll
    for (int i = 0; i < 2; i++)
        #pragma unroll
        for (int j = 0; j < 4; j++)
            #pragma unroll
            for (int r = 0; r < 4; r++) acc[i][j][r] = 0.0f;

    const uint32_t aAddr = sbase + (wm + (lid & 15)) * TSTRIDE + (lid >> 4) * 16;
    const uint32_t bAddr = sbase + A_STAGE
        + (wn + (lid & 7) + ((lid >> 4) & 1) * 8) * TSTRIDE + ((lid >> 3) & 1) * 16;

    issue(0, 0); cp_commit();
    issue(1, 1); cp_commit();
    issue(2, 2); cp_commit();

    for (int c = 0; c < NITER; c++) {
        asm volatile("cp.async.wait_group 2;" ::: "memory");
        __syncthreads();
        if (c + 3 < NITER) issue(c + 3, (c + 3) & 3);
        cp_commit();

        const uint32_t so = (uint32_t)(c & 3) * STAGE_B;
        #pragma unroll
        for (int ks = 0; ks < 2; ks++) {
            uint32_t afr[2][4], bfr[2][4];
            #pragma unroll
            for (int mt = 0; mt < 2; mt++)
                ldmatrix_x4(afr[mt], aAddr + so + mt * (16 * TSTRIDE) + ks * 32);
            #pragma unroll
            for (int ntp = 0; ntp < 2; ntp++)
                ldmatrix_x4(bfr[ntp], bAddr + so + ntp * (16 * TSTRIDE) + ks * 32);
            #pragma unroll
            for (int mt = 0; mt < 2; mt++)
                #pragma unroll
                for (int ntp = 0; ntp < 2; ntp++) {
                    mma_f16(acc[mt][2 * ntp],     afr[mt], bfr[ntp]);
                    mma_f16(acc[mt][2 * ntp + 1], afr[mt], bfr[ntp] + 2);
                }
        }
    }

    const int erow = (lid >> 2);
    const int ecol = (lid & 3) * 2;
    #pragma unroll
    for (int mt = 0; mt < 2; mt++) {
        #pragma unroll
        for (int nt = 0; nt < 4; nt++) {
            int r = m0 + wm + mt * 16 + erow;
            int col = n0 + wn + nt * 8 + ecol;
            *(float2*)&C[(size_t)r * N + col] = make_float2(acc[mt][nt][0], acc[mt][nt][1]);
            *(float2*)&C[(size_t)(r + 8) * N + col] = make_float2(acc[mt][nt][2], acc[mt][nt][3]);
        }
    }
}

// ---------------------------------------------------------------------------
// RoPE + fp16 convert: q -> qh, k -> kh, v -> vh (all hi only)
// ---------------------------------------------------------------------------
__global__ void rope_split(const float* __restrict__ qkv,
                           const float* __restrict__ cosb, const float* __restrict__ sinb,
                           __half* __restrict__ qh, __half* __restrict__ kh,
                           __half* __restrict__ vh) {
    const int NQP = S_LEN * NH * 64;
    const int NKP = S_LEN * NKV * 64;
    const int NV  = S_LEN * KD;
    int idx = blockIdx.x * blockDim.x + threadIdx.x;
    if (idx < NQP) {
        int d = idx & 63, hh = (idx >> 6) % NH, s = idx / (64 * NH);
        float c = cosb[s * HD + d], sn = sinb[s * HD + d];
        const float* p = qkv + (size_t)s * QKV_N + hh * HD;
        float x1 = p[d], x2 = p[d + 64];
        size_t o = (size_t)s * QD + hh * HD + d;
        qh[o]      = __float2half(x1 * c - x2 * sn);
        qh[o + 64] = __float2half(x2 * c + x1 * sn);
    } else if (idx < NQP + NKP) {
        int t = idx - NQP;
        int d = t & 63, hh = (t >> 6) % NKV, s = t / (64 * NKV);
        float c = cosb[s * HD + d], sn = sinb[s * HD + d];
        const float* p = qkv + (size_t)s * QKV_N + QD + hh * HD;
        float x1 = p[d], x2 = p[d + 64];
        size_t o = (size_t)s * KD + hh * HD + d;
        kh[o]      = __float2half(x1 * c - x2 * sn);
        kh[o + 64] = __float2half(x2 * c + x1 * sn);
    } else if (idx < NQP + NKP + NV) {
        int t = idx - NQP - NKP;
        int s = t / KD, j = t - s * KD;
        vh[t] = __float2half(qkv[(size_t)s * QKV_N + QD + KD + j]);
    }
}

// ---------------------------------------------------------------------------
// Tensor-core flash attention, pure fp16 single-pass, sliding window + softcap.
// S = Qh·Kh^T ; O = Ph·Vh. Epilogue -> a2 [hi|lo] fp16 for 2-pass O-proj.
// ---------------------------------------------------------------------------
#define RSTR   272
#define STG_OFF 34816                 // Qh region (128*272)
#define KSTG   17408                  // 64*272
#define STG_SZ 34816                  // Kh+Vh per stage
#define ATTN_SMEM (STG_OFF + 2*STG_SZ)  // 104448

__global__ __launch_bounds__(256)
void attn_tc(const __half* __restrict__ Qh,
             const __half* __restrict__ Kh, const __half* __restrict__ Vh,
             __half* __restrict__ Out) {
    extern __shared__ __align__(16) char smem[];
    const uint32_t sb = smem_u32(smem);
    const int tid = threadIdx.x, wid = tid >> 5, lid = tid & 31;
    const int h = blockIdx.y, q0 = blockIdx.x * 128, kvh = h >> 1;

    // Q loads: 128 rows x 16 chunks
    #pragma unroll
    for (int i = 0; i < 8; i++) {
        int id = tid + i * 256;
        int row = id >> 4, c = id & 15;
        cpasync16(sb + row * RSTR + c * 16,
                  Qh + (size_t)(q0 + row) * QD + h * HD + c * 8);
    }

    int jmin = q0 - (WINDOW - 1); if (jmin < 0) jmin = 0;
    const int t0 = jmin >> 6, t1 = (q0 + 127) >> 6;

    auto issueKV = [&](int t, int st) {
        const int kt = t << 6;
        const uint32_t sbase = sb + STG_OFF + (uint32_t)st * STG_SZ;
        #pragma unroll
        for (int i = 0; i < 8; i++) {
            int id = tid + i * 256;
            int mat = id >> 10, id2 = id & 1023;    // 0=Kh, 1=Vh
            int row = id2 >> 4, c = id2 & 15;
            const __half* base = mat ? Vh : Kh;
            cpasync16(sbase + mat * KSTG + row * RSTR + c * 16,
                      base + (size_t)(kt + row) * KD + kvh * HD + c * 8);
        }
    };
    issueKV(t0, 0); cp_commit();

    float o[16][4];
    #pragma unroll
    for (int i = 0; i < 16; i++)
        #pragma unroll
        for (int j = 0; j < 4; j++) o[i][j] = 0.0f;
    float m0 = -1e30f, m1 = -1e30f, l0 = 0.0f, l1 = 0.0f;

    const int wm = wid * 16;
    const int i0 = q0 + wm + (lid >> 2), i1 = i0 + 8;
    const uint32_t qa_h = sb + (wm + (lid & 15)) * RSTR + (lid >> 4) * 16;
    const uint32_t ka_row = (lid & 7) + ((lid >> 4) & 1) * 8;
    const uint32_t ka_coff = ((lid >> 3) & 1) * 16;
    const uint32_t v_row = (lid & 7) + ((lid >> 3) & 1) * 8;
    const uint32_t v_coff = ((lid >> 4) & 1) * 16;

    int st = 0;
    for (int t = t0; t <= t1; t++) {
        if (t < t1) { issueKV(t + 1, st ^ 1); cp_commit(); }
        if (t < t1) asm volatile("cp.async.wait_group 1;" ::: "memory");
        else        asm volatile("cp.async.wait_group 0;" ::: "memory");
        __syncthreads();

        const uint32_t stg = sb + STG_OFF + (uint32_t)st * STG_SZ;

        float sf[8][4];
        #pragma unroll
        for (int nt = 0; nt < 8; nt++)
            #pragma unroll
            for (int j = 0; j < 4; j++) sf[nt][j] = 0.0f;

        // S = Qh·Kh^T (single pass)
        #pragma unroll
        for (int kk = 0; kk < 8; kk++) {
            uint32_t a[4];
            ldmatrix_x4(a, qa_h + kk * 32);
            #pragma unroll
            for (int ntp = 0; ntp < 4; ntp++) {
                uint32_t b[4];
                ldmatrix_x4(b, stg + (ntp * 16 + ka_row) * RSTR + ka_coff + kk * 32);
                mma_f16(sf[2 * ntp],     a, b);
                mma_f16(sf[2 * ntp + 1], a, b + 2);
            }
        }

        const int jt = t << 6;
        float mx0 = -1e30f, mx1 = -1e30f;
        #pragma unroll
        for (int nt = 0; nt < 8; nt++) {
            int jb = jt + nt * 8 + ((lid & 3) << 1);
            #pragma unroll
            for (int vv = 0; vv < 4; vv++) {
                int jj = jb + (vv & 1);
                int ii = (vv < 2) ? i0 : i1;
                float e = __expf(sf[nt][vv] * TANHF2);
                float val = SOFTCAP * __fdividef(e - 1.0f, e + 1.0f);
                bool ok = (jj <= ii) && (ii - jj < WINDOW);
                sf[nt][vv] = ok ? val : -1e30f;
            }
            mx0 = fmaxf(mx0, fmaxf(sf[nt][0], sf[nt][1]));
            mx1 = fmaxf(mx1, fmaxf(sf[nt][2], sf[nt][3]));
        }
        mx0 = fmaxf(mx0, __shfl_xor_sync(0xffffffffu, mx0, 1));
        mx0 = fmaxf(mx0, __shfl_xor_sync(0xffffffffu, mx0, 2));
        mx1 = fmaxf(mx1, __shfl_xor_sync(0xffffffffu, mx1, 1));
        mx1 = fmaxf(mx1, __shfl_xor_sync(0xffffffffu, mx1, 2));

        float mn0 = fmaxf(m0, mx0), mn1 = fmaxf(m1, mx1);
        float sc0 = __expf(m0 - mn0), sc1 = __expf(m1 - mn1);
        m0 = mn0; m1 = mn1;

        float s0 = 0.0f, s1 = 0.0f;
        uint32_t phA[8], phB[8];
        #pragma unroll
        for (int nt = 0; nt < 8; nt++) {
            float p0 = __expf(sf[nt][0] - mn0), p1 = __expf(sf[nt][1] - mn0);
            float p2 = __expf(sf[nt][2] - mn1), p3 = __expf(sf[nt][3] - mn1);
            s0 += p0 + p1; s1 += p2 + p3;
            __half2 hA = __floats2half2_rn(p0, p1);
            __half2 hB = __floats2half2_rn(p2, p3);
            phA[nt] = *reinterpret_cast<uint32_t*>(&hA);
            phB[nt] = *reinterpret_cast<uint32_t*>(&hB);
        }
        s0 += __shfl_xor_sync(0xffffffffu, s0, 1);
        s0 += __shfl_xor_sync(0xffffffffu, s0, 2);
        s1 += __shfl_xor_sync(0xffffffffu, s1, 1);
        s1 += __shfl_xor_sync(0xffffffffu, s1, 2);
        l0 = l0 * sc0 + s0;
        l1 = l1 * sc1 + s1;

        #pragma unroll
        for (int nt = 0; nt < 16; nt++) {
            o[nt][0] *= sc0; o[nt][1] *= sc0;
            o[nt][2] *= sc1; o[nt][3] *= sc1;
        }

        // O += Ph·Vh (single pass)
        const uint32_t vb = stg + KSTG;
        #pragma unroll
        for (int kk = 0; kk < 4; kk++) {
            uint32_t a[4] = { phA[2 * kk], phB[2 * kk], phA[2 * kk + 1], phB[2 * kk + 1] };
            #pragma unroll
            for (int np = 0; np < 8; np++) {
                uint32_t b[4];
                ldmatrix_x4_t(b, vb + (kk * 16 + v_row) * RSTR + np * 32 + v_coff);
                mma_f16(o[2 * np],     a, b);
                mma_f16(o[2 * np + 1], a, b + 2);
            }
        }
        __syncthreads();
        st ^= 1;
    }

    // epilogue: normalize + write split [hi|lo] fp16 rows into a2
    const float inv0 = 1.0f / l0, inv1 = 1.0f / l1;
    #pragma unroll
    for (int nt = 0; nt < 16; nt++) {
        int col = h * HD + nt * 8 + ((lid & 3) << 1);
        {
            float x0 = o[nt][0] * inv0, x1 = o[nt][1] * inv0;
            __half2 hh = __floats2half2_rn(x0, x1);
            __half2 ll = __floats2half2_rn(x0 - __half2float(__low2half(hh)),
                                           x1 - __half2float(__high2half(hh)));
            uint32_t* row = reinterpret_cast<uint32_t*>(Out + (size_t)i0 * K2);
            row[col >> 1] = *reinterpret_cast<uint32_t*>(&hh);
            row[(HID + col) >> 1] = *reinterpret_cast<uint32_t*>(&ll);
        }
        {
            float x0 = o[nt][2] * inv1, x1 = o[nt][3] * inv1;
            __half2 hh = __floats2half2_rn(x0, x1);
            __half2 ll = __floats2half2_rn(x0 - __half2float(__low2half(hh)),
                                           x1 - __half2float(__high2half(hh)));
            uint32_t* row = reinterpret_cast<uint32_t*>(Out + (size_t)i1 * K2);
            row[col >> 1] = *reinterpret_cast<uint32_t*>(&hh);
            row[(HID + col) >> 1] = *reinterpret_cast<uint32_t*>(&ll);
        }
    }
}

// ---------------------------------------------------------------------------
extern "C" void kernel_launch(void* const* d_in, const int* in_sizes, int n_in,
                              void* d_out, int out_size) {
    const float* hs   = (const float*)d_in[0];
    const float* cosb = (const float*)d_in[1];
    const float* sinb = (const float*)d_in[2];
    // d_in[3] = attention_mask (unused; mask computed analytically)
    const float* Wq = (const float*)d_in[4];
    const float* Wk = (const float*)d_in[5];
    const float* Wv = (const float*)d_in[6];
    const float* Wo = (const float*)d_in[7];
    float* out = (float*)d_out;

    float *qkv;
    __half *a2, *wqkv, *wo, *qh, *kh, *vh;
    cudaGetSymbolAddress((void**)&qkv,  g_qkv);
    cudaGetSymbolAddress((void**)&a2,   g_a2);
    cudaGetSymbolAddress((void**)&wqkv, g_wqkv);
    cudaGetSymbolAddress((void**)&wo,   g_wo);
    cudaGetSymbolAddress((void**)&qh,   g_qh);
    cudaGetSymbolAddress((void**)&kh,   g_kh);
    cudaGetSymbolAddress((void**)&vh,   g_vh);

    cudaFuncSetAttribute(gemm_f16, cudaFuncAttributeMaxDynamicSharedMemorySize, SM_GEMM);
    cudaFuncSetAttribute(attn_tc, cudaFuncAttributeMaxDynamicSharedMemorySize, ATTN_SMEM);

    // conversions (weights packed into one fused fp16 buffer: rows q|k|v)
    split_act<<<(S_LEN*HID + 255)/256, 256>>>(hs, a2, S_LEN*HID);
    wt_f16<<<dim3(QD/32, HID/32), dim3(32, 8)>>>(Wq, wqkv, QD);
    wt_f16<<<dim3(KD/32, HID/32), dim3(32, 8)>>>(Wk, wqkv + (size_t)QD * HID, KD);
    wt_f16<<<dim3(KD/32, HID/32), dim3(32, 8)>>>(Wv, wqkv + (size_t)(QD + KD) * HID, KD);
    wt_f16<<<dim3(QD/32, HID/32), dim3(32, 8)>>>(Wo, wo, QD);

    // fused QKV projection (fp16 2-pass)
    gemm_f16<<<dim3(QKV_N/128, S_LEN/256), 1024, SM_GEMM>>>(a2, wqkv, qkv, QKV_N);

    // fused rope + fp16 convert
    int total = S_LEN*NH*64 + S_LEN*NKV*64 + S_LEN*KD;
    rope_split<<<(total + 255)/256, 256>>>(qkv, cosb, sinb, qh, kh, vh);

    // tensor-core attention (pure fp16) -> writes split activations into a2
    attn_tc<<<dim3(S_LEN/128, NH), 256, ATTN_SMEM>>>(qh, kh, vh, a2);

    // output projection (fp16 2-pass)
    gemm_f16<<<dim3(HID/128, S_LEN/256), 1024, SM_GEMM>>>(a2, wo, out, HID);
}

// round 15
// speedup vs baseline: 6.1086x; 1.5940x over previous
#include <cuda_runtime.h>
#include <cuda_bf16.h>
#include <cuda_fp16.h>
#include <cstdint>
#include <math.h>

#define S_LEN 4096
#define HID   2048
#define NH    16
#define NKV   8
#define HD    128
#define QD    (NH*HD)    // 2048
#define KD    (NKV*HD)   // 1024
#define QKV_N 4096       // fused projection width: q(2048)|k(1024)|v(1024)
#define WINDOW 1024
#define SCALING 0.08838834764831845f  // 128^-0.5
#define SOFTCAP 50.0f
#define TANHF2 (2.0f*SCALING/SOFTCAP)

#define BK    32
#define NITER (HID/BK)   // 64: single-pass fp16 GEMM

// ---------------- scratch (static device globals; no runtime alloc) ----------
__device__ float g_qkv[S_LEN*QKV_N];            // 64 MB fused q|k|v fp32
__device__ __half g_a16[S_LEN*HID];             // 16 MB activations fp16 (reused: hs-conv then attn-out)
__device__ __half g_wqkv[QKV_N*HID];            // 16 MB fp16 weights (rows q|k|v)
__device__ __half g_wo[HID*QD];                 // 8 MB  fp16 Wo^T
__device__ __half g_qh[S_LEN*QD];               // 16 MB (post-rope fp16)
__device__ __half g_kh[S_LEN*KD];               // 8 MB
__device__ __half g_vh[S_LEN*KD];               // 8 MB

// ---------------- helpers ----------------------------------------------------
__device__ __forceinline__ uint32_t smem_u32(const void* p) {
    uint32_t a;
    asm("{ .reg .u64 t; cvta.to.shared.u64 t, %1; cvt.u32.u64 %0, t; }" : "=r"(a) : "l"(p));
    return a;
}
__device__ __forceinline__ void cpasync16(uint32_t saddr, const void* g) {
    asm volatile("cp.async.cg.shared.global [%0], [%1], 16;" :: "r"(saddr), "l"(g));
}
__device__ __forceinline__ void cp_commit() {
    asm volatile("cp.async.commit_group;" ::: "memory");
}
__device__ __forceinline__ void ldmatrix_x4(uint32_t* r, uint32_t addr) {
    asm volatile("ldmatrix.sync.aligned.m8n8.x4.shared.b16 {%0,%1,%2,%3}, [%4];"
                 : "=r"(r[0]), "=r"(r[1]), "=r"(r[2]), "=r"(r[3]) : "r"(addr));
}
__device__ __forceinline__ void ldmatrix_x4_t(uint32_t* r, uint32_t addr) {
    asm volatile("ldmatrix.sync.aligned.m8n8.x4.trans.shared.b16 {%0,%1,%2,%3}, [%4];"
                 : "=r"(r[0]), "=r"(r[1]), "=r"(r[2]), "=r"(r[3]) : "r"(addr));
}
__device__ __forceinline__ void mma_f16(float* d, const uint32_t* a, const uint32_t* b) {
    asm volatile(
        "mma.sync.aligned.m16n8k16.row.col.f32.f16.f16.f32 "
        "{%0,%1,%2,%3}, {%4,%5,%6,%7}, {%8,%9}, {%0,%1,%2,%3};"
        : "+f"(d[0]), "+f"(d[1]), "+f"(d[2]), "+f"(d[3])
        : "r"(a[0]), "r"(a[1]), "r"(a[2]), "r"(a[3]), "r"(b[0]), "r"(b[1]));
}

// ---------------------------------------------------------------------------
// conv_act: fp32 -> fp16 elementwise (vectorized x4)
// ---------------------------------------------------------------------------
__global__ void conv_act(const float* __restrict__ X, __half* __restrict__ A,
                         int total4) {
    int idx = blockIdx.x * blockDim.x + threadIdx.x;
    if (idx >= total4) return;
    float4 v = reinterpret_cast<const float4*>(X)[idx];
    __half2 lo = __floats2half2_rn(v.x, v.y);
    __half2 hi = __floats2half2_rn(v.z, v.w);
    uint2 out;
    out.x = *reinterpret_cast<uint32_t*>(&lo);
    out.y = *reinterpret_cast<uint32_t*>(&hi);
    reinterpret_cast<uint2*>(A)[idx] = out;
}

// W [HID, Ndim] fp32 -> B rows [Ndim, HID] fp16 (transposed + rounded)
__global__ void wt_f16(const float* __restrict__ W, __half* __restrict__ B2,
                       int Ndim) {
    __shared__ float tile[32][33];
    int k0 = blockIdx.y * 32, n0 = blockIdx.x * 32;
    int tx = threadIdx.x, ty = threadIdx.y;   // 32 x 8
    #pragma unroll
    for (int i = 0; i < 32; i += 8)
        tile[ty + i][tx] = W[(size_t)(k0 + ty + i) * Ndim + n0 + tx];
    __syncthreads();
    #pragma unroll
    for (int i = 0; i < 32; i += 8) {
        int n = n0 + ty + i, k = k0 + tx;
        B2[(size_t)n * HID + k] = __float2half(tile[tx][ty + i]);
    }
}

// ---------------------------------------------------------------------------
// fp16 mma.sync GEMM (single pass): C[M,N] = A[M,HID] · B[N,HID]^T, fp32 accum
// BM=256, BN=128, BK=32, 4-stage cp.async, 1024 threads (32 warps 8x4, 32x32)
// ---------------------------------------------------------------------------
#define TSTRIDE 80
#define A_STAGE (256*TSTRIDE)            // 20480
#define B_STAGE (128*TSTRIDE)            // 10240
#define STAGE_B (A_STAGE + B_STAGE)      // 30720
#define SM_GEMM (4*STAGE_B)              // 122880

__global__ __launch_bounds__(1024, 1)
void gemm_f16(const __half* __restrict__ A,
              const __half* __restrict__ B2,
              float* __restrict__ C, int N) {
    extern __shared__ __align__(16) char smem[];
    const uint32_t sbase = smem_u32(smem);

    const int tid = threadIdx.x;
    const int wid = tid >> 5;
    const int lid = tid & 31;
    const int m0 = blockIdx.y * 256;
    const int n0 = blockIdx.x * 128;
    const int wm = (wid & 7) * 32;     // 8 warp rows
    const int wn = (wid >> 3) * 32;    // 4 warp cols

    const int arow = tid >> 2;
    const int ac   = tid & 3;
    const __half* Abase = A + (size_t)(m0 + arow) * HID + ac * 8;
    const int brow = (tid >> 2) & 127;
    const __half* Bbase = B2 + (size_t)(n0 + brow) * HID + ac * 8;
    const uint32_t sA = sbase + arow * TSTRIDE + ac * 16;
    const uint32_t sB = sbase + A_STAGE + brow * TSTRIDE + ac * 16;

    auto issue = [&](int c, int st) {
        const size_t ko = (size_t)c * BK;
        const uint32_t so = (uint32_t)st * STAGE_B;
        cpasync16(sA + so, Abase + ko);
        if (tid < 512) cpasync16(sB + so, Bbase + ko);
    };

    float acc[2][4][4];
    #pragma unroll
    for (int i = 0; i < 2; i++)
        #pragma unroll
        for (int j = 0; j < 4; j++)
            #pragma unroll
            for (int r = 0; r < 4; r++) acc[i][j][r] = 0.0f;

    const uint32_t aAddr = sbase + (wm + (lid & 15)) * TSTRIDE + (lid >> 4) * 16;
    const uint32_t bAddr = sbase + A_STAGE
        + (wn + (lid & 7) + ((lid >> 4) & 1) * 8) * TSTRIDE + ((lid >> 3) & 1) * 16;

    issue(0, 0); cp_commit();
    issue(1, 1); cp_commit();
    issue(2, 2); cp_commit();

    for (int c = 0; c < NITER; c++) {
        asm volatile("cp.async.wait_group 2;" ::: "memory");
        __syncthreads();
        if (c + 3 < NITER) issue(c + 3, (c + 3) & 3);
        cp_commit();

        const uint32_t so = (uint32_t)(c & 3) * STAGE_B;
        #pragma unroll
        for (int ks = 0; ks < 2; ks++) {
            uint32_t afr[2][4], bfr[2][4];
            #pragma unroll
            for (int mt = 0; mt < 2; mt++)
                ldmatrix_x4(afr[mt], aAddr + so + mt * (16 * TSTRIDE) + ks * 32);
            #pragma unroll
            for (int ntp = 0; ntp < 2; ntp++)
                ldmatrix_x4(bfr[ntp], bAddr + so + ntp * (16 * TSTRIDE) + ks * 32);
            #pragma unroll
            for (int mt = 0; mt < 2; mt++)
                #pragma unroll
                for (int ntp = 0; ntp < 2; ntp++) {
                    mma_f16(acc[mt][2 * ntp],     afr[mt], bfr[ntp]);
                    mma_f16(acc[mt][2 * ntp + 1], afr[mt], bfr[ntp] + 2);
                }
        }
    }

    const int erow = (lid >> 2);
    const int ecol = (lid & 3) * 2;
    #pragma unroll
    for (int mt = 0; mt < 2; mt++) {
        #pragma unroll
        for (int nt = 0; nt < 4; nt++) {
            int r = m0 + wm + mt * 16 + erow;
            int col = n0 + wn + nt * 8 + ecol;
            *(float2*)&C[(size_t)r * N + col] = make_float2(acc[mt][nt][0], acc[mt][nt][1]);
            *(float2*)&C[(size_t)(r + 8) * N + col] = make_float2(acc[mt][nt][2], acc[mt][nt][3]);
        }
    }
}

// ---------------------------------------------------------------------------
// RoPE + fp16 convert: q -> qh, k -> kh, v -> vh
// ---------------------------------------------------------------------------
__global__ void rope_split(const float* __restrict__ qkv,
                           const float* __restrict__ cosb, const float* __restrict__ sinb,
                           __half* __restrict__ qh, __half* __restrict__ kh,
                           __half* __restrict__ vh) {
    const int NQP = S_LEN * NH * 64;
    const int NKP = S_LEN * NKV * 64;
    const int NV  = S_LEN * KD;
    int idx = blockIdx.x * blockDim.x + threadIdx.x;
    if (idx < NQP) {
        int d = idx & 63, hh = (idx >> 6) % NH, s = idx / (64 * NH);
        float c = cosb[s * HD + d], sn = sinb[s * HD + d];
        const float* p = qkv + (size_t)s * QKV_N + hh * HD;
        float x1 = p[d], x2 = p[d + 64];
        size_t o = (size_t)s * QD + hh * HD + d;
        qh[o]      = __float2half(x1 * c - x2 * sn);
        qh[o + 64] = __float2half(x2 * c + x1 * sn);
    } else if (idx < NQP + NKP) {
        int t = idx - NQP;
        int d = t & 63, hh = (t >> 6) % NKV, s = t / (64 * NKV);
        float c = cosb[s * HD + d], sn = sinb[s * HD + d];
        const float* p = qkv + (size_t)s * QKV_N + QD + hh * HD;
        float x1 = p[d], x2 = p[d + 64];
        size_t o = (size_t)s * KD + hh * HD + d;
        kh[o]      = __float2half(x1 * c - x2 * sn);
        kh[o + 64] = __float2half(x2 * c + x1 * sn);
    } else if (idx < NQP + NKP + NV) {
        int t = idx - NQP - NKP;
        int s = t / KD, j = t - s * KD;
        vh[t] = __float2half(qkv[(size_t)s * QKV_N + QD + KD + j]);
    }
}

// ---------------------------------------------------------------------------
// Tensor-core flash attention, pure fp16 single-pass, sliding window + softcap.
// S = Qh·Kh^T ; O = Ph·Vh. Epilogue -> a16 [S, HID] fp16.
// ---------------------------------------------------------------------------
#define RSTR   272
#define STG_OFF 34816                 // Qh region (128*272)
#define KSTG   17408                  // 64*272
#define STG_SZ 34816                  // Kh+Vh per stage
#define ATTN_SMEM (STG_OFF + 2*STG_SZ)  // 104448

__global__ __launch_bounds__(256)
void attn_tc(const __half* __restrict__ Qh,
             const __half* __restrict__ Kh, const __half* __restrict__ Vh,
             __half* __restrict__ Out) {
    extern __shared__ __align__(16) char smem[];
    const uint32_t sb = smem_u32(smem);
    const int tid = threadIdx.x, wid = tid >> 5, lid = tid & 31;
    const int h = blockIdx.y, q0 = blockIdx.x * 128, kvh = h >> 1;

    // Q loads: 128 rows x 16 chunks
    #pragma unroll
    for (int i = 0; i < 8; i++) {
        int id = tid + i * 256;
        int row = id >> 4, c = id & 15;
        cpasync16(sb + row * RSTR + c * 16,
                  Qh + (size_t)(q0 + row) * QD + h * HD + c * 8);
    }

    int jmin = q0 - (WINDOW - 1); if (jmin < 0) jmin = 0;
    const int t0 = jmin >> 6, t1 = (q0 + 127) >> 6;

    auto issueKV = [&](int t, int st) {
        const int kt = t << 6;
        const uint32_t sbase = sb + STG_OFF + (uint32_t)st * STG_SZ;
        #pragma unroll
        for (int i = 0; i < 8; i++) {
            int id = tid + i * 256;
            int mat = id >> 10, id2 = id & 1023;    // 0=Kh, 1=Vh
            int row = id2 >> 4, c = id2 & 15;
            const __half* base = mat ? Vh : Kh;
            cpasync16(sbase + mat * KSTG + row * RSTR + c * 16,
                      base + (size_t)(kt + row) * KD + kvh * HD + c * 8);
        }
    };
    issueKV(t0, 0); cp_commit();

    float o[16][4];
    #pragma unroll
    for (int i = 0; i < 16; i++)
        #pragma unroll
        for (int j = 0; j < 4; j++) o[i][j] = 0.0f;
    float m0 = -1e30f, m1 = -1e30f, l0 = 0.0f, l1 = 0.0f;

    const int wm = wid * 16;
    const int i0 = q0 + wm + (lid >> 2), i1 = i0 + 8;
    const uint32_t qa_h = sb + (wm + (lid & 15)) * RSTR + (lid >> 4) * 16;
    const uint32_t ka_row = (lid & 7) + ((lid >> 4) & 1) * 8;
    const uint32_t ka_coff = ((lid >> 3) & 1) * 16;
    const uint32_t v_row = (lid & 7) + ((lid >> 3) & 1) * 8;
    const uint32_t v_coff = ((lid >> 4) & 1) * 16;

    int st = 0;
    for (int t = t0; t <= t1; t++) {
        if (t < t1) { issueKV(t + 1, st ^ 1); cp_commit(); }
        if (t < t1) asm volatile("cp.async.wait_group 1;" ::: "memory");
        else        asm volatile("cp.async.wait_group 0;" ::: "memory");
        __syncthreads();

        const uint32_t stg = sb + STG_OFF + (uint32_t)st * STG_SZ;

        float sf[8][4];
        #pragma unroll
        for (int nt = 0; nt < 8; nt++)
            #pragma unroll
            for (int j = 0; j < 4; j++) sf[nt][j] = 0.0f;

        // S = Qh·Kh^T (single pass)
        #pragma unroll
        for (int kk = 0; kk < 8; kk++) {
            uint32_t a[4];
            ldmatrix_x4(a, qa_h + kk * 32);
            #pragma unroll
            for (int ntp = 0; ntp < 4; ntp++) {
                uint32_t b[4];
                ldmatrix_x4(b, stg + (ntp * 16 + ka_row) * RSTR + ka_coff + kk * 32);
                mma_f16(sf[2 * ntp],     a, b);
                mma_f16(sf[2 * ntp + 1], a, b + 2);
            }
        }

        const int jt = t << 6;
        float mx0 = -1e30f, mx1 = -1e30f;
        #pragma unroll
        for (int nt = 0; nt < 8; nt++) {
            int jb = jt + nt * 8 + ((lid & 3) << 1);
            #pragma unroll
            for (int vv = 0; vv < 4; vv++) {
                int jj = jb + (vv & 1);
                int ii = (vv < 2) ? i0 : i1;
                float e = __expf(sf[nt][vv] * TANHF2);
                float val = SOFTCAP * __fdividef(e - 1.0f, e + 1.0f);
                bool ok = (jj <= ii) && (ii - jj < WINDOW);
                sf[nt][vv] = ok ? val : -1e30f;
            }
            mx0 = fmaxf(mx0, fmaxf(sf[nt][0], sf[nt][1]));
            mx1 = fmaxf(mx1, fmaxf(sf[nt][2], sf[nt][3]));
        }
        mx0 = fmaxf(mx0, __shfl_xor_sync(0xffffffffu, mx0, 1));
        mx0 = fmaxf(mx0, __shfl_xor_sync(0xffffffffu, mx0, 2));
        mx1 = fmaxf(mx1, __shfl_xor_sync(0xffffffffu, mx1, 1));
        mx1 = fmaxf(mx1, __shfl_xor_sync(0xffffffffu, mx1, 2));

        float mn0 = fmaxf(m0, mx0), mn1 = fmaxf(m1, mx1);
        float sc0 = __expf(m0 - mn0), sc1 = __expf(m1 - mn1);
        m0 = mn0; m1 = mn1;

        float s0 = 0.0f, s1 = 0.0f;
        uint32_t phA[8], phB[8];
        #pragma unroll
        for (int nt = 0; nt < 8; nt++) {
            float p0 = __expf(sf[nt][0] - mn0), p1 = __expf(sf[nt][1] - mn0);
            float p2 = __expf(sf[nt][2] - mn1), p3 = __expf(sf[nt][3] - mn1);
            s0 += p0 + p1; s1 += p2 + p3;
            __half2 hA = __floats2half2_rn(p0, p1);
            __half2 hB = __floats2half2_rn(p2, p3);
            phA[nt] = *reinterpret_cast<uint32_t*>(&hA);
            phB[nt] = *reinterpret_cast<uint32_t*>(&hB);
        }
        s0 += __shfl_xor_sync(0xffffffffu, s0, 1);
        s0 += __shfl_xor_sync(0xffffffffu, s0, 2);
        s1 += __shfl_xor_sync(0xffffffffu, s1, 1);
        s1 += __shfl_xor_sync(0xffffffffu, s1, 2);
        l0 = l0 * sc0 + s0;
        l1 = l1 * sc1 + s1;

        #pragma unroll
        for (int nt = 0; nt < 16; nt++) {
            o[nt][0] *= sc0; o[nt][1] *= sc0;
            o[nt][2] *= sc1; o[nt][3] *= sc1;
        }

        // O += Ph·Vh (single pass)
        const uint32_t vb = stg + KSTG;
        #pragma unroll
        for (int kk = 0; kk < 4; kk++) {
            uint32_t a[4] = { phA[2 * kk], phB[2 * kk], phA[2 * kk + 1], phB[2 * kk + 1] };
            #pragma unroll
            for (int np = 0; np < 8; np++) {
                uint32_t b[4];
                ldmatrix_x4_t(b, vb + (kk * 16 + v_row) * RSTR + np * 32 + v_coff);
                mma_f16(o[2 * np],     a, b);
                mma_f16(o[2 * np + 1], a, b + 2);
            }
        }
        __syncthreads();
        st ^= 1;
    }

    // epilogue: normalize + write fp16 rows into a16 [S, HID]
    const float inv0 = 1.0f / l0, inv1 = 1.0f / l1;
    #pragma unroll
    for (int nt = 0; nt < 16; nt++) {
        int col = h * HD + nt * 8 + ((lid & 3) << 1);
        {
            __half2 hh = __floats2half2_rn(o[nt][0] * inv0, o[nt][1] * inv0);
            reinterpret_cast<uint32_t*>(Out + (size_t)i0 * HID)[col >> 1] =
                *reinterpret_cast<uint32_t*>(&hh);
        }
        {
            __half2 hh = __floats2half2_rn(o[nt][2] * inv1, o[nt][3] * inv1);
            reinterpret_cast<uint32_t*>(Out + (size_t)i1 * HID)[col >> 1] =
                *reinterpret_cast<uint32_t*>(&hh);
        }
    }
}

// ---------------------------------------------------------------------------
extern "C" void kernel_launch(void* const* d_in, const int* in_sizes, int n_in,
                              void* d_out, int out_size) {
    const float* hs   = (const float*)d_in[0];
    const float* cosb = (const float*)d_in[1];
    const float* sinb = (const float*)d_in[2];
    // d_in[3] = attention_mask (unused; mask computed analytically)
    const float* Wq = (const float*)d_in[4];
    const float* Wk = (const float*)d_in[5];
    const float* Wv = (const float*)d_in[6];
    const float* Wo = (const float*)d_in[7];
    float* out = (float*)d_out;

    float *qkv;
    __half *a16, *wqkv, *wo, *qh, *kh, *vh;
    cudaGetSymbolAddress((void**)&qkv,  g_qkv);
    cudaGetSymbolAddress((void**)&a16,  g_a16);
    cudaGetSymbolAddress((void**)&wqkv, g_wqkv);
    cudaGetSymbolAddress((void**)&wo,   g_wo);
    cudaGetSymbolAddress((void**)&qh,   g_qh);
    cudaGetSymbolAddress((void**)&kh,   g_kh);
    cudaGetSymbolAddress((void**)&vh,   g_vh);

    cudaFuncSetAttribute(gemm_f16, cudaFuncAttributeMaxDynamicSharedMemorySize, SM_GEMM);
    cudaFuncSetAttribute(attn_tc, cudaFuncAttributeMaxDynamicSharedMemorySize, ATTN_SMEM);

    // conversions (weights packed into one fused fp16 buffer: rows q|k|v)
    conv_act<<<(S_LEN*HID/4 + 255)/256, 256>>>(hs, a16, S_LEN*HID/4);
    wt_f16<<<dim3(QD/32, HID/32), dim3(32, 8)>>>(Wq, wqkv, QD);
    wt_f16<<<dim3(KD/32, HID/32), dim3(32, 8)>>>(Wk, wqkv + (size_t)QD * HID, KD);
    wt_f16<<<dim3(KD/32, HID/32), dim3(32, 8)>>>(Wv, wqkv + (size_t)(QD + KD) * HID, KD);
    wt_f16<<<dim3(QD/32, HID/32), dim3(32, 8)>>>(Wo, wo, QD);

    // fused QKV projection (single-pass fp16)
    gemm_f16<<<dim3(QKV_N/128, S_LEN/256), 1024, SM_GEMM>>>(a16, wqkv, qkv, QKV_N);

    // fused rope + fp16 convert
    int total = S_LEN*NH*64 + S_LEN*NKV*64 + S_LEN*KD;
    rope_split<<<(total + 255)/256, 256>>>(qkv, cosb, sinb, qh, kh, vh);

    // tensor-core attention (pure fp16) -> writes fp16 activations into a16
    attn_tc<<<dim3(S_LEN/128, NH), 256, ATTN_SMEM>>>(qh, kh, vh, a16);

    // output projection (single-pass fp16)
    gemm_f16<<<dim3(HID/128, S_LEN/256), 1024, SM_GEMM>>>(a16, wo, out, HID);
}

// round 16
// speedup vs baseline: 6.3726x; 1.0432x over previous
#include <cuda_runtime.h>
#include <cuda_bf16.h>
#include <cuda_fp16.h>
#include <cstdint>
#include <math.h>

#define S_LEN 4096
#define HID   2048
#define NH    16
#define NKV   8
#define HD    128
#define QD    (NH*HD)    // 2048
#define KD    (NKV*HD)   // 1024
#define QKV_N 4096       // fused projection width: q(2048)|k(1024)|v(1024)
#define WINDOW 1024
#define SCALING 0.08838834764831845f  // 128^-0.5
#define SOFTCAP 50.0f
#define TANHF2 (2.0f*SCALING/SOFTCAP)

#define BK    32
#define NITER (HID/BK)   // 64: single-pass fp16 GEMM

// ---------------- scratch (static device globals; no runtime alloc) ----------
__device__ float g_qkv[S_LEN*QKV_N];            // 64 MB fused q|k|v fp32
__device__ __half g_a16[S_LEN*HID];             // 16 MB activations fp16 (reused)
__device__ __half g_wqkv[QKV_N*HID];            // 16 MB fp16 weights (rows q|k|v)
__device__ __half g_wo[HID*QD];                 // 8 MB  fp16 Wo^T
__device__ __half g_qh[S_LEN*QD];               // 16 MB (post-rope fp16)
__device__ __half g_kh[S_LEN*KD];               // 8 MB
__device__ __half g_vh[S_LEN*KD];               // 8 MB

// ---------------- helpers ----------------------------------------------------
__device__ __forceinline__ uint32_t smem_u32(const void* p) {
    uint32_t a;
    asm("{ .reg .u64 t; cvta.to.shared.u64 t, %1; cvt.u32.u64 %0, t; }" : "=r"(a) : "l"(p));
    return a;
}
__device__ __forceinline__ void cpasync16(uint32_t saddr, const void* g) {
    asm volatile("cp.async.cg.shared.global [%0], [%1], 16;" :: "r"(saddr), "l"(g));
}
__device__ __forceinline__ void cp_commit() {
    asm volatile("cp.async.commit_group;" ::: "memory");
}
__device__ __forceinline__ void ldmatrix_x4(uint32_t* r, uint32_t addr) {
    asm volatile("ldmatrix.sync.aligned.m8n8.x4.shared.b16 {%0,%1,%2,%3}, [%4];"
                 : "=r"(r[0]), "=r"(r[1]), "=r"(r[2]), "=r"(r[3]) : "r"(addr));
}
__device__ __forceinline__ void ldmatrix_x4_t(uint32_t* r, uint32_t addr) {
    asm volatile("ldmatrix.sync.aligned.m8n8.x4.trans.shared.b16 {%0,%1,%2,%3}, [%4];"
                 : "=r"(r[0]), "=r"(r[1]), "=r"(r[2]), "=r"(r[3]) : "r"(addr));
}
__device__ __forceinline__ void mma_f16(float* d, const uint32_t* a, const uint32_t* b) {
    asm volatile(
        "mma.sync.aligned.m16n8k16.row.col.f32.f16.f16.f32 "
        "{%0,%1,%2,%3}, {%4,%5,%6,%7}, {%8,%9}, {%0,%1,%2,%3};"
        : "+f"(d[0]), "+f"(d[1]), "+f"(d[2]), "+f"(d[3])
        : "r"(a[0]), "r"(a[1]), "r"(a[2]), "r"(a[3]), "r"(b[0]), "r"(b[1]));
}

// ---------------------------------------------------------------------------
// conv_act: fp32 -> fp16 elementwise (vectorized x4)
// ---------------------------------------------------------------------------
__global__ void conv_act(const float* __restrict__ X, __half* __restrict__ A,
                         int total4) {
    int idx = blockIdx.x * blockDim.x + threadIdx.x;
    if (idx >= total4) return;
    float4 v = reinterpret_cast<const float4*>(X)[idx];
    __half2 lo = __floats2half2_rn(v.x, v.y);
    __half2 hi = __floats2half2_rn(v.z, v.w);
    uint2 out;
    out.x = *reinterpret_cast<uint32_t*>(&lo);
    out.y = *reinterpret_cast<uint32_t*>(&hi);
    reinterpret_cast<uint2*>(A)[idx] = out;
}

// All four weights in one launch; blockIdx.z selects the matrix.
// W [HID, Ndim] fp32 -> B rows [Ndim, HID] fp16 (transposed + rounded)
__global__ void wt_f16_all(const float* __restrict__ Wq, const float* __restrict__ Wk,
                           const float* __restrict__ Wv, const float* __restrict__ Wo,
                           __half* __restrict__ wqkv, __half* __restrict__ wo) {
    const float* W; __half* B2; int Ndim;
    switch (blockIdx.z) {
        case 0:  W = Wq; B2 = wqkv;                              Ndim = QD; break;
        case 1:  W = Wk; B2 = wqkv + (size_t)QD * HID;           Ndim = KD; break;
        case 2:  W = Wv; B2 = wqkv + (size_t)(QD + KD) * HID;    Ndim = KD; break;
        default: W = Wo; B2 = wo;                                Ndim = QD; break;
    }
    int n0 = blockIdx.x * 32;
    if (n0 >= Ndim) return;
    __shared__ float tile[32][33];
    int k0 = blockIdx.y * 32;
    int tx = threadIdx.x, ty = threadIdx.y;   // 32 x 8
    #pragma unroll
    for (int i = 0; i < 32; i += 8)
        tile[ty + i][tx] = W[(size_t)(k0 + ty + i) * Ndim + n0 + tx];
    __syncthreads();
    #pragma unroll
    for (int i = 0; i < 32; i += 8) {
        int n = n0 + ty + i, k = k0 + tx;
        B2[(size_t)n * HID + k] = __float2half(tile[tx][ty + i]);
    }
}

// ---------------------------------------------------------------------------
// fp16 mma.sync GEMM (single pass): C[M,N] = A[M,HID] · B[N,HID]^T, fp32 accum
// BM=128, BN=128, BK=32, 4-stage cp.async, 512 threads (16 warps 4x4, 32x32)
// ---------------------------------------------------------------------------
#define TSTRIDE 80
#define A_STAGE (128*TSTRIDE)            // 10240
#define B_STAGE (128*TSTRIDE)            // 10240
#define STAGE_B (A_STAGE + B_STAGE)      // 20480
#define SM_GEMM (4*STAGE_B)              // 81920

__global__ __launch_bounds__(512, 1)
void gemm_f16(const __half* __restrict__ A,
              const __half* __restrict__ B2,
              float* __restrict__ C, int N) {
    extern __shared__ __align__(16) char smem[];
    const uint32_t sbase = smem_u32(smem);

    const int tid = threadIdx.x;
    const int wid = tid >> 5;
    const int lid = tid & 31;
    const int m0 = blockIdx.y * 128;
    const int n0 = blockIdx.x * 128;
    const int wm = (wid & 3) * 32;     // 4 warp rows
    const int wn = (wid >> 2) * 32;    // 4 warp cols

    const int arow = tid >> 2;          // 0..127
    const int ac   = tid & 3;
    const __half* Abase = A + (size_t)(m0 + arow) * HID + ac * 8;
    const __half* Bbase = B2 + (size_t)(n0 + arow) * HID + ac * 8;
    const uint32_t sA = sbase + arow * TSTRIDE + ac * 16;
    const uint32_t sB = sA + A_STAGE;

    auto issue = [&](int c, int st) {
        const size_t ko = (size_t)c * BK;
        const uint32_t so = (uint32_t)st * STAGE_B;
        cpasync16(sA + so, Abase + ko);
        cpasync16(sB + so, Bbase + ko);
    };

    float acc[2][4][4];
    #pragma unroll
    for (int i = 0; i < 2; i++)
        #pragma unroll
        for (int j = 0; j < 4; j++)
            #pragma unroll
            for (int r = 0; r < 4; r++) acc[i][j][r] = 0.0f;

    const uint32_t aAddr = sbase + (wm + (lid & 15)) * TSTRIDE + (lid >> 4) * 16;
    const uint32_t bAddr = sbase + A_STAGE
        + (wn + (lid & 7) + ((lid >> 4) & 1) * 8) * TSTRIDE + ((lid >> 3) & 1) * 16;

    issue(0, 0); cp_commit();
    issue(1, 1); cp_commit();
    issue(2, 2); cp_commit();

    for (int c = 0; c < NITER; c++) {
        asm volatile("cp.async.wait_group 2;" ::: "memory");
        __syncthreads();
        if (c + 3 < NITER) issue(c + 3, (c + 3) & 3);
        cp_commit();

        const uint32_t so = (uint32_t)(c & 3) * STAGE_B;
        #pragma unroll
        for (int ks = 0; ks < 2; ks++) {
            uint32_t afr[2][4], bfr[2][4];
            #pragma unroll
            for (int mt = 0; mt < 2; mt++)
                ldmatrix_x4(afr[mt], aAddr + so + mt * (16 * TSTRIDE) + ks * 32);
            #pragma unroll
            for (int ntp = 0; ntp < 2; ntp++)
                ldmatrix_x4(bfr[ntp], bAddr + so + ntp * (16 * TSTRIDE) + ks * 32);
            #pragma unroll
            for (int mt = 0; mt < 2; mt++)
                #pragma unroll
                for (int ntp = 0; ntp < 2; ntp++) {
                    mma_f16(acc[mt][2 * ntp],     afr[mt], bfr[ntp]);
                    mma_f16(acc[mt][2 * ntp + 1], afr[mt], bfr[ntp] + 2);
                }
        }
    }

    const int erow = (lid >> 2);
    const int ecol = (lid & 3) * 2;
    #pragma unroll
    for (int mt = 0; mt < 2; mt++) {
        #pragma unroll
        for (int nt = 0; nt < 4; nt++) {
            int r = m0 + wm + mt * 16 + erow;
            int col = n0 + wn + nt * 8 + ecol;
            *(float2*)&C[(size_t)r * N + col] = make_float2(acc[mt][nt][0], acc[mt][nt][1]);
            *(float2*)&C[(size_t)(r + 8) * N + col] = make_float2(acc[mt][nt][2], acc[mt][nt][3]);
        }
    }
}

// ---------------------------------------------------------------------------
// RoPE + fp16 convert: q -> qh, k -> kh, v -> vh
// ---------------------------------------------------------------------------
__global__ void rope_split(const float* __restrict__ qkv,
                           const float* __restrict__ cosb, const float* __restrict__ sinb,
                           __half* __restrict__ qh, __half* __restrict__ kh,
                           __half* __restrict__ vh) {
    const int NQP = S_LEN * NH * 64;
    const int NKP = S_LEN * NKV * 64;
    const int NV  = S_LEN * KD;
    int idx = blockIdx.x * blockDim.x + threadIdx.x;
    if (idx < NQP) {
        int d = idx & 63, hh = (idx >> 6) % NH, s = idx / (64 * NH);
        float c = cosb[s * HD + d], sn = sinb[s * HD + d];
        const float* p = qkv + (size_t)s * QKV_N + hh * HD;
        float x1 = p[d], x2 = p[d + 64];
        size_t o = (size_t)s * QD + hh * HD + d;
        qh[o]      = __float2half(x1 * c - x2 * sn);
        qh[o + 64] = __float2half(x2 * c + x1 * sn);
    } else if (idx < NQP + NKP) {
        int t = idx - NQP;
        int d = t & 63, hh = (t >> 6) % NKV, s = t / (64 * NKV);
        float c = cosb[s * HD + d], sn = sinb[s * HD + d];
        const float* p = qkv + (size_t)s * QKV_N + QD + hh * HD;
        float x1 = p[d], x2 = p[d + 64];
        size_t o = (size_t)s * KD + hh * HD + d;
        kh[o]      = __float2half(x1 * c - x2 * sn);
        kh[o + 64] = __float2half(x2 * c + x1 * sn);
    } else if (idx < NQP + NKP + NV) {
        int t = idx - NQP - NKP;
        int s = t / KD, j = t - s * KD;
        vh[t] = __float2half(qkv[(size_t)s * QKV_N + QD + KD + j]);
    }
}

// ---------------------------------------------------------------------------
// Tensor-core flash attention, pure fp16 single-pass, sliding window + softcap.
// S = Qh·Kh^T ; O = Ph·Vh. Epilogue -> a16 [S, HID] fp16. 2 CTAs/SM target.
// ---------------------------------------------------------------------------
#define RSTR   272
#define STG_OFF 34816                 // Qh region (128*272)
#define KSTG   17408                  // 64*272
#define STG_SZ 34816                  // Kh+Vh per stage
#define ATTN_SMEM (STG_OFF + 2*STG_SZ)  // 104448

__global__ __launch_bounds__(256, 2)
void attn_tc(const __half* __restrict__ Qh,
             const __half* __restrict__ Kh, const __half* __restrict__ Vh,
             __half* __restrict__ Out) {
    extern __shared__ __align__(16) char smem[];
    const uint32_t sb = smem_u32(smem);
    const int tid = threadIdx.x, wid = tid >> 5, lid = tid & 31;
    const int h = blockIdx.y, q0 = blockIdx.x * 128, kvh = h >> 1;

    // Q loads: 128 rows x 16 chunks
    #pragma unroll
    for (int i = 0; i < 8; i++) {
        int id = tid + i * 256;
        int row = id >> 4, c = id & 15;
        cpasync16(sb + row * RSTR + c * 16,
                  Qh + (size_t)(q0 + row) * QD + h * HD + c * 8);
    }

    int jmin = q0 - (WINDOW - 1); if (jmin < 0) jmin = 0;
    const int t0 = jmin >> 6, t1 = (q0 + 127) >> 6;

    auto issueKV = [&](int t, int st) {
        const int kt = t << 6;
        const uint32_t sbase = sb + STG_OFF + (uint32_t)st * STG_SZ;
        #pragma unroll
        for (int i = 0; i < 8; i++) {
            int id = tid + i * 256;
            int mat = id >> 10, id2 = id & 1023;    // 0=Kh, 1=Vh
            int row = id2 >> 4, c = id2 & 15;
            const __half* base = mat ? Vh : Kh;
            cpasync16(sbase + mat * KSTG + row * RSTR + c * 16,
                      base + (size_t)(kt + row) * KD + kvh * HD + c * 8);
        }
    };
    issueKV(t0, 0); cp_commit();

    float o[16][4];
    #pragma unroll
    for (int i = 0; i < 16; i++)
        #pragma unroll
        for (int j = 0; j < 4; j++) o[i][j] = 0.0f;
    float m0 = -1e30f, m1 = -1e30f, l0 = 0.0f, l1 = 0.0f;

    const int wm = wid * 16;
    const int i0 = q0 + wm + (lid >> 2), i1 = i0 + 8;
    const uint32_t qa_h = sb + (wm + (lid & 15)) * RSTR + (lid >> 4) * 16;
    const uint32_t ka_row = (lid & 7) + ((lid >> 4) & 1) * 8;
    const uint32_t ka_coff = ((lid >> 3) & 1) * 16;
    const uint32_t v_row = (lid & 7) + ((lid >> 3) & 1) * 8;
    const uint32_t v_coff = ((lid >> 4) & 1) * 16;

    int st = 0;
    for (int t = t0; t <= t1; t++) {
        if (t < t1) { issueKV(t + 1, st ^ 1); cp_commit(); }
        if (t < t1) asm volatile("cp.async.wait_group 1;" ::: "memory");
        else        asm volatile("cp.async.wait_group 0;" ::: "memory");
        __syncthreads();

        const uint32_t stg = sb + STG_OFF + (uint32_t)st * STG_SZ;

        float sf[8][4];
        #pragma unroll
        for (int nt = 0; nt < 8; nt++)
            #pragma unroll
            for (int j = 0; j < 4; j++) sf[nt][j] = 0.0f;

        // S = Qh·Kh^T (single pass)
        #pragma unroll
        for (int kk = 0; kk < 8; kk++) {
            uint32_t a[4];
            ldmatrix_x4(a, qa_h + kk * 32);
            #pragma unroll
            for (int ntp = 0; ntp < 4; ntp++) {
                uint32_t b[4];
                ldmatrix_x4(b, stg + (ntp * 16 + ka_row) * RSTR + ka_coff + kk * 32);
                mma_f16(sf[2 * ntp],     a, b);
                mma_f16(sf[2 * ntp + 1], a, b + 2);
            }
        }

        const int jt = t << 6;
        float mx0 = -1e30f, mx1 = -1e30f;
        #pragma unroll
        for (int nt = 0; nt < 8; nt++) {
            int jb = jt + nt * 8 + ((lid & 3) << 1);
            #pragma unroll
            for (int vv = 0; vv < 4; vv++) {
                int jj = jb + (vv & 1);
                int ii = (vv < 2) ? i0 : i1;
                float e = __expf(sf[nt][vv] * TANHF2);
                float val = SOFTCAP * __fdividef(e - 1.0f, e + 1.0f);
                bool ok = (jj <= ii) && (ii - jj < WINDOW);
                sf[nt][vv] = ok ? val : -1e30f;
            }
            mx0 = fmaxf(mx0, fmaxf(sf[nt][0], sf[nt][1]));
            mx1 = fmaxf(mx1, fmaxf(sf[nt][2], sf[nt][3]));
        }
        mx0 = fmaxf(mx0, __shfl_xor_sync(0xffffffffu, mx0, 1));
        mx0 = fmaxf(mx0, __shfl_xor_sync(0xffffffffu, mx0, 2));
        mx1 = fmaxf(mx1, __shfl_xor_sync(0xffffffffu, mx1, 1));
        mx1 = fmaxf(mx1, __shfl_xor_sync(0xffffffffu, mx1, 2));

        float mn0 = fmaxf(m0, mx0), mn1 = fmaxf(m1, mx1);
        float sc0 = __expf(m0 - mn0), sc1 = __expf(m1 - mn1);
        m0 = mn0; m1 = mn1;

        float s0 = 0.0f, s1 = 0.0f;
        uint32_t phA[8], phB[8];
        #pragma unroll
        for (int nt = 0; nt < 8; nt++) {
            float p0 = __expf(sf[nt][0] - mn0), p1 = __expf(sf[nt][1] - mn0);
            float p2 = __expf(sf[nt][2] - mn1), p3 = __expf(sf[nt][3] - mn1);
            s0 += p0 + p1; s1 += p2 + p3;
            __half2 hA = __floats2half2_rn(p0, p1);
            __half2 hB = __floats2half2_rn(p2, p3);
            phA[nt] = *reinterpret_cast<uint32_t*>(&hA);
            phB[nt] = *reinterpret_cast<uint32_t*>(&hB);
        }
        s0 += __shfl_xor_sync(0xffffffffu, s0, 1);
        s0 += __shfl_xor_sync(0xffffffffu, s0, 2);
        s1 += __shfl_xor_sync(0xffffffffu, s1, 1);
        s1 += __shfl_xor_sync(0xffffffffu, s1, 2);
        l0 = l0 * sc0 + s0;
        l1 = l1 * sc1 + s1;

        #pragma unroll
        for (int nt = 0; nt < 16; nt++) {
            o[nt][0] *= sc0; o[nt][1] *= sc0;
            o[nt][2] *= sc1; o[nt][3] *= sc1;
        }

        // O += Ph·Vh (single pass)
        const uint32_t vb = stg + KSTG;
        #pragma unroll
        for (int kk = 0; kk < 4; kk++) {
            uint32_t a[4] = { phA[2 * kk], phB[2 * kk], phA[2 * kk + 1], phB[2 * kk + 1] };
            #pragma unroll
            for (int np = 0; np < 8; np++) {
                uint32_t b[4];
                ldmatrix_x4_t(b, vb + (kk * 16 + v_row) * RSTR + np * 32 + v_coff);
                mma_f16(o[2 * np],     a, b);
                mma_f16(o[2 * np + 1], a, b + 2);
            }
        }
        __syncthreads();
        st ^= 1;
    }

    // epilogue: normalize + write fp16 rows into a16 [S, HID]
    const float inv0 = 1.0f / l0, inv1 = 1.0f / l1;
    #pragma unroll
    for (int nt = 0; nt < 16; nt++) {
        int col = h * HD + nt * 8 + ((lid & 3) << 1);
        {
            __half2 hh = __floats2half2_rn(o[nt][0] * inv0, o[nt][1] * inv0);
            reinterpret_cast<uint32_t*>(Out + (size_t)i0 * HID)[col >> 1] =
                *reinterpret_cast<uint32_t*>(&hh);
        }
        {
            __half2 hh = __floats2half2_rn(o[nt][2] * inv1, o[nt][3] * inv1);
            reinterpret_cast<uint32_t*>(Out + (size_t)i1 * HID)[col >> 1] =
                *reinterpret_cast<uint32_t*>(&hh);
        }
    }
}

// ---------------------------------------------------------------------------
extern "C" void kernel_launch(void* const* d_in, const int* in_sizes, int n_in,
                              void* d_out, int out_size) {
    const float* hs   = (const float*)d_in[0];
    const float* cosb = (const float*)d_in[1];
    const float* sinb = (const float*)d_in[2];
    // d_in[3] = attention_mask (unused; mask computed analytically)
    const float* Wq = (const float*)d_in[4];
    const float* Wk = (const float*)d_in[5];
    const float* Wv = (const float*)d_in[6];
    const float* Wo = (const float*)d_in[7];
    float* out = (float*)d_out;

    float *qkv;
    __half *a16, *wqkv, *wo, *qh, *kh, *vh;
    cudaGetSymbolAddress((void**)&qkv,  g_qkv);
    cudaGetSymbolAddress((void**)&a16,  g_a16);
    cudaGetSymbolAddress((void**)&wqkv, g_wqkv);
    cudaGetSymbolAddress((void**)&wo,   g_wo);
    cudaGetSymbolAddress((void**)&qh,   g_qh);
    cudaGetSymbolAddress((void**)&kh,   g_kh);
    cudaGetSymbolAddress((void**)&vh,   g_vh);

    cudaFuncSetAttribute(gemm_f16, cudaFuncAttributeMaxDynamicSharedMemorySize, SM_GEMM);
    cudaFuncSetAttribute(attn_tc, cudaFuncAttributeMaxDynamicSharedMemorySize, ATTN_SMEM);

    // conversions (one fused weight launch; z selects matrix)
    conv_act<<<(S_LEN*HID/4 + 255)/256, 256>>>(hs, a16, S_LEN*HID/4);
    wt_f16_all<<<dim3(QD/32, HID/32, 4), dim3(32, 8)>>>(Wq, Wk, Wv, Wo, wqkv, wo);

    // fused QKV projection (single-pass fp16, BM=128)
    gemm_f16<<<dim3(QKV_N/128, S_LEN/128), 512, SM_GEMM>>>(a16, wqkv, qkv, QKV_N);

    // fused rope + fp16 convert
    int total = S_LEN*NH*64 + S_LEN*NKV*64 + S_LEN*KD;
    rope_split<<<(total + 255)/256, 256>>>(qkv, cosb, sinb, qh, kh, vh);

    // tensor-core attention (pure fp16) -> writes fp16 activations into a16
    attn_tc<<<dim3(S_LEN/128, NH), 256, ATTN_SMEM>>>(qh, kh, vh, a16);

    // output projection (single-pass fp16, BM=128)
    gemm_f16<<<dim3(HID/128, S_LEN/128), 512, SM_GEMM>>>(a16, wo, out, HID);
}